// round 12
// baseline (speedup 1.0000x reference)
#include <cuda_runtime.h>
#include <cuda_bf16.h>
#include <math.h>

#define BSZ    2
#define ERA    35718
#define HMESH  10242
#define NSRC_F (BSZ*ERA)      // 71436
#define NDST_F (BSZ*HMESH)    // 20484
#define E_E2H  107154
#define E_H2H  61440
#define E_H2E  107154
#define HID    256
#define K_F    102
#define K_B    260
#define OUTC   96

// offsets into g_wred (precomputed attention-reduced weight vectors)
#define OFF_WSA_F 0     // 102
#define OFF_WCA_F 104   // 5
#define OFF_WEA_F 112   // 3
#define OFF_WSA_B 128   // 260
#define OFF_WCA_B 392   // 5
#define OFF_WEA_B 400   // 3
#define OFF_WER   408   // 12 : (l*2+h)*4 + k

// ---------------- scratch (static device arrays; no allocation) ----------------
__device__ float g_Vf   [NSRC_F*HID];
__device__ float g_psrc_f[NSRC_F];
__device__ float g_pctx_f[NDST_F];
__device__ float g_pqs  [NDST_F*2];
__device__ float g_pqd  [NDST_F*2];
__device__ float g_psrc_b[NDST_F];
__device__ float g_pctx_b[NSRC_F];
__device__ float g_xlat [NDST_F*HID];
__device__ float g_q    [NDST_F*HID];
__device__ float g_gout [NDST_F*HID];
__device__ float g_h    [NDST_F*HID];
__device__ float g_Vb   [NDST_F*OUTC];
__device__ float g_wred [512];

// CSR (per-batch graphs; shared across the 2 batches)
__device__ int g_ptr_e2h[HMESH+1];  __device__ int g_pos_e2h[HMESH];  __device__ int g_eid_e2h[E_E2H];
__device__ int g_ptr_h2h[HMESH+1];  __device__ int g_pos_h2h[HMESH];  __device__ int g_eid_h2h[E_H2H];
__device__ int g_ptr_h2e[ERA+1];    __device__ int g_pos_h2e[ERA];    __device__ int g_eid_h2e[E_H2E];

// ---------------- CSR build ----------------
#define N_CSR_ZERO (2*HMESH + ERA)
#define E_CSR_ALL  (E_E2H + E_H2H + E_H2E)

__global__ void k_csr_zero() {
    int i = blockIdx.x * blockDim.x + threadIdx.x;
    if (i < HMESH)                 g_pos_e2h[i] = 0;
    else if (i < 2*HMESH)          g_pos_h2h[i - HMESH] = 0;
    else if (i < N_CSR_ZERO)       g_pos_h2e[i - 2*HMESH] = 0;
}

__global__ void k_csr_count(const int* __restrict__ e2h, const int* __restrict__ h2h,
                            const int* __restrict__ h2e) {
    int i = blockIdx.x * blockDim.x + threadIdx.x;
    if (i < E_E2H)                        atomicAdd(&g_pos_e2h[e2h[E_E2H + i]], 1);
    else if (i < E_E2H + E_H2H)           atomicAdd(&g_pos_h2h[h2h[E_H2H + (i - E_E2H)]], 1);
    else if (i < E_CSR_ALL)               atomicAdd(&g_pos_h2e[h2e[E_H2E + (i - E_E2H - E_H2H)]], 1);
}

// one block per graph; carry-loop block scan. pos becomes the running fill cursor.
__global__ void k_csr_scan() {
    __shared__ int sm[32];
    int g = blockIdx.x;
    int* cnt = (g == 0) ? g_pos_e2h : (g == 1) ? g_pos_h2h : g_pos_h2e;
    int* ptr = (g == 0) ? g_ptr_e2h : (g == 1) ? g_ptr_h2h : g_ptr_h2e;
    int n    = (g == 2) ? ERA : HMESH;
    int t = threadIdx.x, lane = t & 31, wid = t >> 5;
    int carry = 0;
    for (int base = 0; base < n; base += 1024) {
        int v = (base + t < n) ? cnt[base + t] : 0;
        int x = v;
#pragma unroll
        for (int o = 1; o < 32; o <<= 1) {
            int y = __shfl_up_sync(0xffffffff, x, o);
            if (lane >= o) x += y;
        }
        if (lane == 31) sm[wid] = x;
        __syncthreads();
        if (wid == 0) {
            int s = sm[lane];
#pragma unroll
            for (int o = 1; o < 32; o <<= 1) {
                int y = __shfl_up_sync(0xffffffff, s, o);
                if (lane >= o) s += y;
            }
            sm[lane] = s;
        }
        __syncthreads();
        int warp_off = (wid > 0) ? sm[wid - 1] : 0;
        int total = sm[31];
        int excl = carry + warp_off + x - v;
        if (base + t < n) { ptr[base + t] = excl; cnt[base + t] = excl; }
        carry += total;
        __syncthreads();
    }
    if (t == 0) ptr[n] = carry;
}

__global__ void k_csr_fill(const int* __restrict__ e2h, const int* __restrict__ h2h,
                           const int* __restrict__ h2e) {
    int i = blockIdx.x * blockDim.x + threadIdx.x;
    if (i < E_E2H) {
        int idx = atomicAdd(&g_pos_e2h[e2h[E_E2H + i]], 1);
        g_eid_e2h[idx] = i;
    } else if (i < E_E2H + E_H2H) {
        int eo = i - E_E2H;
        int idx = atomicAdd(&g_pos_h2h[h2h[E_H2H + eo]], 1);
        g_eid_h2h[idx] = eo;
    } else if (i < E_CSR_ALL) {
        int eo = i - E_E2H - E_H2H;
        int idx = atomicAdd(&g_pos_h2e[h2e[E_H2E + eo]], 1);
        g_eid_h2e[idx] = eo;
    }
}

// ---------------- precompute reduced weight vectors ----------------
__global__ void k_precompute(const float* fmWsrc, const float* fmWctx, const float* fmWedge,
                             const float* fmAtt,
                             const float* bmWsrc, const float* bmWctx, const float* bmWedge,
                             const float* bmAtt,
                             const float* gatWe, const float* gatAe) {
    int t = threadIdx.x;  // 512 threads
    if (t < K_F) {
        float a = 0.f;
        for (int j = 0; j < HID; j++) a += fmWsrc[t*HID + j] * fmAtt[j];
        g_wred[OFF_WSA_F + t] = a;
    } else if (t < K_F + 5) {
        int r = t - K_F; float a = 0.f;
        for (int j = 0; j < HID; j++) a += fmWctx[r*HID + j] * fmAtt[j];
        g_wred[OFF_WCA_F + r] = a;
    } else if (t < K_F + 8) {
        int r = t - K_F - 5; float a = 0.f;
        for (int j = 0; j < HID; j++) a += fmWedge[r*HID + j] * fmAtt[j];
        g_wred[OFF_WEA_F + r] = a;
    }
    if (t >= 128 && t < 128 + K_B) {
        int r = t - 128; float a = 0.f;
        for (int j = 0; j < OUTC; j++) a += bmWsrc[r*OUTC + j] * bmAtt[j];
        g_wred[OFF_WSA_B + r] = a;
    }
    if (t >= 400 && t < 405) {
        int r = t - 400; float a = 0.f;
        for (int j = 0; j < OUTC; j++) a += bmWctx[r*OUTC + j] * bmAtt[j];
        g_wred[OFF_WCA_B + r] = a;
    }
    if (t >= 405 && t < 408) {
        int r = t - 405; float a = 0.f;
        for (int j = 0; j < OUTC; j++) a += bmWedge[r*OUTC + j] * bmAtt[j];
        g_wred[OFF_WEA_B + r] = a;
    }
    if (t >= 408 && t < 420) {
        int idx = t - 408;
        int l = idx / 6, h = (idx % 6) / 3, k = idx % 3;
        float a = 0.f;
        for (int dd = 0; dd < 128; dd++)
            a += gatWe[((l*3 + k)*2 + h)*128 + dd] * gatAe[(l*2 + h)*128 + dd];
        g_wred[OFF_WER + (l*2 + h)*4 + k] = a;
    }
}

// ---------------- psrc_f (dot only; x_in concat is fused into the GEMM loader) --------
__global__ void k_psrc_f(const float* __restrict__ x, const float* __restrict__ era_ll) {
    int w = (blockIdx.x * blockDim.x + threadIdx.x) >> 5;
    int lane = threadIdx.x & 31;
    if (w >= NSRC_F) return;
    int node = w % ERA;
    float acc = 0.f;
#pragma unroll
    for (int it = 0; it < 4; it++) {
        int c = lane + it * 32;
        float v = 0.f;
        if (c < 98)       v = x[(size_t)w * 98 + c];
        else if (c < 102) v = era_ll[node * 4 + (c - 98)];
        if (c < 102) acc += v * g_wred[OFF_WSA_F + c];
    }
    for (int o = 16; o > 0; o >>= 1) acc += __shfl_down_sync(0xffffffff, acc, o);
    if (lane == 0) g_psrc_f[w] = acc;
}

__global__ void k_pctx_f(const float* __restrict__ fm_ctx, const float* __restrict__ h_ll) {
    int d = blockIdx.x * blockDim.x + threadIdx.x;
    if (d >= NDST_F) return;
    int node = d % HMESH;
    float a = fm_ctx[node] * g_wred[OFF_WCA_F];
#pragma unroll
    for (int k = 0; k < 4; k++) a += h_ll[node * 4 + k] * g_wred[OFF_WCA_F + 1 + k];
    g_pctx_f[d] = a;
}

// ---------------- tf32 tensor-core GEMM with fused A-loaders + optional pq epilogue ----
// amode 0: A[row*lda+k]
// amode 1: x_in on the fly  (k<98: x[row*98+k]; 98<=k<102: era_ll[(row%ERA)*4+k-98])
// amode 2: x_proc on the fly (k<256: gout+xlat; 256<=k<260: h_ll[(row%HMESH)*4+k-256])
// pq epilogue (pqs!=null): blockIdx.y==head; block cols == that head's 128 dims, so each
// block computes FINAL pqs/pqd for its 128 rows (shfl over tig + smem reduce, no atomics).
#define SMS 136

__device__ __forceinline__ unsigned cvt_tf32(float f) {
    unsigned r;
    asm("cvt.rna.tf32.f32 %0, %1;" : "=r"(r) : "f"(f));
    return r;
}

__device__ __forceinline__ float loadA(int amode, const float* __restrict__ A, int lda,
                                       const float* __restrict__ ax, int row, int node, int k) {
    if (amode == 0) return A[(size_t)row * lda + k];
    if (amode == 1) {
        if (k < 98)  return A[(size_t)row * 98 + k];
        if (k < 102) return ax[node * 4 + (k - 98)];
        return 0.f;
    }
    if (k < 256) return g_gout[(size_t)row * 256 + k] + g_xlat[(size_t)row * 256 + k];
    if (k < 260) return ax[node * 4 + (k - 256)];
    return 0.f;
}

__global__ __launch_bounds__(256, 2) void k_gemm(const float* __restrict__ A, int lda,
                                                 const float* __restrict__ B,
                                                 float* __restrict__ C,
                                                 int M, int N, int K,
                                                 int amode, const float* __restrict__ ax,
                                                 const float* __restrict__ pqa_s,
                                                 const float* __restrict__ pqa_d,
                                                 float* pqs, float* pqd) {
    __shared__ unsigned As[2][16 * SMS];
    __shared__ unsigned Bs[2][16 * SMS];
    __shared__ float sAs[128], sAd[128];
    __shared__ float sred[128][2];
    int tid = threadIdx.x;
    int wid = tid >> 5, lane = tid & 31;
    int m0 = blockIdx.x * 128, n0 = blockIdx.y * 128;
    int head = blockIdx.y;
    int warpM = wid >> 2, warpN = wid & 3;
    int gid = lane >> 2, tig = lane & 3;
    bool do_pq = (pqs != nullptr);

    int am = tid >> 1, ak = (tid & 1) * 8;
    int bk = tid >> 4, bn = (tid & 15) * 8;
    int grow = m0 + am;
    int nodediv = (amode == 1) ? ERA : HMESH;
    int anode = grow % nodediv;

    if (do_pq && tid < 128) {
        sAs[tid] = pqa_s[head * 128 + tid];
        sAd[tid] = pqa_d[head * 128 + tid];
        sred[tid][0] = 0.f; sred[tid][1] = 0.f;
    }

    float cacc[4][4][4];
#pragma unroll
    for (int i = 0; i < 4; i++)
#pragma unroll
        for (int j = 0; j < 4; j++)
#pragma unroll
            for (int r = 0; r < 4; r++) cacc[i][j][r] = 0.f;

    float ra[8], rb[8];

#pragma unroll
    for (int i = 0; i < 8; i++) {
        int k = ak + i;
        ra[i] = (grow < M && k < K) ? loadA(amode, A, lda, ax, grow, anode, k) : 0.f;
    }
#pragma unroll
    for (int i = 0; i < 8; i++) {
        int gn = n0 + bn + i;
        rb[i] = (bk < K && gn < N) ? B[(size_t)bk * N + gn] : 0.f;
    }
#pragma unroll
    for (int i = 0; i < 8; i++) As[0][(ak + i) * SMS + am] = cvt_tf32(ra[i]);
#pragma unroll
    for (int i = 0; i < 8; i++) Bs[0][bk * SMS + bn + i] = cvt_tf32(rb[i]);
    __syncthreads();

    int p = 0;
    for (int k0 = 16; k0 < K + 16; k0 += 16) {
        bool has_next = (k0 < K);
        if (has_next) {
#pragma unroll
            for (int i = 0; i < 8; i++) {
                int k = k0 + ak + i;
                ra[i] = (grow < M && k < K) ? loadA(amode, A, lda, ax, grow, anode, k) : 0.f;
            }
            int kg = k0 + bk;
#pragma unroll
            for (int i = 0; i < 8; i++) {
                int gn = n0 + bn + i;
                rb[i] = (kg < K && gn < N) ? B[(size_t)kg * N + gn] : 0.f;
            }
        }
#pragma unroll
        for (int ks = 0; ks < 2; ks++) {
            unsigned af[4][4], bf[4][2];
#pragma unroll
            for (int mt = 0; mt < 4; mt++) {
                int mb = warpM * 64 + mt * 16;
                int base = (ks * 8 + tig) * SMS + mb + gid;
                af[mt][0] = As[p][base];
                af[mt][1] = As[p][base + 8];
                af[mt][2] = As[p][base + 4 * SMS];
                af[mt][3] = As[p][base + 4 * SMS + 8];
            }
#pragma unroll
            for (int nt = 0; nt < 4; nt++) {
                int nb = warpN * 32 + nt * 8;
                int base = (ks * 8 + tig) * SMS + nb + gid;
                bf[nt][0] = Bs[p][base];
                bf[nt][1] = Bs[p][base + 4 * SMS];
            }
#pragma unroll
            for (int mt = 0; mt < 4; mt++)
#pragma unroll
                for (int nt = 0; nt < 4; nt++) {
                    asm volatile(
                        "mma.sync.aligned.m16n8k8.row.col.f32.tf32.tf32.f32 "
                        "{%0,%1,%2,%3}, {%4,%5,%6,%7}, {%8,%9}, {%0,%1,%2,%3};"
                        : "+f"(cacc[mt][nt][0]), "+f"(cacc[mt][nt][1]),
                          "+f"(cacc[mt][nt][2]), "+f"(cacc[mt][nt][3])
                        : "r"(af[mt][0]), "r"(af[mt][1]), "r"(af[mt][2]), "r"(af[mt][3]),
                          "r"(bf[nt][0]), "r"(bf[nt][1]));
                }
        }
        if (has_next) {
            int q = p ^ 1;
#pragma unroll
            for (int i = 0; i < 8; i++) As[q][(ak + i) * SMS + am] = cvt_tf32(ra[i]);
#pragma unroll
            for (int i = 0; i < 8; i++) Bs[q][bk * SMS + bn + i] = cvt_tf32(rb[i]);
            __syncthreads();
            p = q;
        }
    }

    // C store
#pragma unroll
    for (int mt = 0; mt < 4; mt++) {
#pragma unroll
        for (int nt = 0; nt < 4; nt++) {
            int row0 = m0 + warpM * 64 + mt * 16 + gid;
            int col  = n0 + warpN * 32 + nt * 8 + 2 * tig;
            if (col + 1 < N) {
                if (row0 < M)
                    *(float2*)&C[(size_t)row0 * N + col] =
                        make_float2(cacc[mt][nt][0], cacc[mt][nt][1]);
                if (row0 + 8 < M)
                    *(float2*)&C[(size_t)(row0 + 8) * N + col] =
                        make_float2(cacc[mt][nt][2], cacc[mt][nt][3]);
            }
        }
    }

    // fused pq epilogue
    if (do_pq) {
        float ps[4][2], pd[4][2];
#pragma unroll
        for (int mt = 0; mt < 4; mt++) { ps[mt][0]=ps[mt][1]=pd[mt][0]=pd[mt][1]=0.f; }
#pragma unroll
        for (int mt = 0; mt < 4; mt++)
#pragma unroll
            for (int nt = 0; nt < 4; nt++) {
                int cl = warpN * 32 + nt * 8 + 2 * tig;
                float as0 = sAs[cl], as1 = sAs[cl + 1];
                float ad0 = sAd[cl], ad1 = sAd[cl + 1];
                ps[mt][0] += cacc[mt][nt][0]*as0 + cacc[mt][nt][1]*as1;
                pd[mt][0] += cacc[mt][nt][0]*ad0 + cacc[mt][nt][1]*ad1;
                ps[mt][1] += cacc[mt][nt][2]*as0 + cacc[mt][nt][3]*as1;
                pd[mt][1] += cacc[mt][nt][2]*ad0 + cacc[mt][nt][3]*ad1;
            }
        // reduce over tig (lanes sharing gid)
#pragma unroll
        for (int off = 1; off < 4; off <<= 1) {
#pragma unroll
            for (int mt = 0; mt < 4; mt++)
#pragma unroll
                for (int r = 0; r < 2; r++) {
                    ps[mt][r] += __shfl_xor_sync(0xffffffffu, ps[mt][r], off);
                    pd[mt][r] += __shfl_xor_sync(0xffffffffu, pd[mt][r], off);
                }
        }
        if (tig == 0) {
#pragma unroll
            for (int mt = 0; mt < 4; mt++)
#pragma unroll
                for (int r = 0; r < 2; r++) {
                    int rl = warpM * 64 + mt * 16 + gid + r * 8;
                    atomicAdd(&sred[rl][0], ps[mt][r]);
                    atomicAdd(&sred[rl][1], pd[mt][r]);
                }
        }
        __syncthreads();
        if (tid < 128) {
            int row = m0 + tid;
            if (row < M) {
                pqs[row * 2 + head] = sred[tid][0];
                pqd[row * 2 + head] = sred[tid][1];
            }
        }
    }
}

// ---------------- fused gathers: lane-parallel logits + shfl-broadcast accumulate ----------
__device__ __forceinline__ void fwd_edge_meta(int p0, int idx, int cnt, int b, float pc,
                                              const int* __restrict__ e2h,
                                              const float* __restrict__ ea,
                                              int &s, float &ev) {
    s = 0; ev = 0.f;
    if (idx < cnt) {
        int eo = g_eid_e2h[p0 + idx];
        s = e2h[eo] + b * ERA;
        float pe = ea[eo*3]   * g_wred[OFF_WEA_F]
                 + ea[eo*3+1] * g_wred[OFF_WEA_F+1]
                 + ea[eo*3+2] * g_wred[OFF_WEA_F+2];
        float l = g_psrc_f[s] + pc + pe;
        l = l > 0.f ? l : 0.2f * l;
        ev = expf(l);
    }
}

__global__ void k_fwd_gather(const int* __restrict__ e2h, const float* __restrict__ ea) {
    int w = (blockIdx.x * blockDim.x + threadIdx.x) >> 5;
    int lane = threadIdx.x & 31;
    if (w >= NDST_F * 2) return;
    int half = w & 1, d = w >> 1;
    int node = d % HMESH, b = d / HMESH;
    int p0 = g_ptr_e2h[node];
    int cnt = g_ptr_e2h[node + 1] - p0;
    float pc = g_pctx_f[d];

    int s0; float e0;
    fwd_edge_meta(p0, lane, cnt, b, pc, e2h, ea, s0, e0);
    float ssum = e0;
    for (int base = 32; base < cnt; base += 32) {
        int st; float et;
        fwd_edge_meta(p0, base + lane, cnt, b, pc, e2h, ea, st, et);
        ssum += et;
    }
#pragma unroll
    for (int o = 16; o > 0; o >>= 1) ssum += __shfl_xor_sync(0xffffffffu, ssum, o);
    float inv = 1.f / (ssum + 1e-9f);

    float4 acc = make_float4(0.f, 0.f, 0.f, 0.f);
    int c = half * 128 + lane * 4;
    int n1 = cnt < 32 ? cnt : 32;
    for (int j = 0; j < n1; j++) {
        int s = __shfl_sync(0xffffffffu, s0, j);
        float alpha = __shfl_sync(0xffffffffu, e0, j) * inv;
        float4 v = *(const float4*)&g_Vf[s * HID + c];
        acc.x += alpha * v.x; acc.y += alpha * v.y;
        acc.z += alpha * v.z; acc.w += alpha * v.w;
    }
    for (int base = 32; base < cnt; base += 32) {
        int st; float et;
        fwd_edge_meta(p0, base + lane, cnt, b, pc, e2h, ea, st, et);
        int nn = (cnt - base) < 32 ? (cnt - base) : 32;
        for (int j = 0; j < nn; j++) {
            int s = __shfl_sync(0xffffffffu, st, j);
            float alpha = __shfl_sync(0xffffffffu, et, j) * inv;
            float4 v = *(const float4*)&g_Vf[s * HID + c];
            acc.x += alpha * v.x; acc.y += alpha * v.y;
            acc.z += alpha * v.z; acc.w += alpha * v.w;
        }
    }
    *(float4*)&g_xlat[d * HID + c] = acc;
}

__device__ __forceinline__ void gat_edge_meta(int p0, int idx, int cnt, int b, int h,
                                              float pqd_d, int l,
                                              const int* __restrict__ h2h,
                                              const float* __restrict__ ea,
                                              int &s, float &ev) {
    s = 0; ev = 0.f;
    if (idx < cnt) {
        int eo = g_eid_h2h[p0 + idx];
        s = h2h[eo] + b * HMESH;
        const float* wer = &g_wred[OFF_WER + (l*2 + h)*4];
        float pe = ea[eo*3]*wer[0] + ea[eo*3+1]*wer[1] + ea[eo*3+2]*wer[2];
        float lg = g_pqs[s*2 + h] + pqd_d + pe;
        lg = lg > 0.f ? lg : 0.2f * lg;
        ev = expf(lg);
    }
}

__global__ void k_gat_gather(const int* __restrict__ h2h, const float* __restrict__ ea,
                             float* __restrict__ outbuf, int l, int apply_gelu) {
    int w = (blockIdx.x * blockDim.x + threadIdx.x) >> 5;
    int lane = threadIdx.x & 31;
    if (w >= NDST_F * 2) return;
    int half = w & 1, d = w >> 1;
    int node = d % HMESH, b = d / HMESH;
    int p0 = g_ptr_h2h[node];
    int cnt = g_ptr_h2h[node + 1] - p0;
    float pqd_d = g_pqd[d*2 + half];

    int s0; float e0;
    gat_edge_meta(p0, lane, cnt, b, half, pqd_d, l, h2h, ea, s0, e0);
    float ssum = e0;
    for (int base = 32; base < cnt; base += 32) {
        int st; float et;
        gat_edge_meta(p0, base + lane, cnt, b, half, pqd_d, l, h2h, ea, st, et);
        ssum += et;
    }
#pragma unroll
    for (int o = 16; o > 0; o >>= 1) ssum += __shfl_xor_sync(0xffffffffu, ssum, o);
    float inv = 1.f / (ssum + 1e-9f);

    float4 acc = make_float4(0.f, 0.f, 0.f, 0.f);
    int c = half * 128 + lane * 4;
    int n1 = cnt < 32 ? cnt : 32;
    for (int j = 0; j < n1; j++) {
        int s = __shfl_sync(0xffffffffu, s0, j);
        float alpha = __shfl_sync(0xffffffffu, e0, j) * inv;
        float4 v = *(const float4*)&g_q[s * HID + c];
        acc.x += alpha * v.x; acc.y += alpha * v.y;
        acc.z += alpha * v.z; acc.w += alpha * v.w;
    }
    for (int base = 32; base < cnt; base += 32) {
        int st; float et;
        gat_edge_meta(p0, base + lane, cnt, b, half, pqd_d, l, h2h, ea, st, et);
        int nn = (cnt - base) < 32 ? (cnt - base) : 32;
        for (int j = 0; j < nn; j++) {
            int s = __shfl_sync(0xffffffffu, st, j);
            float alpha = __shfl_sync(0xffffffffu, et, j) * inv;
            float4 v = *(const float4*)&g_q[s * HID + c];
            acc.x += alpha * v.x; acc.y += alpha * v.y;
            acc.z += alpha * v.z; acc.w += alpha * v.w;
        }
    }
    if (apply_gelu) {
        float* a = &acc.x;
#pragma unroll
        for (int i = 0; i < 4; i++) {
            float xx = a[i];
            float t = tanhf(0.7978845608f * (xx + 0.044715f * xx * xx * xx));
            a[i] = 0.5f * xx * (1.f + t);
        }
    }
    *(float4*)&outbuf[d * HID + c] = acc;
}

__device__ __forceinline__ void bwd_edge_meta(int p0, int idx, int cnt, int b, float pc,
                                              const int* __restrict__ h2e,
                                              const float* __restrict__ ea,
                                              int &s, float &ev) {
    s = 0; ev = 0.f;
    if (idx < cnt) {
        int eo = g_eid_h2e[p0 + idx];
        s = h2e[eo] + b * HMESH;
        float pe = ea[eo*3]   * g_wred[OFF_WEA_B]
                 + ea[eo*3+1] * g_wred[OFF_WEA_B+1]
                 + ea[eo*3+2] * g_wred[OFF_WEA_B+2];
        float l = g_psrc_b[s] + pc + pe;
        l = l > 0.f ? l : 0.2f * l;
        ev = expf(l);
    }
}

__global__ void k_bwd_gather(const int* __restrict__ h2e, const float* __restrict__ ea,
                             const float* __restrict__ x, float* __restrict__ out) {
    int w = (blockIdx.x * blockDim.x + threadIdx.x) >> 5;
    int lane = threadIdx.x & 31;
    if (w >= NSRC_F) return;
    int node = w % ERA, b = w / ERA;
    int p0 = g_ptr_h2e[node];
    int cnt = g_ptr_h2e[node + 1] - p0;
    float pc = g_pctx_b[w];

    int s0; float e0;
    bwd_edge_meta(p0, lane, cnt, b, pc, h2e, ea, s0, e0);
    float ssum = e0;
    for (int base = 32; base < cnt; base += 32) {
        int st; float et;
        bwd_edge_meta(p0, base + lane, cnt, b, pc, h2e, ea, st, et);
        ssum += et;
    }
#pragma unroll
    for (int o = 16; o > 0; o >>= 1) ssum += __shfl_xor_sync(0xffffffffu, ssum, o);
    float inv = 1.f / (ssum + 1e-9f);

    int c = lane * 4;
    float4 acc = make_float4(0.f, 0.f, 0.f, 0.f);
    int n1 = cnt < 32 ? cnt : 32;
    for (int j = 0; j < n1; j++) {
        int s = __shfl_sync(0xffffffffu, s0, j);
        float alpha = __shfl_sync(0xffffffffu, e0, j) * inv;
        if (lane < 24) {
            float4 v = *(const float4*)&g_Vb[s * OUTC + c];
            acc.x += alpha * v.x; acc.y += alpha * v.y;
            acc.z += alpha * v.z; acc.w += alpha * v.w;
        }
    }
    for (int base = 32; base < cnt; base += 32) {
        int st; float et;
        bwd_edge_meta(p0, base + lane, cnt, b, pc, h2e, ea, st, et);
        int nn = (cnt - base) < 32 ? (cnt - base) : 32;
        for (int j = 0; j < nn; j++) {
            int s = __shfl_sync(0xffffffffu, st, j);
            float alpha = __shfl_sync(0xffffffffu, et, j) * inv;
            if (lane < 24) {
                float4 v = *(const float4*)&g_Vb[s * OUTC + c];
                acc.x += alpha * v.x; acc.y += alpha * v.y;
                acc.z += alpha * v.z; acc.w += alpha * v.w;
            }
        }
    }
    if (lane < 24) {
        const float* xr = &x[(size_t)w * 98 + c];
        acc.x += xr[0]; acc.y += xr[1]; acc.z += xr[2]; acc.w += xr[3];
        *(float4*)&out[w * OUTC + c] = acc;
    }
}

// ---------------- decoder prep: psrc_b dot only (x_proc concat fused into GEMM) -------
__global__ void k_psrc_b(const float* __restrict__ h_ll) {
    int n = (blockIdx.x * blockDim.x + threadIdx.x) >> 5;
    int lane = threadIdx.x & 31;
    if (n >= NDST_F) return;
    int node = n % HMESH;
    float acc = 0.f;
#pragma unroll
    for (int it = 0; it < 9; it++) {
        int c = lane + it * 32;
        if (c < K_B) {
            float v;
            if (c < 256) v = g_gout[n * HID + c] + g_xlat[n * HID + c];
            else         v = h_ll[node * 4 + (c - 256)];
            acc += v * g_wred[OFF_WSA_B + c];
        }
    }
    for (int o = 16; o > 0; o >>= 1) acc += __shfl_down_sync(0xffffffff, acc, o);
    if (lane == 0) g_psrc_b[n] = acc;
}

__global__ void k_pctx_b(const float* __restrict__ bm_ctx, const float* __restrict__ era_ll) {
    int d = blockIdx.x * blockDim.x + threadIdx.x;
    if (d >= NSRC_F) return;
    int node = d % ERA;
    float a = bm_ctx[node] * g_wred[OFF_WCA_B];
#pragma unroll
    for (int k = 0; k < 4; k++) a += era_ll[node * 4 + k] * g_wred[OFF_WCA_B + 1 + k];
    g_pctx_b[d] = a;
}

// ---------------- host ----------------
static float* sym(const void* s) { void* p = nullptr; cudaGetSymbolAddress(&p, s); return (float*)p; }

extern "C" void kernel_launch(void* const* d_in, const int* in_sizes, int n_in,
                              void* d_out, int out_size) {
    const float* x        = (const float*)d_in[0];
    const int*   e2h      = (const int*)  d_in[1];
    const int*   h2h      = (const int*)  d_in[2];
    const int*   h2e      = (const int*)  d_in[3];
    const float* e2h_attr = (const float*)d_in[4];
    const float* h2h_attr = (const float*)d_in[5];
    const float* h2e_attr = (const float*)d_in[6];
    const float* era_ll   = (const float*)d_in[7];
    const float* h_ll     = (const float*)d_in[8];
    const float* fm_ctx   = (const float*)d_in[9];
    const float* fm_Wsrc  = (const float*)d_in[10];
    const float* fm_Wctx  = (const float*)d_in[11];
    const float* fm_Wedge = (const float*)d_in[12];
    const float* fm_att   = (const float*)d_in[13];
    const float* fm_Wval  = (const float*)d_in[14];
    const float* bm_ctx   = (const float*)d_in[15];
    const float* bm_Wsrc  = (const float*)d_in[16];
    const float* bm_Wctx  = (const float*)d_in[17];
    const float* bm_Wedge = (const float*)d_in[18];
    const float* bm_att   = (const float*)d_in[19];
    const float* bm_Wval  = (const float*)d_in[20];
    const float* gat_W    = (const float*)d_in[21];
    const float* gat_We   = (const float*)d_in[22];
    const float* gat_asrc = (const float*)d_in[23];
    const float* gat_adst = (const float*)d_in[24];
    const float* gat_ae   = (const float*)d_in[25];
    float* out = (float*)d_out;

    float* p_Vf   = sym(g_Vf);
    float* p_xlat = sym(g_xlat);
    float* p_q    = sym(g_q);
    float* p_gout = sym(g_gout);
    float* p_h    = sym(g_h);
    float* p_Vb   = sym(g_Vb);
    float* p_pqs  = sym(g_pqs);
    float* p_pqd  = sym(g_pqd);

    const int T = 256;
    auto cdiv = [](int a, int b) { return (a + b - 1) / b; };

    // CSR build (depends only on index inputs)
    k_csr_zero<<<cdiv(N_CSR_ZERO, T), T>>>();
    k_csr_count<<<cdiv(E_CSR_ALL, T), T>>>(e2h, h2h, h2e);
    k_csr_scan<<<3, 1024>>>();
    k_csr_fill<<<cdiv(E_CSR_ALL, T), T>>>(e2h, h2h, h2e);

    k_precompute<<<1, 512>>>(fm_Wsrc, fm_Wctx, fm_Wedge, fm_att,
                             bm_Wsrc, bm_Wctx, bm_Wedge, bm_att, gat_We, gat_ae);
    k_psrc_f<<<cdiv(NSRC_F * 32, T), T>>>(x, era_ll);
    k_pctx_f<<<cdiv(NDST_F, T), T>>>(fm_ctx, h_ll);

    // Vf = x_in @ fm_Wval  (A built on the fly from x + era_ll)
    k_gemm<<<dim3(cdiv(NSRC_F, 128), 2), 256>>>(x, 0, fm_Wval, p_Vf, NSRC_F, HID, K_F,
                                                1, era_ll, nullptr, nullptr,
                                                nullptr, nullptr);

    k_fwd_gather<<<cdiv(NDST_F * 2 * 32, T), T>>>(e2h, e2h_attr);

    // GAT layers: pq dots fused into the GEMM epilogue
    for (int l = 0; l < 2; l++) {
        const float* hin = (l == 0) ? p_xlat : p_h;
        k_gemm<<<dim3(cdiv(NDST_F, 128), 2), 256>>>(hin, HID, gat_W + l * HID * HID, p_q,
                                                    NDST_F, HID, HID,
                                                    0, nullptr,
                                                    gat_asrc + l * 256, gat_adst + l * 256,
                                                    p_pqs, p_pqd);
        k_gat_gather<<<cdiv(NDST_F * 2 * 32, T), T>>>(h2h, h2h_attr,
                                                      (l == 0) ? p_h : p_gout, l,
                                                      (l == 0) ? 1 : 0);
    }

    // decoder
    k_psrc_b<<<cdiv(NDST_F * 32, T), T>>>(h_ll);
    k_pctx_b<<<cdiv(NSRC_F, T), T>>>(bm_ctx, era_ll);
    // Vb = x_proc @ bm_Wval  (A built on the fly from gout+xlat + h_ll)
    k_gemm<<<dim3(cdiv(NDST_F, 128), 1), 256>>>(nullptr, 0, bm_Wval, p_Vb, NDST_F, OUTC, K_B,
                                                2, h_ll, nullptr, nullptr,
                                                nullptr, nullptr);

    k_bwd_gather<<<cdiv(NSRC_F * 32, T), T>>>(h2e, h2e_attr, x, out);
}

// round 13
// speedup vs baseline: 1.2134x; 1.2134x over previous
#include <cuda_runtime.h>
#include <cuda_bf16.h>
#include <math.h>

#define BSZ    2
#define ERA    35718
#define HMESH  10242
#define NSRC_F (BSZ*ERA)      // 71436
#define NDST_F (BSZ*HMESH)    // 20484
#define E_E2H  107154
#define E_H2H  61440
#define E_H2E  107154
#define HID    256
#define K_F    102
#define LDA_F  104
#define K_B    260
#define OUTC   96

// offsets into g_wred (precomputed attention-reduced weight vectors)
#define OFF_WSA_F 0     // 102
#define OFF_WCA_F 104   // 5
#define OFF_WEA_F 112   // 3
#define OFF_WSA_B 128   // 260
#define OFF_WCA_B 392   // 5
#define OFF_WEA_B 400   // 3
#define OFF_WER   408   // 12 : (l*2+h)*4 + k

// ---------------- scratch (static device arrays; no allocation) ----------------
__device__ float g_xin  [NSRC_F*LDA_F];
__device__ float g_Vf   [NSRC_F*HID];
__device__ float g_psrc_f[NSRC_F];
__device__ float g_pctx_f[NDST_F];
__device__ float g_pqs  [NDST_F*2];
__device__ float g_pqd  [NDST_F*2];
__device__ float g_psrc_b[NDST_F];
__device__ float g_pctx_b[NSRC_F];
__device__ float g_xlat [NDST_F*HID];
__device__ float g_q    [NDST_F*HID];
__device__ float g_gout [NDST_F*HID];
__device__ float g_h    [NDST_F*HID];
__device__ float g_xpc  [NDST_F*K_B];
__device__ float g_Vb   [NDST_F*OUTC];
__device__ float g_wred [512];

// CSR (per-batch graphs; shared across the 2 batches)
__device__ int g_ptr_e2h[HMESH+1];  __device__ int g_pos_e2h[HMESH];  __device__ int g_eid_e2h[E_E2H];
__device__ int g_ptr_h2h[HMESH+1];  __device__ int g_pos_h2h[HMESH];  __device__ int g_eid_h2h[E_H2H];
__device__ int g_ptr_h2e[ERA+1];    __device__ int g_pos_h2e[ERA];    __device__ int g_eid_h2e[E_H2E];

// ---------------- CSR build ----------------
#define N_CSR_ZERO (2*HMESH + ERA)
#define E_CSR_ALL  (E_E2H + E_H2H + E_H2E)

__global__ void k_csr_zero() {
    int i = blockIdx.x * blockDim.x + threadIdx.x;
    if (i < HMESH)                 g_pos_e2h[i] = 0;
    else if (i < 2*HMESH)          g_pos_h2h[i - HMESH] = 0;
    else if (i < N_CSR_ZERO)       g_pos_h2e[i - 2*HMESH] = 0;
}

__global__ void k_csr_count(const int* __restrict__ e2h, const int* __restrict__ h2h,
                            const int* __restrict__ h2e) {
    int i = blockIdx.x * blockDim.x + threadIdx.x;
    if (i < E_E2H)                        atomicAdd(&g_pos_e2h[e2h[E_E2H + i]], 1);
    else if (i < E_E2H + E_H2H)           atomicAdd(&g_pos_h2h[h2h[E_H2H + (i - E_E2H)]], 1);
    else if (i < E_CSR_ALL)               atomicAdd(&g_pos_h2e[h2e[E_H2E + (i - E_E2H - E_H2H)]], 1);
}

// one block per graph; carry-loop block scan. pos becomes the running fill cursor.
__global__ void k_csr_scan() {
    __shared__ int sm[32];
    int g = blockIdx.x;
    int* cnt = (g == 0) ? g_pos_e2h : (g == 1) ? g_pos_h2h : g_pos_h2e;
    int* ptr = (g == 0) ? g_ptr_e2h : (g == 1) ? g_ptr_h2h : g_ptr_h2e;
    int n    = (g == 2) ? ERA : HMESH;
    int t = threadIdx.x, lane = t & 31, wid = t >> 5;
    int carry = 0;
    for (int base = 0; base < n; base += 1024) {
        int v = (base + t < n) ? cnt[base + t] : 0;
        int x = v;
#pragma unroll
        for (int o = 1; o < 32; o <<= 1) {
            int y = __shfl_up_sync(0xffffffff, x, o);
            if (lane >= o) x += y;
        }
        if (lane == 31) sm[wid] = x;
        __syncthreads();
        if (wid == 0) {
            int s = sm[lane];
#pragma unroll
            for (int o = 1; o < 32; o <<= 1) {
                int y = __shfl_up_sync(0xffffffff, s, o);
                if (lane >= o) s += y;
            }
            sm[lane] = s;
        }
        __syncthreads();
        int warp_off = (wid > 0) ? sm[wid - 1] : 0;
        int total = sm[31];
        int excl = carry + warp_off + x - v;
        if (base + t < n) { ptr[base + t] = excl; cnt[base + t] = excl; }
        carry += total;
        __syncthreads();
    }
    if (t == 0) ptr[n] = carry;
}

__global__ void k_csr_fill(const int* __restrict__ e2h, const int* __restrict__ h2h,
                           const int* __restrict__ h2e) {
    int i = blockIdx.x * blockDim.x + threadIdx.x;
    if (i < E_E2H) {
        int idx = atomicAdd(&g_pos_e2h[e2h[E_E2H + i]], 1);
        g_eid_e2h[idx] = i;
    } else if (i < E_E2H + E_H2H) {
        int eo = i - E_E2H;
        int idx = atomicAdd(&g_pos_h2h[h2h[E_H2H + eo]], 1);
        g_eid_h2h[idx] = eo;
    } else if (i < E_CSR_ALL) {
        int eo = i - E_E2H - E_H2H;
        int idx = atomicAdd(&g_pos_h2e[h2e[E_H2E + eo]], 1);
        g_eid_h2e[idx] = eo;
    }
}

// ---------------- precompute reduced weight vectors ----------------
__global__ void k_precompute(const float* fmWsrc, const float* fmWctx, const float* fmWedge,
                             const float* fmAtt,
                             const float* bmWsrc, const float* bmWctx, const float* bmWedge,
                             const float* bmAtt,
                             const float* gatWe, const float* gatAe) {
    int t = threadIdx.x;  // 512 threads
    if (t < K_F) {
        float a = 0.f;
        for (int j = 0; j < HID; j++) a += fmWsrc[t*HID + j] * fmAtt[j];
        g_wred[OFF_WSA_F + t] = a;
    } else if (t < K_F + 5) {
        int r = t - K_F; float a = 0.f;
        for (int j = 0; j < HID; j++) a += fmWctx[r*HID + j] * fmAtt[j];
        g_wred[OFF_WCA_F + r] = a;
    } else if (t < K_F + 8) {
        int r = t - K_F - 5; float a = 0.f;
        for (int j = 0; j < HID; j++) a += fmWedge[r*HID + j] * fmAtt[j];
        g_wred[OFF_WEA_F + r] = a;
    }
    if (t >= 128 && t < 128 + K_B) {
        int r = t - 128; float a = 0.f;
        for (int j = 0; j < OUTC; j++) a += bmWsrc[r*OUTC + j] * bmAtt[j];
        g_wred[OFF_WSA_B + r] = a;
    }
    if (t >= 400 && t < 405) {
        int r = t - 400; float a = 0.f;
        for (int j = 0; j < OUTC; j++) a += bmWctx[r*OUTC + j] * bmAtt[j];
        g_wred[OFF_WCA_B + r] = a;
    }
    if (t >= 405 && t < 408) {
        int r = t - 405; float a = 0.f;
        for (int j = 0; j < OUTC; j++) a += bmWedge[r*OUTC + j] * bmAtt[j];
        g_wred[OFF_WEA_B + r] = a;
    }
    if (t >= 408 && t < 420) {
        int idx = t - 408;
        int l = idx / 6, h = (idx % 6) / 3, k = idx % 3;
        float a = 0.f;
        for (int dd = 0; dd < 128; dd++)
            a += gatWe[((l*3 + k)*2 + h)*128 + dd] * gatAe[(l*2 + h)*128 + dd];
        g_wred[OFF_WER + (l*2 + h)*4 + k] = a;
    }
}

// ---------------- build x_in (concat + pad) and psrc_f ----------------
__global__ void k_build_xin(const float* __restrict__ x, const float* __restrict__ era_ll) {
    int w = (blockIdx.x * blockDim.x + threadIdx.x) >> 5;
    int lane = threadIdx.x & 31;
    if (w >= NSRC_F) return;
    int node = w % ERA;
    float acc = 0.f;
#pragma unroll
    for (int it = 0; it < 4; it++) {
        int c = lane + it * 32;
        float v = 0.f;
        if (c < 98)       v = x[(size_t)w * 98 + c];
        else if (c < 102) v = era_ll[node * 4 + (c - 98)];
        if (c < LDA_F) g_xin[w * LDA_F + c] = v;
        if (c < 102)   acc += v * g_wred[OFF_WSA_F + c];
    }
    for (int o = 16; o > 0; o >>= 1) acc += __shfl_down_sync(0xffffffff, acc, o);
    if (lane == 0) g_psrc_f[w] = acc;
}

__global__ void k_pctx_f(const float* __restrict__ fm_ctx, const float* __restrict__ h_ll) {
    int d = blockIdx.x * blockDim.x + threadIdx.x;
    if (d >= NDST_F) return;
    int node = d % HMESH;
    float a = fm_ctx[node] * g_wred[OFF_WCA_F];
#pragma unroll
    for (int k = 0; k < 4; k++) a += h_ll[node * 4 + k] * g_wred[OFF_WCA_F + 1 + k];
    g_pctx_f[d] = a;
}

// ---------------- tf32 tensor-core GEMM: C[M,N] = A[M,K(lda)] * B[K,N] ----------------
// vectorized (float4) global loads; all strides 16B-aligned by construction.
#define SMS 136

__device__ __forceinline__ unsigned cvt_tf32(float f) {
    unsigned r;
    asm("cvt.rna.tf32.f32 %0, %1;" : "=r"(r) : "f"(f));
    return r;
}

__device__ __forceinline__ void load_a8(const float* __restrict__ A, size_t base,
                                        int k, int K, float* ra) {
    if (k + 7 < K) {
        float4 v0 = *(const float4*)&A[base + k];
        float4 v1 = *(const float4*)&A[base + k + 4];
        ra[0]=v0.x; ra[1]=v0.y; ra[2]=v0.z; ra[3]=v0.w;
        ra[4]=v1.x; ra[5]=v1.y; ra[6]=v1.z; ra[7]=v1.w;
    } else {
#pragma unroll
        for (int i = 0; i < 8; i++) ra[i] = (k + i < K) ? A[base + k + i] : 0.f;
    }
}

__device__ __forceinline__ void load_b8(const float* __restrict__ B, int kg, int K,
                                        int N, int gn0, float* rb) {
    if (kg < K) {
        if (gn0 + 7 < N) {
            float4 v0 = *(const float4*)&B[(size_t)kg * N + gn0];
            float4 v1 = *(const float4*)&B[(size_t)kg * N + gn0 + 4];
            rb[0]=v0.x; rb[1]=v0.y; rb[2]=v0.z; rb[3]=v0.w;
            rb[4]=v1.x; rb[5]=v1.y; rb[6]=v1.z; rb[7]=v1.w;
        } else {
#pragma unroll
            for (int i = 0; i < 8; i++)
                rb[i] = (gn0 + i < N) ? B[(size_t)kg * N + gn0 + i] : 0.f;
        }
    } else {
#pragma unroll
        for (int i = 0; i < 8; i++) rb[i] = 0.f;
    }
}

__global__ __launch_bounds__(256, 2) void k_gemm(const float* __restrict__ A, int lda,
                                                 const float* __restrict__ B,
                                                 float* __restrict__ C,
                                                 int M, int N, int K) {
    __shared__ unsigned As[2][16 * SMS];
    __shared__ unsigned Bs[2][16 * SMS];
    int tid = threadIdx.x;
    int wid = tid >> 5, lane = tid & 31;
    int m0 = blockIdx.x * 128, n0 = blockIdx.y * 128;
    int warpM = wid >> 2, warpN = wid & 3;
    int gid = lane >> 2, tig = lane & 3;

    int am = tid >> 1, ak = (tid & 1) * 8;
    int bk = tid >> 4, bn = (tid & 15) * 8;
    int grow = m0 + am;
    size_t abase = (size_t)grow * lda;

    float cacc[4][4][4];
#pragma unroll
    for (int i = 0; i < 4; i++)
#pragma unroll
        for (int j = 0; j < 4; j++)
#pragma unroll
            for (int r = 0; r < 4; r++) cacc[i][j][r] = 0.f;

    float ra[8], rb[8];

    if (grow < M) load_a8(A, abase, ak, K, ra);
    else { 
#pragma unroll
        for (int i = 0; i < 8; i++) ra[i] = 0.f; 
    }
    load_b8(B, bk, K, N, n0 + bn, rb);
#pragma unroll
    for (int i = 0; i < 8; i++) As[0][(ak + i) * SMS + am] = cvt_tf32(ra[i]);
#pragma unroll
    for (int i = 0; i < 8; i++) Bs[0][bk * SMS + bn + i] = cvt_tf32(rb[i]);
    __syncthreads();

    int p = 0;
    for (int k0 = 16; k0 < K + 16; k0 += 16) {
        bool has_next = (k0 < K);
        if (has_next) {
            if (grow < M) load_a8(A, abase, k0 + ak, K, ra);
            else { 
#pragma unroll
                for (int i = 0; i < 8; i++) ra[i] = 0.f; 
            }
            load_b8(B, k0 + bk, K, N, n0 + bn, rb);
        }
#pragma unroll
        for (int ks = 0; ks < 2; ks++) {
            unsigned af[4][4], bf[4][2];
#pragma unroll
            for (int mt = 0; mt < 4; mt++) {
                int mb = warpM * 64 + mt * 16;
                int base = (ks * 8 + tig) * SMS + mb + gid;
                af[mt][0] = As[p][base];
                af[mt][1] = As[p][base + 8];
                af[mt][2] = As[p][base + 4 * SMS];
                af[mt][3] = As[p][base + 4 * SMS + 8];
            }
#pragma unroll
            for (int nt = 0; nt < 4; nt++) {
                int nb = warpN * 32 + nt * 8;
                int base = (ks * 8 + tig) * SMS + nb + gid;
                bf[nt][0] = Bs[p][base];
                bf[nt][1] = Bs[p][base + 4 * SMS];
            }
#pragma unroll
            for (int mt = 0; mt < 4; mt++)
#pragma unroll
                for (int nt = 0; nt < 4; nt++) {
                    asm volatile(
                        "mma.sync.aligned.m16n8k8.row.col.f32.tf32.tf32.f32 "
                        "{%0,%1,%2,%3}, {%4,%5,%6,%7}, {%8,%9}, {%0,%1,%2,%3};"
                        : "+f"(cacc[mt][nt][0]), "+f"(cacc[mt][nt][1]),
                          "+f"(cacc[mt][nt][2]), "+f"(cacc[mt][nt][3])
                        : "r"(af[mt][0]), "r"(af[mt][1]), "r"(af[mt][2]), "r"(af[mt][3]),
                          "r"(bf[nt][0]), "r"(bf[nt][1]));
                }
        }
        if (has_next) {
            int q = p ^ 1;
#pragma unroll
            for (int i = 0; i < 8; i++) As[q][(ak + i) * SMS + am] = cvt_tf32(ra[i]);
#pragma unroll
            for (int i = 0; i < 8; i++) Bs[q][bk * SMS + bn + i] = cvt_tf32(rb[i]);
            __syncthreads();
            p = q;
        }
    }

#pragma unroll
    for (int mt = 0; mt < 4; mt++) {
#pragma unroll
        for (int nt = 0; nt < 4; nt++) {
            int row0 = m0 + warpM * 64 + mt * 16 + gid;
            int col  = n0 + warpN * 32 + nt * 8 + 2 * tig;
            if (col + 1 < N) {
                if (row0 < M)
                    *(float2*)&C[(size_t)row0 * N + col] =
                        make_float2(cacc[mt][nt][0], cacc[mt][nt][1]);
                if (row0 + 8 < M)
                    *(float2*)&C[(size_t)(row0 + 8) * N + col] =
                        make_float2(cacc[mt][nt][2], cacc[mt][nt][3]);
            }
        }
    }
}

// ---------------- fused gathers: lane-parallel logits + shfl-broadcast accumulate ----------
__device__ __forceinline__ void fwd_edge_meta(int p0, int idx, int cnt, int b, float pc,
                                              const int* __restrict__ e2h,
                                              const float* __restrict__ ea,
                                              int &s, float &ev) {
    s = 0; ev = 0.f;
    if (idx < cnt) {
        int eo = g_eid_e2h[p0 + idx];
        s = e2h[eo] + b * ERA;
        float pe = ea[eo*3]   * g_wred[OFF_WEA_F]
                 + ea[eo*3+1] * g_wred[OFF_WEA_F+1]
                 + ea[eo*3+2] * g_wred[OFF_WEA_F+2];
        float l = g_psrc_f[s] + pc + pe;
        l = l > 0.f ? l : 0.2f * l;
        ev = expf(l);
    }
}

__global__ void k_fwd_gather(const int* __restrict__ e2h, const float* __restrict__ ea) {
    int w = (blockIdx.x * blockDim.x + threadIdx.x) >> 5;
    int lane = threadIdx.x & 31;
    if (w >= NDST_F * 2) return;
    int half = w & 1, d = w >> 1;
    int node = d % HMESH, b = d / HMESH;
    int p0 = g_ptr_e2h[node];
    int cnt = g_ptr_e2h[node + 1] - p0;
    float pc = g_pctx_f[d];

    int s0; float e0;
    fwd_edge_meta(p0, lane, cnt, b, pc, e2h, ea, s0, e0);
    float ssum = e0;
    for (int base = 32; base < cnt; base += 32) {
        int st; float et;
        fwd_edge_meta(p0, base + lane, cnt, b, pc, e2h, ea, st, et);
        ssum += et;
    }
#pragma unroll
    for (int o = 16; o > 0; o >>= 1) ssum += __shfl_xor_sync(0xffffffffu, ssum, o);
    float inv = 1.f / (ssum + 1e-9f);

    float4 acc = make_float4(0.f, 0.f, 0.f, 0.f);
    int c = half * 128 + lane * 4;
    int n1 = cnt < 32 ? cnt : 32;
    for (int j = 0; j < n1; j++) {
        int s = __shfl_sync(0xffffffffu, s0, j);
        float alpha = __shfl_sync(0xffffffffu, e0, j) * inv;
        float4 v = *(const float4*)&g_Vf[s * HID + c];
        acc.x += alpha * v.x; acc.y += alpha * v.y;
        acc.z += alpha * v.z; acc.w += alpha * v.w;
    }
    for (int base = 32; base < cnt; base += 32) {
        int st; float et;
        fwd_edge_meta(p0, base + lane, cnt, b, pc, e2h, ea, st, et);
        int nn = (cnt - base) < 32 ? (cnt - base) : 32;
        for (int j = 0; j < nn; j++) {
            int s = __shfl_sync(0xffffffffu, st, j);
            float alpha = __shfl_sync(0xffffffffu, et, j) * inv;
            float4 v = *(const float4*)&g_Vf[s * HID + c];
            acc.x += alpha * v.x; acc.y += alpha * v.y;
            acc.z += alpha * v.z; acc.w += alpha * v.w;
        }
    }
    *(float4*)&g_xlat[d * HID + c] = acc;
}

__device__ __forceinline__ void gat_edge_meta(int p0, int idx, int cnt, int b, int h,
                                              float pqd_d, int l,
                                              const int* __restrict__ h2h,
                                              const float* __restrict__ ea,
                                              int &s, float &ev) {
    s = 0; ev = 0.f;
    if (idx < cnt) {
        int eo = g_eid_h2h[p0 + idx];
        s = h2h[eo] + b * HMESH;
        const float* wer = &g_wred[OFF_WER + (l*2 + h)*4];
        float pe = ea[eo*3]*wer[0] + ea[eo*3+1]*wer[1] + ea[eo*3+2]*wer[2];
        float lg = g_pqs[s*2 + h] + pqd_d + pe;
        lg = lg > 0.f ? lg : 0.2f * lg;
        ev = expf(lg);
    }
}

__global__ void k_gat_gather(const int* __restrict__ h2h, const float* __restrict__ ea,
                             float* __restrict__ outbuf, int l, int apply_gelu) {
    int w = (blockIdx.x * blockDim.x + threadIdx.x) >> 5;
    int lane = threadIdx.x & 31;
    if (w >= NDST_F * 2) return;
    int half = w & 1, d = w >> 1;
    int node = d % HMESH, b = d / HMESH;
    int p0 = g_ptr_h2h[node];
    int cnt = g_ptr_h2h[node + 1] - p0;
    float pqd_d = g_pqd[d*2 + half];

    int s0; float e0;
    gat_edge_meta(p0, lane, cnt, b, half, pqd_d, l, h2h, ea, s0, e0);
    float ssum = e0;
    for (int base = 32; base < cnt; base += 32) {
        int st; float et;
        gat_edge_meta(p0, base + lane, cnt, b, half, pqd_d, l, h2h, ea, st, et);
        ssum += et;
    }
#pragma unroll
    for (int o = 16; o > 0; o >>= 1) ssum += __shfl_xor_sync(0xffffffffu, ssum, o);
    float inv = 1.f / (ssum + 1e-9f);

    float4 acc = make_float4(0.f, 0.f, 0.f, 0.f);
    int c = half * 128 + lane * 4;
    int n1 = cnt < 32 ? cnt : 32;
    for (int j = 0; j < n1; j++) {
        int s = __shfl_sync(0xffffffffu, s0, j);
        float alpha = __shfl_sync(0xffffffffu, e0, j) * inv;
        float4 v = *(const float4*)&g_q[s * HID + c];
        acc.x += alpha * v.x; acc.y += alpha * v.y;
        acc.z += alpha * v.z; acc.w += alpha * v.w;
    }
    for (int base = 32; base < cnt; base += 32) {
        int st; float et;
        gat_edge_meta(p0, base + lane, cnt, b, half, pqd_d, l, h2h, ea, st, et);
        int nn = (cnt - base) < 32 ? (cnt - base) : 32;
        for (int j = 0; j < nn; j++) {
            int s = __shfl_sync(0xffffffffu, st, j);
            float alpha = __shfl_sync(0xffffffffu, et, j) * inv;
            float4 v = *(const float4*)&g_q[s * HID + c];
            acc.x += alpha * v.x; acc.y += alpha * v.y;
            acc.z += alpha * v.z; acc.w += alpha * v.w;
        }
    }
    if (apply_gelu) {
        float* a = &acc.x;
#pragma unroll
        for (int i = 0; i < 4; i++) {
            float xx = a[i];
            float t = tanhf(0.7978845608f * (xx + 0.044715f * xx * xx * xx));
            a[i] = 0.5f * xx * (1.f + t);
        }
    }
    *(float4*)&outbuf[d * HID + c] = acc;
}

__device__ __forceinline__ void bwd_edge_meta(int p0, int idx, int cnt, int b, float pc,
                                              const int* __restrict__ h2e,
                                              const float* __restrict__ ea,
                                              int &s, float &ev) {
    s = 0; ev = 0.f;
    if (idx < cnt) {
        int eo = g_eid_h2e[p0 + idx];
        s = h2e[eo] + b * HMESH;
        float pe = ea[eo*3]   * g_wred[OFF_WEA_B]
                 + ea[eo*3+1] * g_wred[OFF_WEA_B+1]
                 + ea[eo*3+2] * g_wred[OFF_WEA_B+2];
        float l = g_psrc_b[s] + pc + pe;
        l = l > 0.f ? l : 0.2f * l;
        ev = expf(l);
    }
}

__global__ void k_bwd_gather(const int* __restrict__ h2e, const float* __restrict__ ea,
                             const float* __restrict__ x, float* __restrict__ out) {
    int w = (blockIdx.x * blockDim.x + threadIdx.x) >> 5;
    int lane = threadIdx.x & 31;
    if (w >= NSRC_F) return;
    int node = w % ERA, b = w / ERA;
    int p0 = g_ptr_h2e[node];
    int cnt = g_ptr_h2e[node + 1] - p0;
    float pc = g_pctx_b[w];

    int s0; float e0;
    bwd_edge_meta(p0, lane, cnt, b, pc, h2e, ea, s0, e0);
    float ssum = e0;
    for (int base = 32; base < cnt; base += 32) {
        int st; float et;
        bwd_edge_meta(p0, base + lane, cnt, b, pc, h2e, ea, st, et);
        ssum += et;
    }
#pragma unroll
    for (int o = 16; o > 0; o >>= 1) ssum += __shfl_xor_sync(0xffffffffu, ssum, o);
    float inv = 1.f / (ssum + 1e-9f);

    int c = lane * 4;
    float4 acc = make_float4(0.f, 0.f, 0.f, 0.f);
    int n1 = cnt < 32 ? cnt : 32;
    for (int j = 0; j < n1; j++) {
        int s = __shfl_sync(0xffffffffu, s0, j);
        float alpha = __shfl_sync(0xffffffffu, e0, j) * inv;
        if (lane < 24) {
            float4 v = *(const float4*)&g_Vb[s * OUTC + c];
            acc.x += alpha * v.x; acc.y += alpha * v.y;
            acc.z += alpha * v.z; acc.w += alpha * v.w;
        }
    }
    for (int base = 32; base < cnt; base += 32) {
        int st; float et;
        bwd_edge_meta(p0, base + lane, cnt, b, pc, h2e, ea, st, et);
        int nn = (cnt - base) < 32 ? (cnt - base) : 32;
        for (int j = 0; j < nn; j++) {
            int s = __shfl_sync(0xffffffffu, st, j);
            float alpha = __shfl_sync(0xffffffffu, et, j) * inv;
            if (lane < 24) {
                float4 v = *(const float4*)&g_Vb[s * OUTC + c];
                acc.x += alpha * v.x; acc.y += alpha * v.y;
                acc.z += alpha * v.z; acc.w += alpha * v.w;
            }
        }
    }
    if (lane < 24) {
        const float* xr = &x[(size_t)w * 98 + c];
        acc.x += xr[0]; acc.y += xr[1]; acc.z += xr[2]; acc.w += xr[3];
        *(float4*)&out[w * OUTC + c] = acc;
    }
}

// ---------------- GAT per-node scalars ----------------
__global__ void k_gat_pq(const float* __restrict__ asrc, const float* __restrict__ adst) {
    int w = (blockIdx.x * blockDim.x + threadIdx.x) >> 5;
    int lane = threadIdx.x & 31;
    if (w >= NDST_F * 2) return;
    int n = w >> 1, h = w & 1;
    const float* qrow = &g_q[n * HID + h * 128];
    float as_ = 0.f, ad_ = 0.f;
#pragma unroll
    for (int it = 0; it < 4; it++) {
        int dd = lane + it * 32;
        float qv = qrow[dd];
        as_ += qv * asrc[h * 128 + dd];
        ad_ += qv * adst[h * 128 + dd];
    }
    for (int o = 16; o > 0; o >>= 1) {
        as_ += __shfl_down_sync(0xffffffff, as_, o);
        ad_ += __shfl_down_sync(0xffffffff, ad_, o);
    }
    if (lane == 0) { g_pqs[w] = as_; g_pqd[w] = ad_; }
}

// ---------------- decoder prep ----------------
__global__ void k_xpc(const float* __restrict__ h_ll) {
    int n = (blockIdx.x * blockDim.x + threadIdx.x) >> 5;
    int lane = threadIdx.x & 31;
    if (n >= NDST_F) return;
    int node = n % HMESH;
    float acc = 0.f;
#pragma unroll
    for (int it = 0; it < 9; it++) {
        int c = lane + it * 32;
        if (c < K_B) {
            float v;
            if (c < 256) v = g_gout[n * HID + c] + g_xlat[n * HID + c];
            else         v = h_ll[node * 4 + (c - 256)];
            g_xpc[n * K_B + c] = v;
            acc += v * g_wred[OFF_WSA_B + c];
        }
    }
    for (int o = 16; o > 0; o >>= 1) acc += __shfl_down_sync(0xffffffff, acc, o);
    if (lane == 0) g_psrc_b[n] = acc;
}

__global__ void k_pctx_b(const float* __restrict__ bm_ctx, const float* __restrict__ era_ll) {
    int d = blockIdx.x * blockDim.x + threadIdx.x;
    if (d >= NSRC_F) return;
    int node = d % ERA;
    float a = bm_ctx[node] * g_wred[OFF_WCA_B];
#pragma unroll
    for (int k = 0; k < 4; k++) a += era_ll[node * 4 + k] * g_wred[OFF_WCA_B + 1 + k];
    g_pctx_b[d] = a;
}

// ---------------- host ----------------
static float* sym(const void* s) { void* p = nullptr; cudaGetSymbolAddress(&p, s); return (float*)p; }

extern "C" void kernel_launch(void* const* d_in, const int* in_sizes, int n_in,
                              void* d_out, int out_size) {
    const float* x        = (const float*)d_in[0];
    const int*   e2h      = (const int*)  d_in[1];
    const int*   h2h      = (const int*)  d_in[2];
    const int*   h2e      = (const int*)  d_in[3];
    const float* e2h_attr = (const float*)d_in[4];
    const float* h2h_attr = (const float*)d_in[5];
    const float* h2e_attr = (const float*)d_in[6];
    const float* era_ll   = (const float*)d_in[7];
    const float* h_ll     = (const float*)d_in[8];
    const float* fm_ctx   = (const float*)d_in[9];
    const float* fm_Wsrc  = (const float*)d_in[10];
    const float* fm_Wctx  = (const float*)d_in[11];
    const float* fm_Wedge = (const float*)d_in[12];
    const float* fm_att   = (const float*)d_in[13];
    const float* fm_Wval  = (const float*)d_in[14];
    const float* bm_ctx   = (const float*)d_in[15];
    const float* bm_Wsrc  = (const float*)d_in[16];
    const float* bm_Wctx  = (const float*)d_in[17];
    const float* bm_Wedge = (const float*)d_in[18];
    const float* bm_att   = (const float*)d_in[19];
    const float* bm_Wval  = (const float*)d_in[20];
    const float* gat_W    = (const float*)d_in[21];
    const float* gat_We   = (const float*)d_in[22];
    const float* gat_asrc = (const float*)d_in[23];
    const float* gat_adst = (const float*)d_in[24];
    const float* gat_ae   = (const float*)d_in[25];
    float* out = (float*)d_out;

    float* p_xin  = sym(g_xin);
    float* p_Vf   = sym(g_Vf);
    float* p_xlat = sym(g_xlat);
    float* p_q    = sym(g_q);
    float* p_gout = sym(g_gout);
    float* p_h    = sym(g_h);
    float* p_xpc  = sym(g_xpc);
    float* p_Vb   = sym(g_Vb);

    const int T = 256;
    auto cdiv = [](int a, int b) { return (a + b - 1) / b; };

    // CSR build (depends only on index inputs)
    k_csr_zero<<<cdiv(N_CSR_ZERO, T), T>>>();
    k_csr_count<<<cdiv(E_CSR_ALL, T), T>>>(e2h, h2h, h2e);
    k_csr_scan<<<3, 1024>>>();
    k_csr_fill<<<cdiv(E_CSR_ALL, T), T>>>(e2h, h2h, h2e);

    k_precompute<<<1, 512>>>(fm_Wsrc, fm_Wctx, fm_Wedge, fm_att,
                             bm_Wsrc, bm_Wctx, bm_Wedge, bm_att, gat_We, gat_ae);
    k_build_xin<<<cdiv(NSRC_F * 32, T), T>>>(x, era_ll);
    k_pctx_f<<<cdiv(NDST_F, T), T>>>(fm_ctx, h_ll);

    // Vf = x_in @ fm_Wval   (tf32 tensor cores)
    k_gemm<<<dim3(cdiv(NSRC_F, 128), 2), 256>>>(p_xin, LDA_F, fm_Wval, p_Vf, NSRC_F, HID, K_F);

    // fused logits+softmax+gather
    k_fwd_gather<<<cdiv(NDST_F * 2 * 32, T), T>>>(e2h, e2h_attr);

    // GAT layers
    for (int l = 0; l < 2; l++) {
        const float* hin = (l == 0) ? p_xlat : p_h;
        k_gemm<<<dim3(cdiv(NDST_F, 128), 2), 256>>>(hin, HID, gat_W + l * HID * HID, p_q,
                                                    NDST_F, HID, HID);
        k_gat_pq<<<cdiv(NDST_F * 2 * 32, T), T>>>(gat_asrc + l * 256, gat_adst + l * 256);
        k_gat_gather<<<cdiv(NDST_F * 2 * 32, T), T>>>(h2h, h2h_attr,
                                                      (l == 0) ? p_h : p_gout, l,
                                                      (l == 0) ? 1 : 0);
    }

    // decoder
    k_xpc<<<cdiv(NDST_F * 32, T), T>>>(h_ll);
    k_pctx_b<<<cdiv(NSRC_F, T), T>>>(bm_ctx, era_ll);
    k_gemm<<<dim3(cdiv(NDST_F, 128), 1), 256>>>(p_xpc, K_B, bm_Wval, p_Vb, NDST_F, OUTC, K_B);

    k_bwd_gather<<<cdiv(NSRC_F * 32, T), T>>>(h2e, h2e_attr, x, out);
}

// round 14
// speedup vs baseline: 1.3085x; 1.0783x over previous
#include <cuda_runtime.h>
#include <cuda_bf16.h>
#include <math.h>

#define BSZ    2
#define ERA    35718
#define HMESH  10242
#define NSRC_F (BSZ*ERA)      // 71436
#define NDST_F (BSZ*HMESH)    // 20484
#define E_E2H  107154
#define E_H2H  61440
#define E_H2E  107154
#define HID    256
#define K_F    102
#define LDA_F  104
#define K_B    260
#define OUTC   96

// offsets into g_wred (precomputed attention-reduced weight vectors)
#define OFF_WSA_F 0     // 102
#define OFF_WCA_F 104   // 5
#define OFF_WEA_F 112   // 3
#define OFF_WSA_B 128   // 260
#define OFF_WCA_B 392   // 5
#define OFF_WEA_B 400   // 3
#define OFF_WER   408   // 12 : (l*2+h)*4 + k

// ---------------- scratch (static device arrays; no allocation) ----------------
__device__ float g_xin  [NSRC_F*LDA_F];
__device__ float g_Vf   [NSRC_F*HID];
__device__ float g_psrc_f[NSRC_F];
__device__ float g_pctx_f[NDST_F];
__device__ float g_pqs  [NDST_F*2];
__device__ float g_pqd  [NDST_F*2];
__device__ float g_psrc_b[NDST_F];
__device__ float g_pctx_b[NSRC_F];
__device__ float g_xlat [NDST_F*HID];
__device__ float g_q    [NDST_F*HID];
__device__ float g_gout [NDST_F*HID];
__device__ float g_h    [NDST_F*HID];
__device__ float g_xpc  [NDST_F*K_B];
__device__ float g_Vb   [NDST_F*OUTC];
__device__ float g_wred [512];

// CSR (per-batch graphs; shared across the 2 batches)
__device__ int g_ptr_e2h[HMESH+1];  __device__ int g_pos_e2h[HMESH];  __device__ int g_eid_e2h[E_E2H];
__device__ int g_ptr_h2h[HMESH+1];  __device__ int g_pos_h2h[HMESH];  __device__ int g_eid_h2h[E_H2H];
__device__ int g_ptr_h2e[ERA+1];    __device__ int g_pos_h2e[ERA];    __device__ int g_eid_h2e[E_H2E];

#define N_CSR_ZERO (2*HMESH + ERA)
#define E_CSR_ALL  (E_E2H + E_H2H + E_H2E)
#define ZBLK ((N_CSR_ZERO + 255) / 256)

// ---------------- merged init: csr_zero + weight precompute ----------------
__global__ void k_init(const float* fmWsrc, const float* fmWctx, const float* fmWedge,
                       const float* fmAtt,
                       const float* bmWsrc, const float* bmWctx, const float* bmWedge,
                       const float* bmAtt,
                       const float* gatWe, const float* gatAe) {
    if (blockIdx.x < ZBLK) {
        int i = blockIdx.x * blockDim.x + threadIdx.x;
        if (i < HMESH)                 g_pos_e2h[i] = 0;
        else if (i < 2*HMESH)          g_pos_h2h[i - HMESH] = 0;
        else if (i < N_CSR_ZERO)       g_pos_h2e[i - 2*HMESH] = 0;
        return;
    }
    int t = (blockIdx.x - ZBLK) * 256 + threadIdx.x;  // 0..511
    if (t >= 512) return;
    if (t < K_F) {
        float a = 0.f;
        for (int j = 0; j < HID; j++) a += fmWsrc[t*HID + j] * fmAtt[j];
        g_wred[OFF_WSA_F + t] = a;
    } else if (t < K_F + 5) {
        int r = t - K_F; float a = 0.f;
        for (int j = 0; j < HID; j++) a += fmWctx[r*HID + j] * fmAtt[j];
        g_wred[OFF_WCA_F + r] = a;
    } else if (t < K_F + 8) {
        int r = t - K_F - 5; float a = 0.f;
        for (int j = 0; j < HID; j++) a += fmWedge[r*HID + j] * fmAtt[j];
        g_wred[OFF_WEA_F + r] = a;
    }
    if (t >= 128 && t < 128 + K_B) {
        int r = t - 128; float a = 0.f;
        for (int j = 0; j < OUTC; j++) a += bmWsrc[r*OUTC + j] * bmAtt[j];
        g_wred[OFF_WSA_B + r] = a;
    }
    if (t >= 400 && t < 405) {
        int r = t - 400; float a = 0.f;
        for (int j = 0; j < OUTC; j++) a += bmWctx[r*OUTC + j] * bmAtt[j];
        g_wred[OFF_WCA_B + r] = a;
    }
    if (t >= 405 && t < 408) {
        int r = t - 405; float a = 0.f;
        for (int j = 0; j < OUTC; j++) a += bmWedge[r*OUTC + j] * bmAtt[j];
        g_wred[OFF_WEA_B + r] = a;
    }
    if (t >= 408 && t < 420) {
        int idx = t - 408;
        int l = idx / 6, h = (idx % 6) / 3, k = idx % 3;
        float a = 0.f;
        for (int dd = 0; dd < 128; dd++)
            a += gatWe[((l*3 + k)*2 + h)*128 + dd] * gatAe[(l*2 + h)*128 + dd];
        g_wred[OFF_WER + (l*2 + h)*4 + k] = a;
    }
}

__global__ void k_csr_count(const int* __restrict__ e2h, const int* __restrict__ h2h,
                            const int* __restrict__ h2e) {
    int i = blockIdx.x * blockDim.x + threadIdx.x;
    if (i < E_E2H)                        atomicAdd(&g_pos_e2h[e2h[E_E2H + i]], 1);
    else if (i < E_E2H + E_H2H)           atomicAdd(&g_pos_h2h[h2h[E_H2H + (i - E_E2H)]], 1);
    else if (i < E_CSR_ALL)               atomicAdd(&g_pos_h2e[h2e[E_H2E + (i - E_E2H - E_H2H)]], 1);
}

// one block per graph; carry-loop block scan. pos becomes the running fill cursor.
__global__ void k_csr_scan() {
    __shared__ int sm[32];
    int g = blockIdx.x;
    int* cnt = (g == 0) ? g_pos_e2h : (g == 1) ? g_pos_h2h : g_pos_h2e;
    int* ptr = (g == 0) ? g_ptr_e2h : (g == 1) ? g_ptr_h2h : g_ptr_h2e;
    int n    = (g == 2) ? ERA : HMESH;
    int t = threadIdx.x, lane = t & 31, wid = t >> 5;
    int carry = 0;
    for (int base = 0; base < n; base += 1024) {
        int v = (base + t < n) ? cnt[base + t] : 0;
        int x = v;
#pragma unroll
        for (int o = 1; o < 32; o <<= 1) {
            int y = __shfl_up_sync(0xffffffff, x, o);
            if (lane >= o) x += y;
        }
        if (lane == 31) sm[wid] = x;
        __syncthreads();
        if (wid == 0) {
            int s = sm[lane];
#pragma unroll
            for (int o = 1; o < 32; o <<= 1) {
                int y = __shfl_up_sync(0xffffffff, s, o);
                if (lane >= o) s += y;
            }
            sm[lane] = s;
        }
        __syncthreads();
        int warp_off = (wid > 0) ? sm[wid - 1] : 0;
        int total = sm[31];
        int excl = carry + warp_off + x - v;
        if (base + t < n) { ptr[base + t] = excl; cnt[base + t] = excl; }
        carry += total;
        __syncthreads();
    }
    if (t == 0) ptr[n] = carry;
}

__global__ void k_csr_fill(const int* __restrict__ e2h, const int* __restrict__ h2h,
                           const int* __restrict__ h2e) {
    int i = blockIdx.x * blockDim.x + threadIdx.x;
    if (i < E_E2H) {
        int idx = atomicAdd(&g_pos_e2h[e2h[E_E2H + i]], 1);
        g_eid_e2h[idx] = i;
    } else if (i < E_E2H + E_H2H) {
        int eo = i - E_E2H;
        int idx = atomicAdd(&g_pos_h2h[h2h[E_H2H + eo]], 1);
        g_eid_h2h[idx] = eo;
    } else if (i < E_CSR_ALL) {
        int eo = i - E_E2H - E_H2H;
        int idx = atomicAdd(&g_pos_h2e[h2e[E_H2E + eo]], 1);
        g_eid_h2e[idx] = eo;
    }
}

// ---------------- merged forward prep: build_xin+psrc_f (warps) & pctx_f (threads) ----
#define XIN_BLK ((NSRC_F * 32 + 255) / 256)

__global__ void k_prep_f(const float* __restrict__ x, const float* __restrict__ era_ll,
                         const float* __restrict__ fm_ctx, const float* __restrict__ h_ll) {
    if (blockIdx.x < XIN_BLK) {
        int w = (blockIdx.x * blockDim.x + threadIdx.x) >> 5;
        int lane = threadIdx.x & 31;
        if (w >= NSRC_F) return;
        int node = w % ERA;
        float acc = 0.f;
#pragma unroll
        for (int it = 0; it < 4; it++) {
            int c = lane + it * 32;
            float v = 0.f;
            if (c < 98)       v = x[(size_t)w * 98 + c];
            else if (c < 102) v = era_ll[node * 4 + (c - 98)];
            if (c < LDA_F) g_xin[w * LDA_F + c] = v;
            if (c < 102)   acc += v * g_wred[OFF_WSA_F + c];
        }
        for (int o = 16; o > 0; o >>= 1) acc += __shfl_down_sync(0xffffffff, acc, o);
        if (lane == 0) g_psrc_f[w] = acc;
        return;
    }
    int d = (blockIdx.x - XIN_BLK) * 256 + threadIdx.x;
    if (d >= NDST_F) return;
    int node = d % HMESH;
    float a = fm_ctx[node] * g_wred[OFF_WCA_F];
#pragma unroll
    for (int k = 0; k < 4; k++) a += h_ll[node * 4 + k] * g_wred[OFF_WCA_F + 1 + k];
    g_pctx_f[d] = a;
}

// ---------------- tf32 tensor-core GEMM: C[M,N] = A[M,K(lda)] * B[K,N] ----------------
// vectorized (float4) global loads; all strides 16B-aligned by construction.
#define SMS 136

__device__ __forceinline__ unsigned cvt_tf32(float f) {
    unsigned r;
    asm("cvt.rna.tf32.f32 %0, %1;" : "=r"(r) : "f"(f));
    return r;
}

__device__ __forceinline__ void load_a8(const float* __restrict__ A, size_t base,
                                        int k, int K, float* ra) {
    if (k + 7 < K) {
        float4 v0 = *(const float4*)&A[base + k];
        float4 v1 = *(const float4*)&A[base + k + 4];
        ra[0]=v0.x; ra[1]=v0.y; ra[2]=v0.z; ra[3]=v0.w;
        ra[4]=v1.x; ra[5]=v1.y; ra[6]=v1.z; ra[7]=v1.w;
    } else {
#pragma unroll
        for (int i = 0; i < 8; i++) ra[i] = (k + i < K) ? A[base + k + i] : 0.f;
    }
}

__device__ __forceinline__ void load_b8(const float* __restrict__ B, int kg, int K,
                                        int N, int gn0, float* rb) {
    if (kg < K) {
        if (gn0 + 7 < N) {
            float4 v0 = *(const float4*)&B[(size_t)kg * N + gn0];
            float4 v1 = *(const float4*)&B[(size_t)kg * N + gn0 + 4];
            rb[0]=v0.x; rb[1]=v0.y; rb[2]=v0.z; rb[3]=v0.w;
            rb[4]=v1.x; rb[5]=v1.y; rb[6]=v1.z; rb[7]=v1.w;
        } else {
#pragma unroll
            for (int i = 0; i < 8; i++)
                rb[i] = (gn0 + i < N) ? B[(size_t)kg * N + gn0 + i] : 0.f;
        }
    } else {
#pragma unroll
        for (int i = 0; i < 8; i++) rb[i] = 0.f;
    }
}

__global__ __launch_bounds__(256, 2) void k_gemm(const float* __restrict__ A, int lda,
                                                 const float* __restrict__ B,
                                                 float* __restrict__ C,
                                                 int M, int N, int K) {
    __shared__ unsigned As[2][16 * SMS];
    __shared__ unsigned Bs[2][16 * SMS];
    int tid = threadIdx.x;
    int wid = tid >> 5, lane = tid & 31;
    int m0 = blockIdx.x * 128, n0 = blockIdx.y * 128;
    int warpM = wid >> 2, warpN = wid & 3;
    int gid = lane >> 2, tig = lane & 3;

    int am = tid >> 1, ak = (tid & 1) * 8;
    int bk = tid >> 4, bn = (tid & 15) * 8;
    int grow = m0 + am;
    size_t abase = (size_t)grow * lda;

    float cacc[4][4][4];
#pragma unroll
    for (int i = 0; i < 4; i++)
#pragma unroll
        for (int j = 0; j < 4; j++)
#pragma unroll
            for (int r = 0; r < 4; r++) cacc[i][j][r] = 0.f;

    float ra[8], rb[8];

    if (grow < M) load_a8(A, abase, ak, K, ra);
    else {
#pragma unroll
        for (int i = 0; i < 8; i++) ra[i] = 0.f;
    }
    load_b8(B, bk, K, N, n0 + bn, rb);
#pragma unroll
    for (int i = 0; i < 8; i++) As[0][(ak + i) * SMS + am] = cvt_tf32(ra[i]);
#pragma unroll
    for (int i = 0; i < 8; i++) Bs[0][bk * SMS + bn + i] = cvt_tf32(rb[i]);
    __syncthreads();

    int p = 0;
    for (int k0 = 16; k0 < K + 16; k0 += 16) {
        bool has_next = (k0 < K);
        if (has_next) {
            if (grow < M) load_a8(A, abase, k0 + ak, K, ra);
            else {
#pragma unroll
                for (int i = 0; i < 8; i++) ra[i] = 0.f;
            }
            load_b8(B, k0 + bk, K, N, n0 + bn, rb);
        }
#pragma unroll
        for (int ks = 0; ks < 2; ks++) {
            unsigned af[4][4], bf[4][2];
#pragma unroll
            for (int mt = 0; mt < 4; mt++) {
                int mb = warpM * 64 + mt * 16;
                int base = (ks * 8 + tig) * SMS + mb + gid;
                af[mt][0] = As[p][base];
                af[mt][1] = As[p][base + 8];
                af[mt][2] = As[p][base + 4 * SMS];
                af[mt][3] = As[p][base + 4 * SMS + 8];
            }
#pragma unroll
            for (int nt = 0; nt < 4; nt++) {
                int nb = warpN * 32 + nt * 8;
                int base = (ks * 8 + tig) * SMS + nb + gid;
                bf[nt][0] = Bs[p][base];
                bf[nt][1] = Bs[p][base + 4 * SMS];
            }
#pragma unroll
            for (int mt = 0; mt < 4; mt++)
#pragma unroll
                for (int nt = 0; nt < 4; nt++) {
                    asm volatile(
                        "mma.sync.aligned.m16n8k8.row.col.f32.tf32.tf32.f32 "
                        "{%0,%1,%2,%3}, {%4,%5,%6,%7}, {%8,%9}, {%0,%1,%2,%3};"
                        : "+f"(cacc[mt][nt][0]), "+f"(cacc[mt][nt][1]),
                          "+f"(cacc[mt][nt][2]), "+f"(cacc[mt][nt][3])
                        : "r"(af[mt][0]), "r"(af[mt][1]), "r"(af[mt][2]), "r"(af[mt][3]),
                          "r"(bf[nt][0]), "r"(bf[nt][1]));
                }
        }
        if (has_next) {
            int q = p ^ 1;
#pragma unroll
            for (int i = 0; i < 8; i++) As[q][(ak + i) * SMS + am] = cvt_tf32(ra[i]);
#pragma unroll
            for (int i = 0; i < 8; i++) Bs[q][bk * SMS + bn + i] = cvt_tf32(rb[i]);
            __syncthreads();
            p = q;
        }
    }

#pragma unroll
    for (int mt = 0; mt < 4; mt++) {
#pragma unroll
        for (int nt = 0; nt < 4; nt++) {
            int row0 = m0 + warpM * 64 + mt * 16 + gid;
            int col  = n0 + warpN * 32 + nt * 8 + 2 * tig;
            if (col + 1 < N) {
                if (row0 < M)
                    *(float2*)&C[(size_t)row0 * N + col] =
                        make_float2(cacc[mt][nt][0], cacc[mt][nt][1]);
                if (row0 + 8 < M)
                    *(float2*)&C[(size_t)(row0 + 8) * N + col] =
                        make_float2(cacc[mt][nt][2], cacc[mt][nt][3]);
            }
        }
    }
}

// ---------------- fused gathers: warp per dst, metadata computed ONCE per warp ---------
__device__ __forceinline__ void fwd_edge_meta(int p0, int idx, int cnt, int b, float pc,
                                              const int* __restrict__ e2h,
                                              const float* __restrict__ ea,
                                              int &s, float &ev) {
    s = 0; ev = 0.f;
    if (idx < cnt) {
        int eo = g_eid_e2h[p0 + idx];
        s = e2h[eo] + b * ERA;
        float pe = ea[eo*3]   * g_wred[OFF_WEA_F]
                 + ea[eo*3+1] * g_wred[OFF_WEA_F+1]
                 + ea[eo*3+2] * g_wred[OFF_WEA_F+2];
        float l = g_psrc_f[s] + pc + pe;
        l = l > 0.f ? l : 0.2f * l;
        ev = expf(l);
    }
}

// warp per dst; both column halves accumulated (alpha is head-independent here)
__global__ void k_fwd_gather(const int* __restrict__ e2h, const float* __restrict__ ea) {
    int d = (blockIdx.x * blockDim.x + threadIdx.x) >> 5;
    int lane = threadIdx.x & 31;
    if (d >= NDST_F) return;
    int node = d % HMESH, b = d / HMESH;
    int p0 = g_ptr_e2h[node];
    int cnt = g_ptr_e2h[node + 1] - p0;
    float pc = g_pctx_f[d];

    int s0; float e0;
    fwd_edge_meta(p0, lane, cnt, b, pc, e2h, ea, s0, e0);
    float ssum = e0;
    for (int base = 32; base < cnt; base += 32) {
        int st; float et;
        fwd_edge_meta(p0, base + lane, cnt, b, pc, e2h, ea, st, et);
        ssum += et;
    }
#pragma unroll
    for (int o = 16; o > 0; o >>= 1) ssum += __shfl_xor_sync(0xffffffffu, ssum, o);
    float inv = 1.f / (ssum + 1e-9f);

    float4 acc0 = make_float4(0.f, 0.f, 0.f, 0.f);
    float4 acc1 = make_float4(0.f, 0.f, 0.f, 0.f);
    int c0 = lane * 4, c1 = 128 + lane * 4;
    int n1 = cnt < 32 ? cnt : 32;
    for (int j = 0; j < n1; j++) {
        int s = __shfl_sync(0xffffffffu, s0, j);
        float alpha = __shfl_sync(0xffffffffu, e0, j) * inv;
        float4 v0 = *(const float4*)&g_Vf[s * HID + c0];
        float4 v1 = *(const float4*)&g_Vf[s * HID + c1];
        acc0.x += alpha * v0.x; acc0.y += alpha * v0.y;
        acc0.z += alpha * v0.z; acc0.w += alpha * v0.w;
        acc1.x += alpha * v1.x; acc1.y += alpha * v1.y;
        acc1.z += alpha * v1.z; acc1.w += alpha * v1.w;
    }
    for (int base = 32; base < cnt; base += 32) {
        int st; float et;
        fwd_edge_meta(p0, base + lane, cnt, b, pc, e2h, ea, st, et);
        int nn = (cnt - base) < 32 ? (cnt - base) : 32;
        for (int j = 0; j < nn; j++) {
            int s = __shfl_sync(0xffffffffu, st, j);
            float alpha = __shfl_sync(0xffffffffu, et, j) * inv;
            float4 v0 = *(const float4*)&g_Vf[s * HID + c0];
            float4 v1 = *(const float4*)&g_Vf[s * HID + c1];
            acc0.x += alpha * v0.x; acc0.y += alpha * v0.y;
            acc0.z += alpha * v0.z; acc0.w += alpha * v0.w;
            acc1.x += alpha * v1.x; acc1.y += alpha * v1.y;
            acc1.z += alpha * v1.z; acc1.w += alpha * v1.w;
        }
    }
    *(float4*)&g_xlat[d * HID + c0] = acc0;
    *(float4*)&g_xlat[d * HID + c1] = acc1;
}

__device__ __forceinline__ void gat_edge_meta2(int p0, int idx, int cnt, int b,
                                               float pqd0, float pqd1, int l,
                                               const int* __restrict__ h2h,
                                               const float* __restrict__ ea,
                                               int &s, float &ev0, float &ev1) {
    s = 0; ev0 = 0.f; ev1 = 0.f;
    if (idx < cnt) {
        int eo = g_eid_h2h[p0 + idx];
        s = h2h[eo] + b * HMESH;
        float a0 = ea[eo*3], a1 = ea[eo*3+1], a2 = ea[eo*3+2];
        const float* w0 = &g_wred[OFF_WER + (l*2)*4];
        const float* w1 = &g_wred[OFF_WER + (l*2 + 1)*4];
        float lg0 = g_pqs[s*2]     + pqd0 + a0*w0[0] + a1*w0[1] + a2*w0[2];
        float lg1 = g_pqs[s*2 + 1] + pqd1 + a0*w1[0] + a1*w1[1] + a2*w1[2];
        lg0 = lg0 > 0.f ? lg0 : 0.2f * lg0;
        lg1 = lg1 > 0.f ? lg1 : 0.2f * lg1;
        ev0 = expf(lg0);
        ev1 = expf(lg1);
    }
}

// warp per dst; both heads accumulated in one pass (metadata loaded once)
__global__ void k_gat_gather(const int* __restrict__ h2h, const float* __restrict__ ea,
                             float* __restrict__ outbuf, int l, int apply_gelu) {
    int d = (blockIdx.x * blockDim.x + threadIdx.x) >> 5;
    int lane = threadIdx.x & 31;
    if (d >= NDST_F) return;
    int node = d % HMESH, b = d / HMESH;
    int p0 = g_ptr_h2h[node];
    int cnt = g_ptr_h2h[node + 1] - p0;
    float pqd0 = g_pqd[d*2], pqd1 = g_pqd[d*2 + 1];

    int s0; float e00, e01;
    gat_edge_meta2(p0, lane, cnt, b, pqd0, pqd1, l, h2h, ea, s0, e00, e01);
    float ssum0 = e00, ssum1 = e01;
    for (int base = 32; base < cnt; base += 32) {
        int st; float et0, et1;
        gat_edge_meta2(p0, base + lane, cnt, b, pqd0, pqd1, l, h2h, ea, st, et0, et1);
        ssum0 += et0; ssum1 += et1;
    }
#pragma unroll
    for (int o = 16; o > 0; o >>= 1) {
        ssum0 += __shfl_xor_sync(0xffffffffu, ssum0, o);
        ssum1 += __shfl_xor_sync(0xffffffffu, ssum1, o);
    }
    float inv0 = 1.f / (ssum0 + 1e-9f);
    float inv1 = 1.f / (ssum1 + 1e-9f);

    float4 acc0 = make_float4(0.f, 0.f, 0.f, 0.f);
    float4 acc1 = make_float4(0.f, 0.f, 0.f, 0.f);
    int c0 = lane * 4, c1 = 128 + lane * 4;
    int n1 = cnt < 32 ? cnt : 32;
    for (int j = 0; j < n1; j++) {
        int s = __shfl_sync(0xffffffffu, s0, j);
        float al0 = __shfl_sync(0xffffffffu, e00, j) * inv0;
        float al1 = __shfl_sync(0xffffffffu, e01, j) * inv1;
        float4 v0 = *(const float4*)&g_q[s * HID + c0];
        float4 v1 = *(const float4*)&g_q[s * HID + c1];
        acc0.x += al0 * v0.x; acc0.y += al0 * v0.y;
        acc0.z += al0 * v0.z; acc0.w += al0 * v0.w;
        acc1.x += al1 * v1.x; acc1.y += al1 * v1.y;
        acc1.z += al1 * v1.z; acc1.w += al1 * v1.w;
    }
    for (int base = 32; base < cnt; base += 32) {
        int st; float et0, et1;
        gat_edge_meta2(p0, base + lane, cnt, b, pqd0, pqd1, l, h2h, ea, st, et0, et1);
        int nn = (cnt - base) < 32 ? (cnt - base) : 32;
        for (int j = 0; j < nn; j++) {
            int s = __shfl_sync(0xffffffffu, st, j);
            float al0 = __shfl_sync(0xffffffffu, et0, j) * inv0;
            float al1 = __shfl_sync(0xffffffffu, et1, j) * inv1;
            float4 v0 = *(const float4*)&g_q[s * HID + c0];
            float4 v1 = *(const float4*)&g_q[s * HID + c1];
            acc0.x += al0 * v0.x; acc0.y += al0 * v0.y;
            acc0.z += al0 * v0.z; acc0.w += al0 * v0.w;
            acc1.x += al1 * v1.x; acc1.y += al1 * v1.y;
            acc1.z += al1 * v1.z; acc1.w += al1 * v1.w;
        }
    }
    if (apply_gelu) {
        float* a0 = &acc0.x; float* a1 = &acc1.x;
#pragma unroll
        for (int i = 0; i < 4; i++) {
            float xx = a0[i];
            float t = tanhf(0.7978845608f * (xx + 0.044715f * xx * xx * xx));
            a0[i] = 0.5f * xx * (1.f + t);
            xx = a1[i];
            t = tanhf(0.7978845608f * (xx + 0.044715f * xx * xx * xx));
            a1[i] = 0.5f * xx * (1.f + t);
        }
    }
    *(float4*)&outbuf[d * HID + c0] = acc0;
    *(float4*)&outbuf[d * HID + c1] = acc1;
}

__device__ __forceinline__ void bwd_edge_meta(int p0, int idx, int cnt, int b, float pc,
                                              const int* __restrict__ h2e,
                                              const float* __restrict__ ea,
                                              int &s, float &ev) {
    s = 0; ev = 0.f;
    if (idx < cnt) {
        int eo = g_eid_h2e[p0 + idx];
        s = h2e[eo] + b * HMESH;
        float pe = ea[eo*3]   * g_wred[OFF_WEA_B]
                 + ea[eo*3+1] * g_wred[OFF_WEA_B+1]
                 + ea[eo*3+2] * g_wred[OFF_WEA_B+2];
        float l = g_psrc_b[s] + pc + pe;
        l = l > 0.f ? l : 0.2f * l;
        ev = expf(l);
    }
}

__global__ void k_bwd_gather(const int* __restrict__ h2e, const float* __restrict__ ea,
                             const float* __restrict__ x, float* __restrict__ out) {
    int w = (blockIdx.x * blockDim.x + threadIdx.x) >> 5;
    int lane = threadIdx.x & 31;
    if (w >= NSRC_F) return;
    int node = w % ERA, b = w / ERA;
    int p0 = g_ptr_h2e[node];
    int cnt = g_ptr_h2e[node + 1] - p0;
    float pc = g_pctx_b[w];

    int s0; float e0;
    bwd_edge_meta(p0, lane, cnt, b, pc, h2e, ea, s0, e0);
    float ssum = e0;
    for (int base = 32; base < cnt; base += 32) {
        int st; float et;
        bwd_edge_meta(p0, base + lane, cnt, b, pc, h2e, ea, st, et);
        ssum += et;
    }
#pragma unroll
    for (int o = 16; o > 0; o >>= 1) ssum += __shfl_xor_sync(0xffffffffu, ssum, o);
    float inv = 1.f / (ssum + 1e-9f);

    int c = lane * 4;
    float4 acc = make_float4(0.f, 0.f, 0.f, 0.f);
    int n1 = cnt < 32 ? cnt : 32;
    for (int j = 0; j < n1; j++) {
        int s = __shfl_sync(0xffffffffu, s0, j);
        float alpha = __shfl_sync(0xffffffffu, e0, j) * inv;
        if (lane < 24) {
            float4 v = *(const float4*)&g_Vb[s * OUTC + c];
            acc.x += alpha * v.x; acc.y += alpha * v.y;
            acc.z += alpha * v.z; acc.w += alpha * v.w;
        }
    }
    for (int base = 32; base < cnt; base += 32) {
        int st; float et;
        bwd_edge_meta(p0, base + lane, cnt, b, pc, h2e, ea, st, et);
        int nn = (cnt - base) < 32 ? (cnt - base) : 32;
        for (int j = 0; j < nn; j++) {
            int s = __shfl_sync(0xffffffffu, st, j);
            float alpha = __shfl_sync(0xffffffffu, et, j) * inv;
            if (lane < 24) {
                float4 v = *(const float4*)&g_Vb[s * OUTC + c];
                acc.x += alpha * v.x; acc.y += alpha * v.y;
                acc.z += alpha * v.z; acc.w += alpha * v.w;
            }
        }
    }
    if (lane < 24) {
        const float* xr = &x[(size_t)w * 98 + c];
        acc.x += xr[0]; acc.y += xr[1]; acc.z += xr[2]; acc.w += xr[3];
        *(float4*)&out[w * OUTC + c] = acc;
    }
}

// ---------------- GAT per-node scalars ----------------
__global__ void k_gat_pq(const float* __restrict__ asrc, const float* __restrict__ adst) {
    int w = (blockIdx.x * blockDim.x + threadIdx.x) >> 5;
    int lane = threadIdx.x & 31;
    if (w >= NDST_F * 2) return;
    int n = w >> 1, h = w & 1;
    const float* qrow = &g_q[n * HID + h * 128];
    float as_ = 0.f, ad_ = 0.f;
#pragma unroll
    for (int it = 0; it < 4; it++) {
        int dd = lane + it * 32;
        float qv = qrow[dd];
        as_ += qv * asrc[h * 128 + dd];
        ad_ += qv * adst[h * 128 + dd];
    }
    for (int o = 16; o > 0; o >>= 1) {
        as_ += __shfl_down_sync(0xffffffff, as_, o);
        ad_ += __shfl_down_sync(0xffffffff, ad_, o);
    }
    if (lane == 0) { g_pqs[w] = as_; g_pqd[w] = ad_; }
}

// ---------------- merged decoder prep: xpc+psrc_b (warps) & pctx_b (threads) ----------
#define XPC_BLK ((NDST_F * 32 + 255) / 256)

__global__ void k_prep_b(const float* __restrict__ h_ll,
                         const float* __restrict__ bm_ctx, const float* __restrict__ era_ll) {
    if (blockIdx.x < XPC_BLK) {
        int n = (blockIdx.x * blockDim.x + threadIdx.x) >> 5;
        int lane = threadIdx.x & 31;
        if (n >= NDST_F) return;
        int node = n % HMESH;
        float acc = 0.f;
#pragma unroll
        for (int it = 0; it < 9; it++) {
            int c = lane + it * 32;
            if (c < K_B) {
                float v;
                if (c < 256) v = g_gout[n * HID + c] + g_xlat[n * HID + c];
                else         v = h_ll[node * 4 + (c - 256)];
                g_xpc[n * K_B + c] = v;
                acc += v * g_wred[OFF_WSA_B + c];
            }
        }
        for (int o = 16; o > 0; o >>= 1) acc += __shfl_down_sync(0xffffffff, acc, o);
        if (lane == 0) g_psrc_b[n] = acc;
        return;
    }
    int d = (blockIdx.x - XPC_BLK) * 256 + threadIdx.x;
    if (d >= NSRC_F) return;
    int node = d % ERA;
    float a = bm_ctx[node] * g_wred[OFF_WCA_B];
#pragma unroll
    for (int k = 0; k < 4; k++) a += era_ll[node * 4 + k] * g_wred[OFF_WCA_B + 1 + k];
    g_pctx_b[d] = a;
}

// ---------------- host ----------------
static float* sym(const void* s) { void* p = nullptr; cudaGetSymbolAddress(&p, s); return (float*)p; }

extern "C" void kernel_launch(void* const* d_in, const int* in_sizes, int n_in,
                              void* d_out, int out_size) {
    const float* x        = (const float*)d_in[0];
    const int*   e2h      = (const int*)  d_in[1];
    const int*   h2h      = (const int*)  d_in[2];
    const int*   h2e      = (const int*)  d_in[3];
    const float* e2h_attr = (const float*)d_in[4];
    const float* h2h_attr = (const float*)d_in[5];
    const float* h2e_attr = (const float*)d_in[6];
    const float* era_ll   = (const float*)d_in[7];
    const float* h_ll     = (const float*)d_in[8];
    const float* fm_ctx   = (const float*)d_in[9];
    const float* fm_Wsrc  = (const float*)d_in[10];
    const float* fm_Wctx  = (const float*)d_in[11];
    const float* fm_Wedge = (const float*)d_in[12];
    const float* fm_att   = (const float*)d_in[13];
    const float* fm_Wval  = (const float*)d_in[14];
    const float* bm_ctx   = (const float*)d_in[15];
    const float* bm_Wsrc  = (const float*)d_in[16];
    const float* bm_Wctx  = (const float*)d_in[17];
    const float* bm_Wedge = (const float*)d_in[18];
    const float* bm_att   = (const float*)d_in[19];
    const float* bm_Wval  = (const float*)d_in[20];
    const float* gat_W    = (const float*)d_in[21];
    const float* gat_We   = (const float*)d_in[22];
    const float* gat_asrc = (const float*)d_in[23];
    const float* gat_adst = (const float*)d_in[24];
    const float* gat_ae   = (const float*)d_in[25];
    float* out = (float*)d_out;

    float* p_xin  = sym(g_xin);
    float* p_Vf   = sym(g_Vf);
    float* p_xlat = sym(g_xlat);
    float* p_q    = sym(g_q);
    float* p_gout = sym(g_gout);
    float* p_h    = sym(g_h);
    float* p_xpc  = sym(g_xpc);
    float* p_Vb   = sym(g_Vb);

    const int T = 256;
    auto cdiv = [](int a, int b) { return (a + b - 1) / b; };

    // init (csr_zero + weight precompute) then CSR build
    k_init<<<ZBLK + 2, T>>>(fm_Wsrc, fm_Wctx, fm_Wedge, fm_att,
                            bm_Wsrc, bm_Wctx, bm_Wedge, bm_att, gat_We, gat_ae);
    k_csr_count<<<cdiv(E_CSR_ALL, T), T>>>(e2h, h2h, h2e);
    k_csr_scan<<<3, 1024>>>();
    k_csr_fill<<<cdiv(E_CSR_ALL, T), T>>>(e2h, h2h, h2e);

    k_prep_f<<<XIN_BLK + cdiv(NDST_F, T), T>>>(x, era_ll, fm_ctx, h_ll);

    // Vf = x_in @ fm_Wval   (tf32 tensor cores)
    k_gemm<<<dim3(cdiv(NSRC_F, 128), 2), 256>>>(p_xin, LDA_F, fm_Wval, p_Vf, NSRC_F, HID, K_F);

    // fused logits+softmax+gather (warp per dst, both halves)
    k_fwd_gather<<<cdiv(NDST_F * 32, T), T>>>(e2h, e2h_attr);

    // GAT layers
    for (int l = 0; l < 2; l++) {
        const float* hin = (l == 0) ? p_xlat : p_h;
        k_gemm<<<dim3(cdiv(NDST_F, 128), 2), 256>>>(hin, HID, gat_W + l * HID * HID, p_q,
                                                    NDST_F, HID, HID);
        k_gat_pq<<<cdiv(NDST_F * 2 * 32, T), T>>>(gat_asrc + l * 256, gat_adst + l * 256);
        k_gat_gather<<<cdiv(NDST_F * 32, T), T>>>(h2h, h2h_attr,
                                                  (l == 0) ? p_h : p_gout, l,
                                                  (l == 0) ? 1 : 0);
    }

    // decoder
    k_prep_b<<<XPC_BLK + cdiv(NSRC_F, T), T>>>(h_ll, bm_ctx, era_ll);
    k_gemm<<<dim3(cdiv(NDST_F, 128), 1), 256>>>(p_xpc, K_B, bm_Wval, p_Vb, NDST_F, OUTC, K_B);

    k_bwd_gather<<<cdiv(NSRC_F * 32, T), T>>>(h2e, h2e_attr, x, out);
}

// round 15
// speedup vs baseline: 1.3203x; 1.0091x over previous
#include <cuda_runtime.h>
#include <cuda_bf16.h>
#include <math.h>

#define BSZ    2
#define ERA    35718
#define HMESH  10242
#define NSRC_F (BSZ*ERA)      // 71436
#define NDST_F (BSZ*HMESH)    // 20484
#define E_E2H  107154
#define E_H2H  61440
#define E_H2E  107154
#define HID    256
#define K_F    102
#define LDA_F  104
#define K_B    260
#define OUTC   96

// offsets into g_wred (precomputed attention-reduced weight vectors)
#define OFF_WSA_F 0     // 102
#define OFF_WCA_F 104   // 5
#define OFF_WEA_F 112   // 3
#define OFF_WSA_B 128   // 260
#define OFF_WCA_B 392   // 5
#define OFF_WEA_B 400   // 3
#define OFF_WER   408   // 12 : (l*2+h)*4 + k

// ---------------- scratch (static device arrays; no allocation) ----------------
__device__ float g_xin  [NSRC_F*LDA_F];
__device__ float g_Vf   [NSRC_F*HID];
__device__ float g_psrc_f[NSRC_F];
__device__ float g_pctx_f[NDST_F];
__device__ float g_pqs  [NDST_F*2];
__device__ float g_pqd  [NDST_F*2];
__device__ float g_psrc_b[NDST_F];
__device__ float g_pctx_b[NSRC_F];
__device__ float g_xlat [NDST_F*HID];
__device__ float g_q    [NDST_F*HID];
__device__ float g_gout [NDST_F*HID];
__device__ float g_h    [NDST_F*HID];
__device__ float g_xpc  [NDST_F*K_B];
__device__ float g_Vb   [NDST_F*OUTC];
__device__ float g_wred [512];

// CSR (per-batch graphs; shared across the 2 batches)
// edat slot = {src, attr0, attr1, attr2} (float bits in y/z/w) in dst-sorted order
__device__ int  g_ptr_e2h[HMESH+1];  __device__ int g_pos_e2h[HMESH];  __device__ int4 g_edat_e2h[E_E2H];
__device__ int  g_ptr_h2h[HMESH+1];  __device__ int g_pos_h2h[HMESH];  __device__ int4 g_edat_h2h[E_H2H];
__device__ int  g_ptr_h2e[ERA+1];    __device__ int g_pos_h2e[ERA];    __device__ int4 g_edat_h2e[E_H2E];

#define N_CSR_ZERO (2*HMESH + ERA)
#define E_CSR_ALL  (E_E2H + E_H2H + E_H2E)
#define ZBLK ((N_CSR_ZERO + 255) / 256)

// ---------------- merged init: csr_zero + weight precompute ----------------
__global__ void k_init(const float* fmWsrc, const float* fmWctx, const float* fmWedge,
                       const float* fmAtt,
                       const float* bmWsrc, const float* bmWctx, const float* bmWedge,
                       const float* bmAtt,
                       const float* gatWe, const float* gatAe) {
    if (blockIdx.x < ZBLK) {
        int i = blockIdx.x * blockDim.x + threadIdx.x;
        if (i < HMESH)                 g_pos_e2h[i] = 0;
        else if (i < 2*HMESH)          g_pos_h2h[i - HMESH] = 0;
        else if (i < N_CSR_ZERO)       g_pos_h2e[i - 2*HMESH] = 0;
        return;
    }
    int t = (blockIdx.x - ZBLK) * 256 + threadIdx.x;  // 0..511
    if (t >= 512) return;
    if (t < K_F) {
        float a = 0.f;
        for (int j = 0; j < HID; j++) a += fmWsrc[t*HID + j] * fmAtt[j];
        g_wred[OFF_WSA_F + t] = a;
    } else if (t < K_F + 5) {
        int r = t - K_F; float a = 0.f;
        for (int j = 0; j < HID; j++) a += fmWctx[r*HID + j] * fmAtt[j];
        g_wred[OFF_WCA_F + r] = a;
    } else if (t < K_F + 8) {
        int r = t - K_F - 5; float a = 0.f;
        for (int j = 0; j < HID; j++) a += fmWedge[r*HID + j] * fmAtt[j];
        g_wred[OFF_WEA_F + r] = a;
    }
    if (t >= 128 && t < 128 + K_B) {
        int r = t - 128; float a = 0.f;
        for (int j = 0; j < OUTC; j++) a += bmWsrc[r*OUTC + j] * bmAtt[j];
        g_wred[OFF_WSA_B + r] = a;
    }
    if (t >= 400 && t < 405) {
        int r = t - 400; float a = 0.f;
        for (int j = 0; j < OUTC; j++) a += bmWctx[r*OUTC + j] * bmAtt[j];
        g_wred[OFF_WCA_B + r] = a;
    }
    if (t >= 405 && t < 408) {
        int r = t - 405; float a = 0.f;
        for (int j = 0; j < OUTC; j++) a += bmWedge[r*OUTC + j] * bmAtt[j];
        g_wred[OFF_WEA_B + r] = a;
    }
    if (t >= 408 && t < 420) {
        int idx = t - 408;
        int l = idx / 6, h = (idx % 6) / 3, k = idx % 3;
        float a = 0.f;
        for (int dd = 0; dd < 128; dd++)
            a += gatWe[((l*3 + k)*2 + h)*128 + dd] * gatAe[(l*2 + h)*128 + dd];
        g_wred[OFF_WER + (l*2 + h)*4 + k] = a;
    }
}

__global__ void k_csr_count(const int* __restrict__ e2h, const int* __restrict__ h2h,
                            const int* __restrict__ h2e) {
    int i = blockIdx.x * blockDim.x + threadIdx.x;
    if (i < E_E2H)                        atomicAdd(&g_pos_e2h[e2h[E_E2H + i]], 1);
    else if (i < E_E2H + E_H2H)           atomicAdd(&g_pos_h2h[h2h[E_H2H + (i - E_E2H)]], 1);
    else if (i < E_CSR_ALL)               atomicAdd(&g_pos_h2e[h2e[E_H2E + (i - E_E2H - E_H2H)]], 1);
}

// one block per graph; carry-loop block scan. pos becomes the running fill cursor.
__global__ void k_csr_scan() {
    __shared__ int sm[32];
    int g = blockIdx.x;
    int* cnt = (g == 0) ? g_pos_e2h : (g == 1) ? g_pos_h2h : g_pos_h2e;
    int* ptr = (g == 0) ? g_ptr_e2h : (g == 1) ? g_ptr_h2h : g_ptr_h2e;
    int n    = (g == 2) ? ERA : HMESH;
    int t = threadIdx.x, lane = t & 31, wid = t >> 5;
    int carry = 0;
    for (int base = 0; base < n; base += 1024) {
        int v = (base + t < n) ? cnt[base + t] : 0;
        int x = v;
#pragma unroll
        for (int o = 1; o < 32; o <<= 1) {
            int y = __shfl_up_sync(0xffffffff, x, o);
            if (lane >= o) x += y;
        }
        if (lane == 31) sm[wid] = x;
        __syncthreads();
        if (wid == 0) {
            int s = sm[lane];
#pragma unroll
            for (int o = 1; o < 32; o <<= 1) {
                int y = __shfl_up_sync(0xffffffff, s, o);
                if (lane >= o) s += y;
            }
            sm[lane] = s;
        }
        __syncthreads();
        int warp_off = (wid > 0) ? sm[wid - 1] : 0;
        int total = sm[31];
        int excl = carry + warp_off + x - v;
        if (base + t < n) { ptr[base + t] = excl; cnt[base + t] = excl; }
        carry += total;
        __syncthreads();
    }
    if (t == 0) ptr[n] = carry;
}

// fill CSR slots with packed {src, a0, a1, a2}; reads of src/attr are coalesced by edge id
__global__ void k_csr_fill(const int* __restrict__ e2h, const int* __restrict__ h2h,
                           const int* __restrict__ h2e,
                           const float* __restrict__ ea_e2h,
                           const float* __restrict__ ea_h2h,
                           const float* __restrict__ ea_h2e) {
    int i = blockIdx.x * blockDim.x + threadIdx.x;
    if (i < E_E2H) {
        int src = e2h[i];
        int idx = atomicAdd(&g_pos_e2h[e2h[E_E2H + i]], 1);
        g_edat_e2h[idx] = make_int4(src,
                                    __float_as_int(ea_e2h[i*3]),
                                    __float_as_int(ea_e2h[i*3+1]),
                                    __float_as_int(ea_e2h[i*3+2]));
    } else if (i < E_E2H + E_H2H) {
        int eo = i - E_E2H;
        int src = h2h[eo];
        int idx = atomicAdd(&g_pos_h2h[h2h[E_H2H + eo]], 1);
        g_edat_h2h[idx] = make_int4(src,
                                    __float_as_int(ea_h2h[eo*3]),
                                    __float_as_int(ea_h2h[eo*3+1]),
                                    __float_as_int(ea_h2h[eo*3+2]));
    } else if (i < E_CSR_ALL) {
        int eo = i - E_E2H - E_H2H;
        int src = h2e[eo];
        int idx = atomicAdd(&g_pos_h2e[h2e[E_H2E + eo]], 1);
        g_edat_h2e[idx] = make_int4(src,
                                    __float_as_int(ea_h2e[eo*3]),
                                    __float_as_int(ea_h2e[eo*3+1]),
                                    __float_as_int(ea_h2e[eo*3+2]));
    }
}

// ---------------- merged forward prep: build_xin+psrc_f (warps) & pctx_f (threads) ----
#define XIN_BLK ((NSRC_F * 32 + 255) / 256)

__global__ void k_prep_f(const float* __restrict__ x, const float* __restrict__ era_ll,
                         const float* __restrict__ fm_ctx, const float* __restrict__ h_ll) {
    if (blockIdx.x < XIN_BLK) {
        int w = (blockIdx.x * blockDim.x + threadIdx.x) >> 5;
        int lane = threadIdx.x & 31;
        if (w >= NSRC_F) return;
        int node = w % ERA;
        float acc = 0.f;
#pragma unroll
        for (int it = 0; it < 4; it++) {
            int c = lane + it * 32;
            float v = 0.f;
            if (c < 98)       v = x[(size_t)w * 98 + c];
            else if (c < 102) v = era_ll[node * 4 + (c - 98)];
            if (c < LDA_F) g_xin[w * LDA_F + c] = v;
            if (c < 102)   acc += v * g_wred[OFF_WSA_F + c];
        }
        for (int o = 16; o > 0; o >>= 1) acc += __shfl_down_sync(0xffffffff, acc, o);
        if (lane == 0) g_psrc_f[w] = acc;
        return;
    }
    int d = (blockIdx.x - XIN_BLK) * 256 + threadIdx.x;
    if (d >= NDST_F) return;
    int node = d % HMESH;
    float a = fm_ctx[node] * g_wred[OFF_WCA_F];
#pragma unroll
    for (int k = 0; k < 4; k++) a += h_ll[node * 4 + k] * g_wred[OFF_WCA_F + 1 + k];
    g_pctx_f[d] = a;
}

// ---------------- tf32 tensor-core GEMM: C[M,N] = A[M,K(lda)] * B[K,N] ----------------
// vectorized (float4) global loads; all strides 16B-aligned by construction.
#define SMS 136

__device__ __forceinline__ unsigned cvt_tf32(float f) {
    unsigned r;
    asm("cvt.rna.tf32.f32 %0, %1;" : "=r"(r) : "f"(f));
    return r;
}

__device__ __forceinline__ void load_a8(const float* __restrict__ A, size_t base,
                                        int k, int K, float* ra) {
    if (k + 7 < K) {
        float4 v0 = *(const float4*)&A[base + k];
        float4 v1 = *(const float4*)&A[base + k + 4];
        ra[0]=v0.x; ra[1]=v0.y; ra[2]=v0.z; ra[3]=v0.w;
        ra[4]=v1.x; ra[5]=v1.y; ra[6]=v1.z; ra[7]=v1.w;
    } else {
#pragma unroll
        for (int i = 0; i < 8; i++) ra[i] = (k + i < K) ? A[base + k + i] : 0.f;
    }
}

__device__ __forceinline__ void load_b8(const float* __restrict__ B, int kg, int K,
                                        int N, int gn0, float* rb) {
    if (kg < K) {
        if (gn0 + 7 < N) {
            float4 v0 = *(const float4*)&B[(size_t)kg * N + gn0];
            float4 v1 = *(const float4*)&B[(size_t)kg * N + gn0 + 4];
            rb[0]=v0.x; rb[1]=v0.y; rb[2]=v0.z; rb[3]=v0.w;
            rb[4]=v1.x; rb[5]=v1.y; rb[6]=v1.z; rb[7]=v1.w;
        } else {
#pragma unroll
            for (int i = 0; i < 8; i++)
                rb[i] = (gn0 + i < N) ? B[(size_t)kg * N + gn0 + i] : 0.f;
        }
    } else {
#pragma unroll
        for (int i = 0; i < 8; i++) rb[i] = 0.f;
    }
}

__global__ __launch_bounds__(256, 2) void k_gemm(const float* __restrict__ A, int lda,
                                                 const float* __restrict__ B,
                                                 float* __restrict__ C,
                                                 int M, int N, int K) {
    __shared__ unsigned As[2][16 * SMS];
    __shared__ unsigned Bs[2][16 * SMS];
    int tid = threadIdx.x;
    int wid = tid >> 5, lane = tid & 31;
    int m0 = blockIdx.x * 128, n0 = blockIdx.y * 128;
    int warpM = wid >> 2, warpN = wid & 3;
    int gid = lane >> 2, tig = lane & 3;

    int am = tid >> 1, ak = (tid & 1) * 8;
    int bk = tid >> 4, bn = (tid & 15) * 8;
    int grow = m0 + am;
    size_t abase = (size_t)grow * lda;

    float cacc[4][4][4];
#pragma unroll
    for (int i = 0; i < 4; i++)
#pragma unroll
        for (int j = 0; j < 4; j++)
#pragma unroll
            for (int r = 0; r < 4; r++) cacc[i][j][r] = 0.f;

    float ra[8], rb[8];

    if (grow < M) load_a8(A, abase, ak, K, ra);
    else {
#pragma unroll
        for (int i = 0; i < 8; i++) ra[i] = 0.f;
    }
    load_b8(B, bk, K, N, n0 + bn, rb);
#pragma unroll
    for (int i = 0; i < 8; i++) As[0][(ak + i) * SMS + am] = cvt_tf32(ra[i]);
#pragma unroll
    for (int i = 0; i < 8; i++) Bs[0][bk * SMS + bn + i] = cvt_tf32(rb[i]);
    __syncthreads();

    int p = 0;
    for (int k0 = 16; k0 < K + 16; k0 += 16) {
        bool has_next = (k0 < K);
        if (has_next) {
            if (grow < M) load_a8(A, abase, k0 + ak, K, ra);
            else {
#pragma unroll
                for (int i = 0; i < 8; i++) ra[i] = 0.f;
            }
            load_b8(B, k0 + bk, K, N, n0 + bn, rb);
        }
#pragma unroll
        for (int ks = 0; ks < 2; ks++) {
            unsigned af[4][4], bf[4][2];
#pragma unroll
            for (int mt = 0; mt < 4; mt++) {
                int mb = warpM * 64 + mt * 16;
                int base = (ks * 8 + tig) * SMS + mb + gid;
                af[mt][0] = As[p][base];
                af[mt][1] = As[p][base + 8];
                af[mt][2] = As[p][base + 4 * SMS];
                af[mt][3] = As[p][base + 4 * SMS + 8];
            }
#pragma unroll
            for (int nt = 0; nt < 4; nt++) {
                int nb = warpN * 32 + nt * 8;
                int base = (ks * 8 + tig) * SMS + nb + gid;
                bf[nt][0] = Bs[p][base];
                bf[nt][1] = Bs[p][base + 4 * SMS];
            }
#pragma unroll
            for (int mt = 0; mt < 4; mt++)
#pragma unroll
                for (int nt = 0; nt < 4; nt++) {
                    asm volatile(
                        "mma.sync.aligned.m16n8k8.row.col.f32.tf32.tf32.f32 "
                        "{%0,%1,%2,%3}, {%4,%5,%6,%7}, {%8,%9}, {%0,%1,%2,%3};"
                        : "+f"(cacc[mt][nt][0]), "+f"(cacc[mt][nt][1]),
                          "+f"(cacc[mt][nt][2]), "+f"(cacc[mt][nt][3])
                        : "r"(af[mt][0]), "r"(af[mt][1]), "r"(af[mt][2]), "r"(af[mt][3]),
                          "r"(bf[nt][0]), "r"(bf[nt][1]));
                }
        }
        if (has_next) {
            int q = p ^ 1;
#pragma unroll
            for (int i = 0; i < 8; i++) As[q][(ak + i) * SMS + am] = cvt_tf32(ra[i]);
#pragma unroll
            for (int i = 0; i < 8; i++) Bs[q][bk * SMS + bn + i] = cvt_tf32(rb[i]);
            __syncthreads();
            p = q;
        }
    }

#pragma unroll
    for (int mt = 0; mt < 4; mt++) {
#pragma unroll
        for (int nt = 0; nt < 4; nt++) {
            int row0 = m0 + warpM * 64 + mt * 16 + gid;
            int col  = n0 + warpN * 32 + nt * 8 + 2 * tig;
            if (col + 1 < N) {
                if (row0 < M)
                    *(float2*)&C[(size_t)row0 * N + col] =
                        make_float2(cacc[mt][nt][0], cacc[mt][nt][1]);
                if (row0 + 8 < M)
                    *(float2*)&C[(size_t)(row0 + 8) * N + col] =
                        make_float2(cacc[mt][nt][2], cacc[mt][nt][3]);
            }
        }
    }
}

// ---------------- fused gathers: packed-metadata CSR, warp per dst -------------------
__device__ __forceinline__ void fwd_edge_meta(int p0, int idx, int cnt, int b, float pc,
                                              int &s, float &ev) {
    s = 0; ev = 0.f;
    if (idx < cnt) {
        int4 m = g_edat_e2h[p0 + idx];    // one coalesced 16B load
        s = m.x + b * ERA;
        float pe = __int_as_float(m.y) * g_wred[OFF_WEA_F]
                 + __int_as_float(m.z) * g_wred[OFF_WEA_F+1]
                 + __int_as_float(m.w) * g_wred[OFF_WEA_F+2];
        float l = g_psrc_f[s] + pc + pe;
        l = l > 0.f ? l : 0.2f * l;
        ev = expf(l);
    }
}

// warp per dst; both column halves accumulated (alpha is head-independent here)
__global__ void k_fwd_gather() {
    int d = (blockIdx.x * blockDim.x + threadIdx.x) >> 5;
    int lane = threadIdx.x & 31;
    if (d >= NDST_F) return;
    int node = d % HMESH, b = d / HMESH;
    int p0 = g_ptr_e2h[node];
    int cnt = g_ptr_e2h[node + 1] - p0;
    float pc = g_pctx_f[d];

    int s0; float e0;
    fwd_edge_meta(p0, lane, cnt, b, pc, s0, e0);
    float ssum = e0;
    for (int base = 32; base < cnt; base += 32) {
        int st; float et;
        fwd_edge_meta(p0, base + lane, cnt, b, pc, st, et);
        ssum += et;
    }
#pragma unroll
    for (int o = 16; o > 0; o >>= 1) ssum += __shfl_xor_sync(0xffffffffu, ssum, o);
    float inv = 1.f / (ssum + 1e-9f);

    float4 acc0 = make_float4(0.f, 0.f, 0.f, 0.f);
    float4 acc1 = make_float4(0.f, 0.f, 0.f, 0.f);
    int c0 = lane * 4, c1 = 128 + lane * 4;
    int n1 = cnt < 32 ? cnt : 32;
    for (int j = 0; j < n1; j++) {
        int s = __shfl_sync(0xffffffffu, s0, j);
        float alpha = __shfl_sync(0xffffffffu, e0, j) * inv;
        float4 v0 = *(const float4*)&g_Vf[s * HID + c0];
        float4 v1 = *(const float4*)&g_Vf[s * HID + c1];
        acc0.x += alpha * v0.x; acc0.y += alpha * v0.y;
        acc0.z += alpha * v0.z; acc0.w += alpha * v0.w;
        acc1.x += alpha * v1.x; acc1.y += alpha * v1.y;
        acc1.z += alpha * v1.z; acc1.w += alpha * v1.w;
    }
    for (int base = 32; base < cnt; base += 32) {
        int st; float et;
        fwd_edge_meta(p0, base + lane, cnt, b, pc, st, et);
        int nn = (cnt - base) < 32 ? (cnt - base) : 32;
        for (int j = 0; j < nn; j++) {
            int s = __shfl_sync(0xffffffffu, st, j);
            float alpha = __shfl_sync(0xffffffffu, et, j) * inv;
            float4 v0 = *(const float4*)&g_Vf[s * HID + c0];
            float4 v1 = *(const float4*)&g_Vf[s * HID + c1];
            acc0.x += alpha * v0.x; acc0.y += alpha * v0.y;
            acc0.z += alpha * v0.z; acc0.w += alpha * v0.w;
            acc1.x += alpha * v1.x; acc1.y += alpha * v1.y;
            acc1.z += alpha * v1.z; acc1.w += alpha * v1.w;
        }
    }
    *(float4*)&g_xlat[d * HID + c0] = acc0;
    *(float4*)&g_xlat[d * HID + c1] = acc1;
}

__device__ __forceinline__ void gat_edge_meta2(int p0, int idx, int cnt, int b,
                                               float pqd0, float pqd1, int l,
                                               int &s, float &ev0, float &ev1) {
    s = 0; ev0 = 0.f; ev1 = 0.f;
    if (idx < cnt) {
        int4 m = g_edat_h2h[p0 + idx];    // one coalesced 16B load
        s = m.x + b * HMESH;
        float a0 = __int_as_float(m.y), a1 = __int_as_float(m.z), a2 = __int_as_float(m.w);
        const float* w0 = &g_wred[OFF_WER + (l*2)*4];
        const float* w1 = &g_wred[OFF_WER + (l*2 + 1)*4];
        float lg0 = g_pqs[s*2]     + pqd0 + a0*w0[0] + a1*w0[1] + a2*w0[2];
        float lg1 = g_pqs[s*2 + 1] + pqd1 + a0*w1[0] + a1*w1[1] + a2*w1[2];
        lg0 = lg0 > 0.f ? lg0 : 0.2f * lg0;
        lg1 = lg1 > 0.f ? lg1 : 0.2f * lg1;
        ev0 = expf(lg0);
        ev1 = expf(lg1);
    }
}

// warp per dst; both heads accumulated in one pass (metadata loaded once)
__global__ void k_gat_gather(float* __restrict__ outbuf, int l, int apply_gelu) {
    int d = (blockIdx.x * blockDim.x + threadIdx.x) >> 5;
    int lane = threadIdx.x & 31;
    if (d >= NDST_F) return;
    int node = d % HMESH, b = d / HMESH;
    int p0 = g_ptr_h2h[node];
    int cnt = g_ptr_h2h[node + 1] - p0;
    float pqd0 = g_pqd[d*2], pqd1 = g_pqd[d*2 + 1];

    int s0; float e00, e01;
    gat_edge_meta2(p0, lane, cnt, b, pqd0, pqd1, l, s0, e00, e01);
    float ssum0 = e00, ssum1 = e01;
    for (int base = 32; base < cnt; base += 32) {
        int st; float et0, et1;
        gat_edge_meta2(p0, base + lane, cnt, b, pqd0, pqd1, l, st, et0, et1);
        ssum0 += et0; ssum1 += et1;
    }
#pragma unroll
    for (int o = 16; o > 0; o >>= 1) {
        ssum0 += __shfl_xor_sync(0xffffffffu, ssum0, o);
        ssum1 += __shfl_xor_sync(0xffffffffu, ssum1, o);
    }
    float inv0 = 1.f / (ssum0 + 1e-9f);
    float inv1 = 1.f / (ssum1 + 1e-9f);

    float4 acc0 = make_float4(0.f, 0.f, 0.f, 0.f);
    float4 acc1 = make_float4(0.f, 0.f, 0.f, 0.f);
    int c0 = lane * 4, c1 = 128 + lane * 4;
    int n1 = cnt < 32 ? cnt : 32;
    for (int j = 0; j < n1; j++) {
        int s = __shfl_sync(0xffffffffu, s0, j);
        float al0 = __shfl_sync(0xffffffffu, e00, j) * inv0;
        float al1 = __shfl_sync(0xffffffffu, e01, j) * inv1;
        float4 v0 = *(const float4*)&g_q[s * HID + c0];
        float4 v1 = *(const float4*)&g_q[s * HID + c1];
        acc0.x += al0 * v0.x; acc0.y += al0 * v0.y;
        acc0.z += al0 * v0.z; acc0.w += al0 * v0.w;
        acc1.x += al1 * v1.x; acc1.y += al1 * v1.y;
        acc1.z += al1 * v1.z; acc1.w += al1 * v1.w;
    }
    for (int base = 32; base < cnt; base += 32) {
        int st; float et0, et1;
        gat_edge_meta2(p0, base + lane, cnt, b, pqd0, pqd1, l, st, et0, et1);
        int nn = (cnt - base) < 32 ? (cnt - base) : 32;
        for (int j = 0; j < nn; j++) {
            int s = __shfl_sync(0xffffffffu, st, j);
            float al0 = __shfl_sync(0xffffffffu, et0, j) * inv0;
            float al1 = __shfl_sync(0xffffffffu, et1, j) * inv1;
            float4 v0 = *(const float4*)&g_q[s * HID + c0];
            float4 v1 = *(const float4*)&g_q[s * HID + c1];
            acc0.x += al0 * v0.x; acc0.y += al0 * v0.y;
            acc0.z += al0 * v0.z; acc0.w += al0 * v0.w;
            acc1.x += al1 * v1.x; acc1.y += al1 * v1.y;
            acc1.z += al1 * v1.z; acc1.w += al1 * v1.w;
        }
    }
    if (apply_gelu) {
        float* a0 = &acc0.x; float* a1 = &acc1.x;
#pragma unroll
        for (int i = 0; i < 4; i++) {
            float xx = a0[i];
            float t = tanhf(0.7978845608f * (xx + 0.044715f * xx * xx * xx));
            a0[i] = 0.5f * xx * (1.f + t);
            xx = a1[i];
            t = tanhf(0.7978845608f * (xx + 0.044715f * xx * xx * xx));
            a1[i] = 0.5f * xx * (1.f + t);
        }
    }
    *(float4*)&outbuf[d * HID + c0] = acc0;
    *(float4*)&outbuf[d * HID + c1] = acc1;
}

__device__ __forceinline__ void bwd_edge_meta(int p0, int idx, int cnt, int b, float pc,
                                              int &s, float &ev) {
    s = 0; ev = 0.f;
    if (idx < cnt) {
        int4 m = g_edat_h2e[p0 + idx];    // one coalesced 16B load
        s = m.x + b * HMESH;
        float pe = __int_as_float(m.y) * g_wred[OFF_WEA_B]
                 + __int_as_float(m.z) * g_wred[OFF_WEA_B+1]
                 + __int_as_float(m.w) * g_wred[OFF_WEA_B+2];
        float l = g_psrc_b[s] + pc + pe;
        l = l > 0.f ? l : 0.2f * l;
        ev = expf(l);
    }
}

__global__ void k_bwd_gather(const float* __restrict__ x, float* __restrict__ out) {
    int w = (blockIdx.x * blockDim.x + threadIdx.x) >> 5;
    int lane = threadIdx.x & 31;
    if (w >= NSRC_F) return;
    int node = w % ERA, b = w / ERA;
    int p0 = g_ptr_h2e[node];
    int cnt = g_ptr_h2e[node + 1] - p0;
    float pc = g_pctx_b[w];

    int s0; float e0;
    bwd_edge_meta(p0, lane, cnt, b, pc, s0, e0);
    float ssum = e0;
    for (int base = 32; base < cnt; base += 32) {
        int st; float et;
        bwd_edge_meta(p0, base + lane, cnt, b, pc, st, et);
        ssum += et;
    }
#pragma unroll
    for (int o = 16; o > 0; o >>= 1) ssum += __shfl_xor_sync(0xffffffffu, ssum, o);
    float inv = 1.f / (ssum + 1e-9f);

    int c = lane * 4;
    float4 acc = make_float4(0.f, 0.f, 0.f, 0.f);
    int n1 = cnt < 32 ? cnt : 32;
    for (int j = 0; j < n1; j++) {
        int s = __shfl_sync(0xffffffffu, s0, j);
        float alpha = __shfl_sync(0xffffffffu, e0, j) * inv;
        if (lane < 24) {
            float4 v = *(const float4*)&g_Vb[s * OUTC + c];
            acc.x += alpha * v.x; acc.y += alpha * v.y;
            acc.z += alpha * v.z; acc.w += alpha * v.w;
        }
    }
    for (int base = 32; base < cnt; base += 32) {
        int st; float et;
        bwd_edge_meta(p0, base + lane, cnt, b, pc, st, et);
        int nn = (cnt - base) < 32 ? (cnt - base) : 32;
        for (int j = 0; j < nn; j++) {
            int s = __shfl_sync(0xffffffffu, st, j);
            float alpha = __shfl_sync(0xffffffffu, et, j) * inv;
            if (lane < 24) {
                float4 v = *(const float4*)&g_Vb[s * OUTC + c];
                acc.x += alpha * v.x; acc.y += alpha * v.y;
                acc.z += alpha * v.z; acc.w += alpha * v.w;
            }
        }
    }
    if (lane < 24) {
        const float* xr = &x[(size_t)w * 98 + c];
        acc.x += xr[0]; acc.y += xr[1]; acc.z += xr[2]; acc.w += xr[3];
        *(float4*)&out[w * OUTC + c] = acc;
    }
}

// ---------------- GAT per-node scalars ----------------
__global__ void k_gat_pq(const float* __restrict__ asrc, const float* __restrict__ adst) {
    int w = (blockIdx.x * blockDim.x + threadIdx.x) >> 5;
    int lane = threadIdx.x & 31;
    if (w >= NDST_F * 2) return;
    int n = w >> 1, h = w & 1;
    const float* qrow = &g_q[n * HID + h * 128];
    float as_ = 0.f, ad_ = 0.f;
#pragma unroll
    for (int it = 0; it < 4; it++) {
        int dd = lane + it * 32;
        float qv = qrow[dd];
        as_ += qv * asrc[h * 128 + dd];
        ad_ += qv * adst[h * 128 + dd];
    }
    for (int o = 16; o > 0; o >>= 1) {
        as_ += __shfl_down_sync(0xffffffff, as_, o);
        ad_ += __shfl_down_sync(0xffffffff, ad_, o);
    }
    if (lane == 0) { g_pqs[w] = as_; g_pqd[w] = ad_; }
}

// ---------------- merged decoder prep: xpc+psrc_b (warps) & pctx_b (threads) ----------
#define XPC_BLK ((NDST_F * 32 + 255) / 256)

__global__ void k_prep_b(const float* __restrict__ h_ll,
                         const float* __restrict__ bm_ctx, const float* __restrict__ era_ll) {
    if (blockIdx.x < XPC_BLK) {
        int n = (blockIdx.x * blockDim.x + threadIdx.x) >> 5;
        int lane = threadIdx.x & 31;
        if (n >= NDST_F) return;
        int node = n % HMESH;
        float acc = 0.f;
#pragma unroll
        for (int it = 0; it < 9; it++) {
            int c = lane + it * 32;
            if (c < K_B) {
                float v;
                if (c < 256) v = g_gout[n * HID + c] + g_xlat[n * HID + c];
                else         v = h_ll[node * 4 + (c - 256)];
                g_xpc[n * K_B + c] = v;
                acc += v * g_wred[OFF_WSA_B + c];
            }
        }
        for (int o = 16; o > 0; o >>= 1) acc += __shfl_down_sync(0xffffffff, acc, o);
        if (lane == 0) g_psrc_b[n] = acc;
        return;
    }
    int d = (blockIdx.x - XPC_BLK) * 256 + threadIdx.x;
    if (d >= NSRC_F) return;
    int node = d % ERA;
    float a = bm_ctx[node] * g_wred[OFF_WCA_B];
#pragma unroll
    for (int k = 0; k < 4; k++) a += era_ll[node * 4 + k] * g_wred[OFF_WCA_B + 1 + k];
    g_pctx_b[d] = a;
}

// ---------------- host ----------------
static float* sym(const void* s) { void* p = nullptr; cudaGetSymbolAddress(&p, s); return (float*)p; }

extern "C" void kernel_launch(void* const* d_in, const int* in_sizes, int n_in,
                              void* d_out, int out_size) {
    const float* x        = (const float*)d_in[0];
    const int*   e2h      = (const int*)  d_in[1];
    const int*   h2h      = (const int*)  d_in[2];
    const int*   h2e      = (const int*)  d_in[3];
    const float* e2h_attr = (const float*)d_in[4];
    const float* h2h_attr = (const float*)d_in[5];
    const float* h2e_attr = (const float*)d_in[6];
    const float* era_ll   = (const float*)d_in[7];
    const float* h_ll     = (const float*)d_in[8];
    const float* fm_ctx   = (const float*)d_in[9];
    const float* fm_Wsrc  = (const float*)d_in[10];
    const float* fm_Wctx  = (const float*)d_in[11];
    const float* fm_Wedge = (const float*)d_in[12];
    const float* fm_att   = (const float*)d_in[13];
    const float* fm_Wval  = (const float*)d_in[14];
    const float* bm_ctx   = (const float*)d_in[15];
    const float* bm_Wsrc  = (const float*)d_in[16];
    const float* bm_Wctx  = (const float*)d_in[17];
    const float* bm_Wedge = (const float*)d_in[18];
    const float* bm_att   = (const float*)d_in[19];
    const float* bm_Wval  = (const float*)d_in[20];
    const float* gat_W    = (const float*)d_in[21];
    const float* gat_We   = (const float*)d_in[22];
    const float* gat_asrc = (const float*)d_in[23];
    const float* gat_adst = (const float*)d_in[24];
    const float* gat_ae   = (const float*)d_in[25];
    float* out = (float*)d_out;

    float* p_xin  = sym(g_xin);
    float* p_Vf   = sym(g_Vf);
    float* p_xlat = sym(g_xlat);
    float* p_q    = sym(g_q);
    float* p_gout = sym(g_gout);
    float* p_h    = sym(g_h);
    float* p_xpc  = sym(g_xpc);
    float* p_Vb   = sym(g_Vb);

    const int T = 256;
    auto cdiv = [](int a, int b) { return (a + b - 1) / b; };

    // init (csr_zero + weight precompute) then CSR build (packed src+attr metadata)
    k_init<<<ZBLK + 2, T>>>(fm_Wsrc, fm_Wctx, fm_Wedge, fm_att,
                            bm_Wsrc, bm_Wctx, bm_Wedge, bm_att, gat_We, gat_ae);
    k_csr_count<<<cdiv(E_CSR_ALL, T), T>>>(e2h, h2h, h2e);
    k_csr_scan<<<3, 1024>>>();
    k_csr_fill<<<cdiv(E_CSR_ALL, T), T>>>(e2h, h2h, h2e, e2h_attr, h2h_attr, h2e_attr);

    k_prep_f<<<XIN_BLK + cdiv(NDST_F, T), T>>>(x, era_ll, fm_ctx, h_ll);

    // Vf = x_in @ fm_Wval   (tf32 tensor cores)
    k_gemm<<<dim3(cdiv(NSRC_F, 128), 2), 256>>>(p_xin, LDA_F, fm_Wval, p_Vf, NSRC_F, HID, K_F);

    // fused logits+softmax+gather (warp per dst, both halves, packed metadata)
    k_fwd_gather<<<cdiv(NDST_F * 32, T), T>>>();

    // GAT layers
    for (int l = 0; l < 2; l++) {
        const float* hin = (l == 0) ? p_xlat : p_h;
        k_gemm<<<dim3(cdiv(NDST_F, 128), 2), 256>>>(hin, HID, gat_W + l * HID * HID, p_q,
                                                    NDST_F, HID, HID);
        k_gat_pq<<<cdiv(NDST_F * 2 * 32, T), T>>>(gat_asrc + l * 256, gat_adst + l * 256);
        k_gat_gather<<<cdiv(NDST_F * 32, T), T>>>((l == 0) ? p_h : p_gout, l,
                                                  (l == 0) ? 1 : 0);
    }

    // decoder
    k_prep_b<<<XPC_BLK + cdiv(NSRC_F, T), T>>>(h_ll, bm_ctx, era_ll);
    k_gemm<<<dim3(cdiv(NDST_F, 128), 1), 256>>>(p_xpc, K_B, bm_Wval, p_Vb, NDST_F, OUTC, K_B);

    k_bwd_gather<<<cdiv(NSRC_F * 32, T), T>>>(x, out);
}

// round 16
// speedup vs baseline: 1.4046x; 1.0638x over previous
#include <cuda_runtime.h>
#include <cuda_bf16.h>
#include <math.h>

#define BSZ    2
#define ERA    35718
#define HMESH  10242
#define NSRC_F (BSZ*ERA)      // 71436
#define NDST_F (BSZ*HMESH)    // 20484
#define E_E2H  107154
#define E_H2H  61440
#define E_H2E  107154
#define HID    256
#define K_F    102
#define LDA_F  104
#define K_B    260
#define OUTC   96

// offsets into g_wred (precomputed attention-reduced weight vectors)
#define OFF_WSA_F 0     // 102
#define OFF_WCA_F 104   // 5
#define OFF_WEA_F 112   // 3
#define OFF_WSA_B 128   // 260
#define OFF_WCA_B 392   // 5
#define OFF_WEA_B 400   // 3
#define OFF_WER   408   // 12 : (l*2+h)*4 + k

// ---------------- scratch (static device arrays; no allocation) ----------------
__device__ float g_xin  [NSRC_F*LDA_F];
__device__ float g_Vf   [NSRC_F*HID];
__device__ float g_psrc_f[NSRC_F];
__device__ float g_pctx_f[NDST_F];
__device__ float g_pqs  [NDST_F*2];
__device__ float g_pqd  [NDST_F*2];
__device__ float g_psrc_b[NDST_F];
__device__ float g_pctx_b[NSRC_F];
__device__ float g_xlat [NDST_F*HID];
__device__ float g_q    [NDST_F*HID];
__device__ float g_gout [NDST_F*HID];
__device__ float g_h    [NDST_F*HID];
__device__ float g_xpc  [NDST_F*K_B];
__device__ float g_Vb   [NDST_F*OUTC];
__device__ float g_wred [512];

// CSR (per-batch graphs; shared across the 2 batches)
// edat slot = {src, attr0, attr1, attr2} (float bits in y/z/w) in dst-sorted order
__device__ int  g_ptr_e2h[HMESH+1];  __device__ int g_pos_e2h[HMESH];  __device__ int4 g_edat_e2h[E_E2H];
__device__ int  g_ptr_h2h[HMESH+1];  __device__ int g_pos_h2h[HMESH];  __device__ int4 g_edat_h2h[E_H2H];
__device__ int  g_ptr_h2e[ERA+1];    __device__ int g_pos_h2e[ERA];    __device__ int4 g_edat_h2e[E_H2E];

#define N_CSR_ZERO (2*HMESH + ERA)
#define E_CSR_ALL  (E_E2H + E_H2H + E_H2E)
#define ZBLK ((N_CSR_ZERO + 255) / 256)

// ---------------- merged init: csr_zero + weight precompute ----------------
__global__ void k_init(const float* fmWsrc, const float* fmWctx, const float* fmWedge,
                       const float* fmAtt,
                       const float* bmWsrc, const float* bmWctx, const float* bmWedge,
                       const float* bmAtt,
                       const float* gatWe, const float* gatAe) {
    if (blockIdx.x < ZBLK) {
        int i = blockIdx.x * blockDim.x + threadIdx.x;
        if (i < HMESH)                 g_pos_e2h[i] = 0;
        else if (i < 2*HMESH)          g_pos_h2h[i - HMESH] = 0;
        else if (i < N_CSR_ZERO)       g_pos_h2e[i - 2*HMESH] = 0;
        return;
    }
    int t = (blockIdx.x - ZBLK) * 256 + threadIdx.x;  // 0..511
    if (t >= 512) return;
    if (t < K_F) {
        float a = 0.f;
        for (int j = 0; j < HID; j++) a += fmWsrc[t*HID + j] * fmAtt[j];
        g_wred[OFF_WSA_F + t] = a;
    } else if (t < K_F + 5) {
        int r = t - K_F; float a = 0.f;
        for (int j = 0; j < HID; j++) a += fmWctx[r*HID + j] * fmAtt[j];
        g_wred[OFF_WCA_F + r] = a;
    } else if (t < K_F + 8) {
        int r = t - K_F - 5; float a = 0.f;
        for (int j = 0; j < HID; j++) a += fmWedge[r*HID + j] * fmAtt[j];
        g_wred[OFF_WEA_F + r] = a;
    }
    if (t >= 128 && t < 128 + K_B) {
        int r = t - 128; float a = 0.f;
        for (int j = 0; j < OUTC; j++) a += bmWsrc[r*OUTC + j] * bmAtt[j];
        g_wred[OFF_WSA_B + r] = a;
    }
    if (t >= 400 && t < 405) {
        int r = t - 400; float a = 0.f;
        for (int j = 0; j < OUTC; j++) a += bmWctx[r*OUTC + j] * bmAtt[j];
        g_wred[OFF_WCA_B + r] = a;
    }
    if (t >= 405 && t < 408) {
        int r = t - 405; float a = 0.f;
        for (int j = 0; j < OUTC; j++) a += bmWedge[r*OUTC + j] * bmAtt[j];
        g_wred[OFF_WEA_B + r] = a;
    }
    if (t >= 408 && t < 420) {
        int idx = t - 408;
        int l = idx / 6, h = (idx % 6) / 3, k = idx % 3;
        float a = 0.f;
        for (int dd = 0; dd < 128; dd++)
            a += gatWe[((l*3 + k)*2 + h)*128 + dd] * gatAe[(l*2 + h)*128 + dd];
        g_wred[OFF_WER + (l*2 + h)*4 + k] = a;
    }
}

__global__ void k_csr_count(const int* __restrict__ e2h, const int* __restrict__ h2h,
                            const int* __restrict__ h2e) {
    int i = blockIdx.x * blockDim.x + threadIdx.x;
    if (i < E_E2H)                        atomicAdd(&g_pos_e2h[e2h[E_E2H + i]], 1);
    else if (i < E_E2H + E_H2H)           atomicAdd(&g_pos_h2h[h2h[E_H2H + (i - E_E2H)]], 1);
    else if (i < E_CSR_ALL)               atomicAdd(&g_pos_h2e[h2e[E_H2E + (i - E_E2H - E_H2H)]], 1);
}

// one block per graph; carry-loop block scan. pos becomes the running fill cursor.
__global__ void k_csr_scan() {
    __shared__ int sm[32];
    int g = blockIdx.x;
    int* cnt = (g == 0) ? g_pos_e2h : (g == 1) ? g_pos_h2h : g_pos_h2e;
    int* ptr = (g == 0) ? g_ptr_e2h : (g == 1) ? g_ptr_h2h : g_ptr_h2e;
    int n    = (g == 2) ? ERA : HMESH;
    int t = threadIdx.x, lane = t & 31, wid = t >> 5;
    int carry = 0;
    for (int base = 0; base < n; base += 1024) {
        int v = (base + t < n) ? cnt[base + t] : 0;
        int x = v;
#pragma unroll
        for (int o = 1; o < 32; o <<= 1) {
            int y = __shfl_up_sync(0xffffffff, x, o);
            if (lane >= o) x += y;
        }
        if (lane == 31) sm[wid] = x;
        __syncthreads();
        if (wid == 0) {
            int s = sm[lane];
#pragma unroll
            for (int o = 1; o < 32; o <<= 1) {
                int y = __shfl_up_sync(0xffffffff, s, o);
                if (lane >= o) s += y;
            }
            sm[lane] = s;
        }
        __syncthreads();
        int warp_off = (wid > 0) ? sm[wid - 1] : 0;
        int total = sm[31];
        int excl = carry + warp_off + x - v;
        if (base + t < n) { ptr[base + t] = excl; cnt[base + t] = excl; }
        carry += total;
        __syncthreads();
    }
    if (t == 0) ptr[n] = carry;
}

// fill CSR slots with packed {src, a0, a1, a2}; reads of src/attr are coalesced by edge id
__global__ void k_csr_fill(const int* __restrict__ e2h, const int* __restrict__ h2h,
                           const int* __restrict__ h2e,
                           const float* __restrict__ ea_e2h,
                           const float* __restrict__ ea_h2h,
                           const float* __restrict__ ea_h2e) {
    int i = blockIdx.x * blockDim.x + threadIdx.x;
    if (i < E_E2H) {
        int src = e2h[i];
        int idx = atomicAdd(&g_pos_e2h[e2h[E_E2H + i]], 1);
        g_edat_e2h[idx] = make_int4(src,
                                    __float_as_int(ea_e2h[i*3]),
                                    __float_as_int(ea_e2h[i*3+1]),
                                    __float_as_int(ea_e2h[i*3+2]));
    } else if (i < E_E2H + E_H2H) {
        int eo = i - E_E2H;
        int src = h2h[eo];
        int idx = atomicAdd(&g_pos_h2h[h2h[E_H2H + eo]], 1);
        g_edat_h2h[idx] = make_int4(src,
                                    __float_as_int(ea_h2h[eo*3]),
                                    __float_as_int(ea_h2h[eo*3+1]),
                                    __float_as_int(ea_h2h[eo*3+2]));
    } else if (i < E_CSR_ALL) {
        int eo = i - E_E2H - E_H2H;
        int src = h2e[eo];
        int idx = atomicAdd(&g_pos_h2e[h2e[E_H2E + eo]], 1);
        g_edat_h2e[idx] = make_int4(src,
                                    __float_as_int(ea_h2e[eo*3]),
                                    __float_as_int(ea_h2e[eo*3+1]),
                                    __float_as_int(ea_h2e[eo*3+2]));
    }
}

// ---------------- merged forward prep: build_xin+psrc_f (warps) & pctx_f (threads) ----
#define XIN_BLK ((NSRC_F * 32 + 255) / 256)

__global__ void k_prep_f(const float* __restrict__ x, const float* __restrict__ era_ll,
                         const float* __restrict__ fm_ctx, const float* __restrict__ h_ll) {
    if (blockIdx.x < XIN_BLK) {
        int w = (blockIdx.x * blockDim.x + threadIdx.x) >> 5;
        int lane = threadIdx.x & 31;
        if (w >= NSRC_F) return;
        int node = w % ERA;
        float acc = 0.f;
#pragma unroll
        for (int it = 0; it < 4; it++) {
            int c = lane + it * 32;
            float v = 0.f;
            if (c < 98)       v = x[(size_t)w * 98 + c];
            else if (c < 102) v = era_ll[node * 4 + (c - 98)];
            if (c < LDA_F) g_xin[w * LDA_F + c] = v;
            if (c < 102)   acc += v * g_wred[OFF_WSA_F + c];
        }
        for (int o = 16; o > 0; o >>= 1) acc += __shfl_down_sync(0xffffffff, acc, o);
        if (lane == 0) g_psrc_f[w] = acc;
        return;
    }
    int d = (blockIdx.x - XIN_BLK) * 256 + threadIdx.x;
    if (d >= NDST_F) return;
    int node = d % HMESH;
    float a = fm_ctx[node] * g_wred[OFF_WCA_F];
#pragma unroll
    for (int k = 0; k < 4; k++) a += h_ll[node * 4 + k] * g_wred[OFF_WCA_F + 1 + k];
    g_pctx_f[d] = a;
}

// ---------------- tf32 tensor-core GEMM with cp.async staging ------------------------
// A staged untransposed [m][A_ST=20] (fragment reads land on distinct banks);
// B staged [k][B_ST=136] as before. Per-16B-chunk src_size handles K/N tails via
// hardware zero-fill. tf32 operands are fed as raw fp32 bits (HW truncates mantissa).
#define A_ST 20
#define B_ST 136

__device__ __forceinline__ void cp_async16(unsigned sa, const void* g, int bytes) {
    asm volatile("cp.async.cg.shared.global [%0], [%1], 16, %2;\n"
                 :: "r"(sa), "l"(g), "r"(bytes));
}
__device__ __forceinline__ void cp_commit() {
    asm volatile("cp.async.commit_group;\n" ::);
}
template <int N>
__device__ __forceinline__ void cp_wait() {
    asm volatile("cp.async.wait_group %0;\n" :: "n"(N));
}

__global__ __launch_bounds__(256, 2) void k_gemm(const float* __restrict__ A, int lda,
                                                 const float* __restrict__ B,
                                                 float* __restrict__ C,
                                                 int M, int N, int K) {
    __shared__ float Asm[2][128 * A_ST];
    __shared__ float Bsm[2][16 * B_ST];
    int tid = threadIdx.x;
    int wid = tid >> 5, lane = tid & 31;
    int m0 = blockIdx.x * 128, n0 = blockIdx.y * 128;
    int warpM = wid >> 2, warpN = wid & 3;
    int gid = lane >> 2, tig = lane & 3;

    float cacc[4][4][4];
#pragma unroll
    for (int i = 0; i < 4; i++)
#pragma unroll
        for (int j = 0; j < 4; j++)
#pragma unroll
            for (int r = 0; r < 4; r++) cacc[i][j][r] = 0.f;

    // chunk ids owned by this thread: 2 for A, 2 for B
    int ca0 = tid * 2, ca1 = tid * 2 + 1;

    auto issue = [&](int buf, int k0) {
#pragma unroll
        for (int i = 0; i < 2; i++) {
            int c = (i == 0) ? ca0 : ca1;
            int row = c >> 2, ko = (c & 3) * 4;
            int grow = m0 + row;
            int kstart = k0 + ko;
            int bytes = 0;
            const float* src = A;
            if (grow < M && kstart < K) {
                bytes = (K - kstart) * 4;
                if (bytes > 16) bytes = 16;
                src = A + (size_t)grow * lda + kstart;
            }
            unsigned sa = (unsigned)__cvta_generic_to_shared(&Asm[buf][row * A_ST + ko]);
            cp_async16(sa, src, bytes);
        }
#pragma unroll
        for (int i = 0; i < 2; i++) {
            int c = (i == 0) ? ca0 : ca1;
            int kr = c >> 5, no = (c & 31) * 4;
            int kg = k0 + kr, gn = n0 + no;
            int bytes = 0;
            const float* src = B;
            if (kg < K && gn < N) {
                bytes = (N - gn) * 4;
                if (bytes > 16) bytes = 16;
                src = B + (size_t)kg * N + gn;
            }
            unsigned sa = (unsigned)__cvta_generic_to_shared(&Bsm[buf][kr * B_ST + no]);
            cp_async16(sa, src, bytes);
        }
        cp_commit();
    };

    int ntile = (K + 15) >> 4;
    issue(0, 0);
    if (ntile > 1) issue(1, 16);

    int p = 0;
    for (int t = 0; t < ntile; t++) {
        if (t + 1 < ntile) cp_wait<1>(); else cp_wait<0>();
        __syncthreads();
#pragma unroll
        for (int ks = 0; ks < 2; ks++) {
            unsigned af[4][4], bf[4][2];
#pragma unroll
            for (int mt = 0; mt < 4; mt++) {
                int mb = warpM * 64 + mt * 16;
                int r0 = (mb + gid) * A_ST + ks * 8 + tig;
                int r1 = (mb + gid + 8) * A_ST + ks * 8 + tig;
                af[mt][0] = __float_as_uint(Asm[p][r0]);
                af[mt][1] = __float_as_uint(Asm[p][r1]);
                af[mt][2] = __float_as_uint(Asm[p][r0 + 4]);
                af[mt][3] = __float_as_uint(Asm[p][r1 + 4]);
            }
#pragma unroll
            for (int nt = 0; nt < 4; nt++) {
                int nb = warpN * 32 + nt * 8;
                int base = (ks * 8 + tig) * B_ST + nb + gid;
                bf[nt][0] = __float_as_uint(Bsm[p][base]);
                bf[nt][1] = __float_as_uint(Bsm[p][base + 4 * B_ST]);
            }
#pragma unroll
            for (int mt = 0; mt < 4; mt++)
#pragma unroll
                for (int nt = 0; nt < 4; nt++) {
                    asm volatile(
                        "mma.sync.aligned.m16n8k8.row.col.f32.tf32.tf32.f32 "
                        "{%0,%1,%2,%3}, {%4,%5,%6,%7}, {%8,%9}, {%0,%1,%2,%3};"
                        : "+f"(cacc[mt][nt][0]), "+f"(cacc[mt][nt][1]),
                          "+f"(cacc[mt][nt][2]), "+f"(cacc[mt][nt][3])
                        : "r"(af[mt][0]), "r"(af[mt][1]), "r"(af[mt][2]), "r"(af[mt][3]),
                          "r"(bf[nt][0]), "r"(bf[nt][1]));
                }
        }
        __syncthreads();
        if (t + 2 < ntile) issue(p, (t + 2) * 16);
        p ^= 1;
    }

#pragma unroll
    for (int mt = 0; mt < 4; mt++) {
#pragma unroll
        for (int nt = 0; nt < 4; nt++) {
            int row0 = m0 + warpM * 64 + mt * 16 + gid;
            int col  = n0 + warpN * 32 + nt * 8 + 2 * tig;
            if (col + 1 < N) {
                if (row0 < M)
                    *(float2*)&C[(size_t)row0 * N + col] =
                        make_float2(cacc[mt][nt][0], cacc[mt][nt][1]);
                if (row0 + 8 < M)
                    *(float2*)&C[(size_t)(row0 + 8) * N + col] =
                        make_float2(cacc[mt][nt][2], cacc[mt][nt][3]);
            }
        }
    }
}

// ---------------- fused gathers: packed-metadata CSR, warp per dst -------------------
__device__ __forceinline__ void fwd_edge_meta(int p0, int idx, int cnt, int b, float pc,
                                              int &s, float &ev) {
    s = 0; ev = 0.f;
    if (idx < cnt) {
        int4 m = g_edat_e2h[p0 + idx];    // one coalesced 16B load
        s = m.x + b * ERA;
        float pe = __int_as_float(m.y) * g_wred[OFF_WEA_F]
                 + __int_as_float(m.z) * g_wred[OFF_WEA_F+1]
                 + __int_as_float(m.w) * g_wred[OFF_WEA_F+2];
        float l = g_psrc_f[s] + pc + pe;
        l = l > 0.f ? l : 0.2f * l;
        ev = expf(l);
    }
}

// warp per dst; both column halves accumulated (alpha is head-independent here)
__global__ void k_fwd_gather() {
    int d = (blockIdx.x * blockDim.x + threadIdx.x) >> 5;
    int lane = threadIdx.x & 31;
    if (d >= NDST_F) return;
    int node = d % HMESH, b = d / HMESH;
    int p0 = g_ptr_e2h[node];
    int cnt = g_ptr_e2h[node + 1] - p0;
    float pc = g_pctx_f[d];

    int s0; float e0;
    fwd_edge_meta(p0, lane, cnt, b, pc, s0, e0);
    float ssum = e0;
    for (int base = 32; base < cnt; base += 32) {
        int st; float et;
        fwd_edge_meta(p0, base + lane, cnt, b, pc, st, et);
        ssum += et;
    }
#pragma unroll
    for (int o = 16; o > 0; o >>= 1) ssum += __shfl_xor_sync(0xffffffffu, ssum, o);
    float inv = 1.f / (ssum + 1e-9f);

    float4 acc0 = make_float4(0.f, 0.f, 0.f, 0.f);
    float4 acc1 = make_float4(0.f, 0.f, 0.f, 0.f);
    int c0 = lane * 4, c1 = 128 + lane * 4;
    int n1 = cnt < 32 ? cnt : 32;
    for (int j = 0; j < n1; j++) {
        int s = __shfl_sync(0xffffffffu, s0, j);
        float alpha = __shfl_sync(0xffffffffu, e0, j) * inv;
        float4 v0 = *(const float4*)&g_Vf[s * HID + c0];
        float4 v1 = *(const float4*)&g_Vf[s * HID + c1];
        acc0.x += alpha * v0.x; acc0.y += alpha * v0.y;
        acc0.z += alpha * v0.z; acc0.w += alpha * v0.w;
        acc1.x += alpha * v1.x; acc1.y += alpha * v1.y;
        acc1.z += alpha * v1.z; acc1.w += alpha * v1.w;
    }
    for (int base = 32; base < cnt; base += 32) {
        int st; float et;
        fwd_edge_meta(p0, base + lane, cnt, b, pc, st, et);
        int nn = (cnt - base) < 32 ? (cnt - base) : 32;
        for (int j = 0; j < nn; j++) {
            int s = __shfl_sync(0xffffffffu, st, j);
            float alpha = __shfl_sync(0xffffffffu, et, j) * inv;
            float4 v0 = *(const float4*)&g_Vf[s * HID + c0];
            float4 v1 = *(const float4*)&g_Vf[s * HID + c1];
            acc0.x += alpha * v0.x; acc0.y += alpha * v0.y;
            acc0.z += alpha * v0.z; acc0.w += alpha * v0.w;
            acc1.x += alpha * v1.x; acc1.y += alpha * v1.y;
            acc1.z += alpha * v1.z; acc1.w += alpha * v1.w;
        }
    }
    *(float4*)&g_xlat[d * HID + c0] = acc0;
    *(float4*)&g_xlat[d * HID + c1] = acc1;
}

__device__ __forceinline__ void gat_edge_meta2(int p0, int idx, int cnt, int b,
                                               float pqd0, float pqd1, int l,
                                               int &s, float &ev0, float &ev1) {
    s = 0; ev0 = 0.f; ev1 = 0.f;
    if (idx < cnt) {
        int4 m = g_edat_h2h[p0 + idx];    // one coalesced 16B load
        s = m.x + b * HMESH;
        float a0 = __int_as_float(m.y), a1 = __int_as_float(m.z), a2 = __int_as_float(m.w);
        const float* w0 = &g_wred[OFF_WER + (l*2)*4];
        const float* w1 = &g_wred[OFF_WER + (l*2 + 1)*4];
        float lg0 = g_pqs[s*2]     + pqd0 + a0*w0[0] + a1*w0[1] + a2*w0[2];
        float lg1 = g_pqs[s*2 + 1] + pqd1 + a0*w1[0] + a1*w1[1] + a2*w1[2];
        lg0 = lg0 > 0.f ? lg0 : 0.2f * lg0;
        lg1 = lg1 > 0.f ? lg1 : 0.2f * lg1;
        ev0 = expf(lg0);
        ev1 = expf(lg1);
    }
}

// warp per dst; both heads accumulated in one pass (metadata loaded once)
__global__ void k_gat_gather(float* __restrict__ outbuf, int l, int apply_gelu) {
    int d = (blockIdx.x * blockDim.x + threadIdx.x) >> 5;
    int lane = threadIdx.x & 31;
    if (d >= NDST_F) return;
    int node = d % HMESH, b = d / HMESH;
    int p0 = g_ptr_h2h[node];
    int cnt = g_ptr_h2h[node + 1] - p0;
    float pqd0 = g_pqd[d*2], pqd1 = g_pqd[d*2 + 1];

    int s0; float e00, e01;
    gat_edge_meta2(p0, lane, cnt, b, pqd0, pqd1, l, s0, e00, e01);
    float ssum0 = e00, ssum1 = e01;
    for (int base = 32; base < cnt; base += 32) {
        int st; float et0, et1;
        gat_edge_meta2(p0, base + lane, cnt, b, pqd0, pqd1, l, st, et0, et1);
        ssum0 += et0; ssum1 += et1;
    }
#pragma unroll
    for (int o = 16; o > 0; o >>= 1) {
        ssum0 += __shfl_xor_sync(0xffffffffu, ssum0, o);
        ssum1 += __shfl_xor_sync(0xffffffffu, ssum1, o);
    }
    float inv0 = 1.f / (ssum0 + 1e-9f);
    float inv1 = 1.f / (ssum1 + 1e-9f);

    float4 acc0 = make_float4(0.f, 0.f, 0.f, 0.f);
    float4 acc1 = make_float4(0.f, 0.f, 0.f, 0.f);
    int c0 = lane * 4, c1 = 128 + lane * 4;
    int n1 = cnt < 32 ? cnt : 32;
    for (int j = 0; j < n1; j++) {
        int s = __shfl_sync(0xffffffffu, s0, j);
        float al0 = __shfl_sync(0xffffffffu, e00, j) * inv0;
        float al1 = __shfl_sync(0xffffffffu, e01, j) * inv1;
        float4 v0 = *(const float4*)&g_q[s * HID + c0];
        float4 v1 = *(const float4*)&g_q[s * HID + c1];
        acc0.x += al0 * v0.x; acc0.y += al0 * v0.y;
        acc0.z += al0 * v0.z; acc0.w += al0 * v0.w;
        acc1.x += al1 * v1.x; acc1.y += al1 * v1.y;
        acc1.z += al1 * v1.z; acc1.w += al1 * v1.w;
    }
    for (int base = 32; base < cnt; base += 32) {
        int st; float et0, et1;
        gat_edge_meta2(p0, base + lane, cnt, b, pqd0, pqd1, l, st, et0, et1);
        int nn = (cnt - base) < 32 ? (cnt - base) : 32;
        for (int j = 0; j < nn; j++) {
            int s = __shfl_sync(0xffffffffu, st, j);
            float al0 = __shfl_sync(0xffffffffu, et0, j) * inv0;
            float al1 = __shfl_sync(0xffffffffu, et1, j) * inv1;
            float4 v0 = *(const float4*)&g_q[s * HID + c0];
            float4 v1 = *(const float4*)&g_q[s * HID + c1];
            acc0.x += al0 * v0.x; acc0.y += al0 * v0.y;
            acc0.z += al0 * v0.z; acc0.w += al0 * v0.w;
            acc1.x += al1 * v1.x; acc1.y += al1 * v1.y;
            acc1.z += al1 * v1.z; acc1.w += al1 * v1.w;
        }
    }
    if (apply_gelu) {
        float* a0 = &acc0.x; float* a1 = &acc1.x;
#pragma unroll
        for (int i = 0; i < 4; i++) {
            float xx = a0[i];
            float t = tanhf(0.7978845608f * (xx + 0.044715f * xx * xx * xx));
            a0[i] = 0.5f * xx * (1.f + t);
            xx = a1[i];
            t = tanhf(0.7978845608f * (xx + 0.044715f * xx * xx * xx));
            a1[i] = 0.5f * xx * (1.f + t);
        }
    }
    *(float4*)&outbuf[d * HID + c0] = acc0;
    *(float4*)&outbuf[d * HID + c1] = acc1;
}

__device__ __forceinline__ void bwd_edge_meta(int p0, int idx, int cnt, int b, float pc,
                                              int &s, float &ev) {
    s = 0; ev = 0.f;
    if (idx < cnt) {
        int4 m = g_edat_h2e[p0 + idx];    // one coalesced 16B load
        s = m.x + b * HMESH;
        float pe = __int_as_float(m.y) * g_wred[OFF_WEA_B]
                 + __int_as_float(m.z) * g_wred[OFF_WEA_B+1]
                 + __int_as_float(m.w) * g_wred[OFF_WEA_B+2];
        float l = g_psrc_b[s] + pc + pe;
        l = l > 0.f ? l : 0.2f * l;
        ev = expf(l);
    }
}

__global__ void k_bwd_gather(const float* __restrict__ x, float* __restrict__ out) {
    int w = (blockIdx.x * blockDim.x + threadIdx.x) >> 5;
    int lane = threadIdx.x & 31;
    if (w >= NSRC_F) return;
    int node = w % ERA, b = w / ERA;
    int p0 = g_ptr_h2e[node];
    int cnt = g_ptr_h2e[node + 1] - p0;
    float pc = g_pctx_b[w];

    int s0; float e0;
    bwd_edge_meta(p0, lane, cnt, b, pc, s0, e0);
    float ssum = e0;
    for (int base = 32; base < cnt; base += 32) {
        int st; float et;
        bwd_edge_meta(p0, base + lane, cnt, b, pc, st, et);
        ssum += et;
    }
#pragma unroll
    for (int o = 16; o > 0; o >>= 1) ssum += __shfl_xor_sync(0xffffffffu, ssum, o);
    float inv = 1.f / (ssum + 1e-9f);

    int c = lane * 4;
    float4 acc = make_float4(0.f, 0.f, 0.f, 0.f);
    int n1 = cnt < 32 ? cnt : 32;
    for (int j = 0; j < n1; j++) {
        int s = __shfl_sync(0xffffffffu, s0, j);
        float alpha = __shfl_sync(0xffffffffu, e0, j) * inv;
        if (lane < 24) {
            float4 v = *(const float4*)&g_Vb[s * OUTC + c];
            acc.x += alpha * v.x; acc.y += alpha * v.y;
            acc.z += alpha * v.z; acc.w += alpha * v.w;
        }
    }
    for (int base = 32; base < cnt; base += 32) {
        int st; float et;
        bwd_edge_meta(p0, base + lane, cnt, b, pc, st, et);
        int nn = (cnt - base) < 32 ? (cnt - base) : 32;
        for (int j = 0; j < nn; j++) {
            int s = __shfl_sync(0xffffffffu, st, j);
            float alpha = __shfl_sync(0xffffffffu, et, j) * inv;
            if (lane < 24) {
                float4 v = *(const float4*)&g_Vb[s * OUTC + c];
                acc.x += alpha * v.x; acc.y += alpha * v.y;
                acc.z += alpha * v.z; acc.w += alpha * v.w;
            }
        }
    }
    if (lane < 24) {
        const float* xr = &x[(size_t)w * 98 + c];
        acc.x += xr[0]; acc.y += xr[1]; acc.z += xr[2]; acc.w += xr[3];
        *(float4*)&out[w * OUTC + c] = acc;
    }
}

// ---------------- GAT per-node scalars ----------------
__global__ void k_gat_pq(const float* __restrict__ asrc, const float* __restrict__ adst) {
    int w = (blockIdx.x * blockDim.x + threadIdx.x) >> 5;
    int lane = threadIdx.x & 31;
    if (w >= NDST_F * 2) return;
    int n = w >> 1, h = w & 1;
    const float* qrow = &g_q[n * HID + h * 128];
    float as_ = 0.f, ad_ = 0.f;
#pragma unroll
    for (int it = 0; it < 4; it++) {
        int dd = lane + it * 32;
        float qv = qrow[dd];
        as_ += qv * asrc[h * 128 + dd];
        ad_ += qv * adst[h * 128 + dd];
    }
    for (int o = 16; o > 0; o >>= 1) {
        as_ += __shfl_down_sync(0xffffffff, as_, o);
        ad_ += __shfl_down_sync(0xffffffff, ad_, o);
    }
    if (lane == 0) { g_pqs[w] = as_; g_pqd[w] = ad_; }
}

// ---------------- merged decoder prep: xpc+psrc_b (warps) & pctx_b (threads) ----------
#define XPC_BLK ((NDST_F * 32 + 255) / 256)

__global__ void k_prep_b(const float* __restrict__ h_ll,
                         const float* __restrict__ bm_ctx, const float* __restrict__ era_ll) {
    if (blockIdx.x < XPC_BLK) {
        int n = (blockIdx.x * blockDim.x + threadIdx.x) >> 5;
        int lane = threadIdx.x & 31;
        if (n >= NDST_F) return;
        int node = n % HMESH;
        float acc = 0.f;
#pragma unroll
        for (int it = 0; it < 9; it++) {
            int c = lane + it * 32;
            if (c < K_B) {
                float v;
                if (c < 256) v = g_gout[n * HID + c] + g_xlat[n * HID + c];
                else         v = h_ll[node * 4 + (c - 256)];
                g_xpc[n * K_B + c] = v;
                acc += v * g_wred[OFF_WSA_B + c];
            }
        }
        for (int o = 16; o > 0; o >>= 1) acc += __shfl_down_sync(0xffffffff, acc, o);
        if (lane == 0) g_psrc_b[n] = acc;
        return;
    }
    int d = (blockIdx.x - XPC_BLK) * 256 + threadIdx.x;
    if (d >= NSRC_F) return;
    int node = d % ERA;
    float a = bm_ctx[node] * g_wred[OFF_WCA_B];
#pragma unroll
    for (int k = 0; k < 4; k++) a += era_ll[node * 4 + k] * g_wred[OFF_WCA_B + 1 + k];
    g_pctx_b[d] = a;
}

// ---------------- host ----------------
static float* sym(const void* s) { void* p = nullptr; cudaGetSymbolAddress(&p, s); return (float*)p; }

extern "C" void kernel_launch(void* const* d_in, const int* in_sizes, int n_in,
                              void* d_out, int out_size) {
    const float* x        = (const float*)d_in[0];
    const int*   e2h      = (const int*)  d_in[1];
    const int*   h2h      = (const int*)  d_in[2];
    const int*   h2e      = (const int*)  d_in[3];
    const float* e2h_attr = (const float*)d_in[4];
    const float* h2h_attr = (const float*)d_in[5];
    const float* h2e_attr = (const float*)d_in[6];
    const float* era_ll   = (const float*)d_in[7];
    const float* h_ll     = (const float*)d_in[8];
    const float* fm_ctx   = (const float*)d_in[9];
    const float* fm_Wsrc  = (const float*)d_in[10];
    const float* fm_Wctx  = (const float*)d_in[11];
    const float* fm_Wedge = (const float*)d_in[12];
    const float* fm_att   = (const float*)d_in[13];
    const float* fm_Wval  = (const float*)d_in[14];
    const float* bm_ctx   = (const float*)d_in[15];
    const float* bm_Wsrc  = (const float*)d_in[16];
    const float* bm_Wctx  = (const float*)d_in[17];
    const float* bm_Wedge = (const float*)d_in[18];
    const float* bm_att   = (const float*)d_in[19];
    const float* bm_Wval  = (const float*)d_in[20];
    const float* gat_W    = (const float*)d_in[21];
    const float* gat_We   = (const float*)d_in[22];
    const float* gat_asrc = (const float*)d_in[23];
    const float* gat_adst = (const float*)d_in[24];
    const float* gat_ae   = (const float*)d_in[25];
    float* out = (float*)d_out;

    float* p_xin  = sym(g_xin);
    float* p_Vf   = sym(g_Vf);
    float* p_xlat = sym(g_xlat);
    float* p_q    = sym(g_q);
    float* p_gout = sym(g_gout);
    float* p_h    = sym(g_h);
    float* p_xpc  = sym(g_xpc);
    float* p_Vb   = sym(g_Vb);

    const int T = 256;
    auto cdiv = [](int a, int b) { return (a + b - 1) / b; };

    // init (csr_zero + weight precompute) then CSR build (packed src+attr metadata)
    k_init<<<ZBLK + 2, T>>>(fm_Wsrc, fm_Wctx, fm_Wedge, fm_att,
                            bm_Wsrc, bm_Wctx, bm_Wedge, bm_att, gat_We, gat_ae);
    k_csr_count<<<cdiv(E_CSR_ALL, T), T>>>(e2h, h2h, h2e);
    k_csr_scan<<<3, 1024>>>();
    k_csr_fill<<<cdiv(E_CSR_ALL, T), T>>>(e2h, h2h, h2e, e2h_attr, h2h_attr, h2e_attr);

    k_prep_f<<<XIN_BLK + cdiv(NDST_F, T), T>>>(x, era_ll, fm_ctx, h_ll);

    // Vf = x_in @ fm_Wval   (tf32 tensor cores, cp.async staging)
    k_gemm<<<dim3(cdiv(NSRC_F, 128), 2), 256>>>(p_xin, LDA_F, fm_Wval, p_Vf, NSRC_F, HID, K_F);

    // fused logits+softmax+gather (warp per dst, both halves, packed metadata)
    k_fwd_gather<<<cdiv(NDST_F * 32, T), T>>>();

    // GAT layers
    for (int l = 0; l < 2; l++) {
        const float* hin = (l == 0) ? p_xlat : p_h;
        k_gemm<<<dim3(cdiv(NDST_F, 128), 2), 256>>>(hin, HID, gat_W + l * HID * HID, p_q,
                                                    NDST_F, HID, HID);
        k_gat_pq<<<cdiv(NDST_F * 2 * 32, T), T>>>(gat_asrc + l * 256, gat_adst + l * 256);
        k_gat_gather<<<cdiv(NDST_F * 32, T), T>>>((l == 0) ? p_h : p_gout, l,
                                                  (l == 0) ? 1 : 0);
    }

    // decoder
    k_prep_b<<<XPC_BLK + cdiv(NSRC_F, T), T>>>(h_ll, bm_ctx, era_ll);
    k_gemm<<<dim3(cdiv(NDST_F, 128), 1), 256>>>(p_xpc, K_B, bm_Wval, p_Vb, NDST_F, OUTC, K_B);

    k_bwd_gather<<<cdiv(NSRC_F * 32, T), T>>>(x, out);
}

// round 17
// speedup vs baseline: 1.4620x; 1.0408x over previous
#include <cuda_runtime.h>
#include <cuda_bf16.h>
#include <math.h>

#define BSZ    2
#define ERA    35718
#define HMESH  10242
#define NSRC_F (BSZ*ERA)      // 71436
#define NDST_F (BSZ*HMESH)    // 20484
#define E_E2H  107154
#define E_H2H  61440
#define E_H2E  107154
#define HID    256
#define K_F    102
#define LDA_F  104
#define K_B    260
#define OUTC   96

// offsets into g_wred (precomputed attention-reduced weight vectors)
#define OFF_WSA_F 0     // 102
#define OFF_WCA_F 104   // 5
#define OFF_WEA_F 112   // 3
#define OFF_WSA_B 128   // 260
#define OFF_WCA_B 392   // 5
#define OFF_WEA_B 400   // 3
#define OFF_WER   408   // 12 : (l*2+h)*4 + k

// ---------------- scratch (static device arrays; no allocation) ----------------
__device__ float g_xin  [NSRC_F*LDA_F];
__device__ float g_Vf   [NSRC_F*HID];
__device__ float g_psrc_f[NSRC_F];
__device__ float g_pctx_f[NDST_F];
__device__ float g_pqs  [NDST_F*2];
__device__ float g_pqd  [NDST_F*2];
__device__ float g_psrc_b[NDST_F];
__device__ float g_pctx_b[NSRC_F];
__device__ float g_xlat [NDST_F*HID];
__device__ float g_q    [NDST_F*HID];
__device__ float g_h    [NDST_F*HID];
__device__ float g_xpc  [NDST_F*K_B];
__device__ float g_Vb   [NDST_F*OUTC];
__device__ float g_wred [512];

// CSR (per-batch graphs; shared across the 2 batches)
// edat slot = {src, attr0, attr1, attr2} (float bits in y/z/w) in dst-sorted order
__device__ int  g_ptr_e2h[HMESH+1];  __device__ int g_pos_e2h[HMESH];  __device__ int4 g_edat_e2h[E_E2H];
__device__ int  g_ptr_h2h[HMESH+1];  __device__ int g_pos_h2h[HMESH];  __device__ int4 g_edat_h2h[E_H2H];
__device__ int  g_ptr_h2e[ERA+1];    __device__ int g_pos_h2e[ERA];    __device__ int4 g_edat_h2e[E_H2E];

#define N_CSR_ZERO (2*HMESH + ERA)
#define E_CSR_ALL  (E_E2H + E_H2H + E_H2E)
#define ZBLK ((N_CSR_ZERO + 255) / 256)

// ---------------- merged init: csr_zero + weight precompute ----------------
__global__ void k_init(const float* fmWsrc, const float* fmWctx, const float* fmWedge,
                       const float* fmAtt,
                       const float* bmWsrc, const float* bmWctx, const float* bmWedge,
                       const float* bmAtt,
                       const float* gatWe, const float* gatAe) {
    if (blockIdx.x < ZBLK) {
        int i = blockIdx.x * blockDim.x + threadIdx.x;
        if (i < HMESH)                 g_pos_e2h[i] = 0;
        else if (i < 2*HMESH)          g_pos_h2h[i - HMESH] = 0;
        else if (i < N_CSR_ZERO)       g_pos_h2e[i - 2*HMESH] = 0;
        return;
    }
    int t = (blockIdx.x - ZBLK) * 256 + threadIdx.x;  // 0..511
    if (t >= 512) return;
    if (t < K_F) {
        float a = 0.f;
        for (int j = 0; j < HID; j++) a += fmWsrc[t*HID + j] * fmAtt[j];
        g_wred[OFF_WSA_F + t] = a;
    } else if (t < K_F + 5) {
        int r = t - K_F; float a = 0.f;
        for (int j = 0; j < HID; j++) a += fmWctx[r*HID + j] * fmAtt[j];
        g_wred[OFF_WCA_F + r] = a;
    } else if (t < K_F + 8) {
        int r = t - K_F - 5; float a = 0.f;
        for (int j = 0; j < HID; j++) a += fmWedge[r*HID + j] * fmAtt[j];
        g_wred[OFF_WEA_F + r] = a;
    }
    if (t >= 128 && t < 128 + K_B) {
        int r = t - 128; float a = 0.f;
        for (int j = 0; j < OUTC; j++) a += bmWsrc[r*OUTC + j] * bmAtt[j];
        g_wred[OFF_WSA_B + r] = a;
    }
    if (t >= 400 && t < 405) {
        int r = t - 400; float a = 0.f;
        for (int j = 0; j < OUTC; j++) a += bmWctx[r*OUTC + j] * bmAtt[j];
        g_wred[OFF_WCA_B + r] = a;
    }
    if (t >= 405 && t < 408) {
        int r = t - 405; float a = 0.f;
        for (int j = 0; j < OUTC; j++) a += bmWedge[r*OUTC + j] * bmAtt[j];
        g_wred[OFF_WEA_B + r] = a;
    }
    if (t >= 408 && t < 420) {
        int idx = t - 408;
        int l = idx / 6, h = (idx % 6) / 3, k = idx % 3;
        float a = 0.f;
        for (int dd = 0; dd < 128; dd++)
            a += gatWe[((l*3 + k)*2 + h)*128 + dd] * gatAe[(l*2 + h)*128 + dd];
        g_wred[OFF_WER + (l*2 + h)*4 + k] = a;
    }
}

__global__ void k_csr_count(const int* __restrict__ e2h, const int* __restrict__ h2h,
                            const int* __restrict__ h2e) {
    int i = blockIdx.x * blockDim.x + threadIdx.x;
    if (i < E_E2H)                        atomicAdd(&g_pos_e2h[e2h[E_E2H + i]], 1);
    else if (i < E_E2H + E_H2H)           atomicAdd(&g_pos_h2h[h2h[E_H2H + (i - E_E2H)]], 1);
    else if (i < E_CSR_ALL)               atomicAdd(&g_pos_h2e[h2e[E_H2E + (i - E_E2H - E_H2H)]], 1);
}

// one block per graph; carry-loop block scan. pos becomes the running fill cursor.
__global__ void k_csr_scan() {
    __shared__ int sm[32];
    int g = blockIdx.x;
    int* cnt = (g == 0) ? g_pos_e2h : (g == 1) ? g_pos_h2h : g_pos_h2e;
    int* ptr = (g == 0) ? g_ptr_e2h : (g == 1) ? g_ptr_h2h : g_ptr_h2e;
    int n    = (g == 2) ? ERA : HMESH;
    int t = threadIdx.x, lane = t & 31, wid = t >> 5;
    int carry = 0;
    for (int base = 0; base < n; base += 1024) {
        int v = (base + t < n) ? cnt[base + t] : 0;
        int x = v;
#pragma unroll
        for (int o = 1; o < 32; o <<= 1) {
            int y = __shfl_up_sync(0xffffffff, x, o);
            if (lane >= o) x += y;
        }
        if (lane == 31) sm[wid] = x;
        __syncthreads();
        if (wid == 0) {
            int s = sm[lane];
#pragma unroll
            for (int o = 1; o < 32; o <<= 1) {
                int y = __shfl_up_sync(0xffffffff, s, o);
                if (lane >= o) s += y;
            }
            sm[lane] = s;
        }
        __syncthreads();
        int warp_off = (wid > 0) ? sm[wid - 1] : 0;
        int total = sm[31];
        int excl = carry + warp_off + x - v;
        if (base + t < n) { ptr[base + t] = excl; cnt[base + t] = excl; }
        carry += total;
        __syncthreads();
    }
    if (t == 0) ptr[n] = carry;
}

// fill CSR slots with packed {src, a0, a1, a2}; reads of src/attr are coalesced by edge id
__global__ void k_csr_fill(const int* __restrict__ e2h, const int* __restrict__ h2h,
                           const int* __restrict__ h2e,
                           const float* __restrict__ ea_e2h,
                           const float* __restrict__ ea_h2h,
                           const float* __restrict__ ea_h2e) {
    int i = blockIdx.x * blockDim.x + threadIdx.x;
    if (i < E_E2H) {
        int src = e2h[i];
        int idx = atomicAdd(&g_pos_e2h[e2h[E_E2H + i]], 1);
        g_edat_e2h[idx] = make_int4(src,
                                    __float_as_int(ea_e2h[i*3]),
                                    __float_as_int(ea_e2h[i*3+1]),
                                    __float_as_int(ea_e2h[i*3+2]));
    } else if (i < E_E2H + E_H2H) {
        int eo = i - E_E2H;
        int src = h2h[eo];
        int idx = atomicAdd(&g_pos_h2h[h2h[E_H2H + eo]], 1);
        g_edat_h2h[idx] = make_int4(src,
                                    __float_as_int(ea_h2h[eo*3]),
                                    __float_as_int(ea_h2h[eo*3+1]),
                                    __float_as_int(ea_h2h[eo*3+2]));
    } else if (i < E_CSR_ALL) {
        int eo = i - E_E2H - E_H2H;
        int src = h2e[eo];
        int idx = atomicAdd(&g_pos_h2e[h2e[E_H2E + eo]], 1);
        g_edat_h2e[idx] = make_int4(src,
                                    __float_as_int(ea_h2e[eo*3]),
                                    __float_as_int(ea_h2e[eo*3+1]),
                                    __float_as_int(ea_h2e[eo*3+2]));
    }
}

// ---------------- merged prep: build_xin+psrc_f (warps), pctx_f, pctx_b --------------
#define XIN_BLK ((NSRC_F * 32 + 255) / 256)
#define PCF_BLK ((NDST_F + 255) / 256)

__global__ void k_prep_f(const float* __restrict__ x, const float* __restrict__ era_ll,
                         const float* __restrict__ fm_ctx, const float* __restrict__ h_ll,
                         const float* __restrict__ bm_ctx) {
    if (blockIdx.x < XIN_BLK) {
        int w = (blockIdx.x * blockDim.x + threadIdx.x) >> 5;
        int lane = threadIdx.x & 31;
        if (w >= NSRC_F) return;
        int node = w % ERA;
        float acc = 0.f;
#pragma unroll
        for (int it = 0; it < 4; it++) {
            int c = lane + it * 32;
            float v = 0.f;
            if (c < 98)       v = x[(size_t)w * 98 + c];
            else if (c < 102) v = era_ll[node * 4 + (c - 98)];
            if (c < LDA_F) g_xin[w * LDA_F + c] = v;
            if (c < 102)   acc += v * g_wred[OFF_WSA_F + c];
        }
        for (int o = 16; o > 0; o >>= 1) acc += __shfl_down_sync(0xffffffff, acc, o);
        if (lane == 0) g_psrc_f[w] = acc;
        return;
    }
    if (blockIdx.x < XIN_BLK + PCF_BLK) {
        int d = (blockIdx.x - XIN_BLK) * 256 + threadIdx.x;
        if (d >= NDST_F) return;
        int node = d % HMESH;
        float a = fm_ctx[node] * g_wred[OFF_WCA_F];
#pragma unroll
        for (int k = 0; k < 4; k++) a += h_ll[node * 4 + k] * g_wred[OFF_WCA_F + 1 + k];
        g_pctx_f[d] = a;
        return;
    }
    int d = (blockIdx.x - XIN_BLK - PCF_BLK) * 256 + threadIdx.x;
    if (d >= NSRC_F) return;
    int node = d % ERA;
    float a = bm_ctx[node] * g_wred[OFF_WCA_B];
#pragma unroll
    for (int k = 0; k < 4; k++) a += era_ll[node * 4 + k] * g_wred[OFF_WCA_B + 1 + k];
    g_pctx_b[d] = a;
}

// ---------------- tf32 tensor-core GEMM with cp.async staging ------------------------
#define A_ST 20
#define B_ST 136

__device__ __forceinline__ void cp_async16(unsigned sa, const void* g, int bytes) {
    asm volatile("cp.async.cg.shared.global [%0], [%1], 16, %2;\n"
                 :: "r"(sa), "l"(g), "r"(bytes));
}
__device__ __forceinline__ void cp_commit() {
    asm volatile("cp.async.commit_group;\n" ::);
}
template <int N>
__device__ __forceinline__ void cp_wait() {
    asm volatile("cp.async.wait_group %0;\n" :: "n"(N));
}

__global__ __launch_bounds__(256, 2) void k_gemm(const float* __restrict__ A, int lda,
                                                 const float* __restrict__ B,
                                                 float* __restrict__ C,
                                                 int M, int N, int K) {
    __shared__ float Asm[2][128 * A_ST];
    __shared__ float Bsm[2][16 * B_ST];
    int tid = threadIdx.x;
    int wid = tid >> 5, lane = tid & 31;
    int m0 = blockIdx.x * 128, n0 = blockIdx.y * 128;
    int warpM = wid >> 2, warpN = wid & 3;
    int gid = lane >> 2, tig = lane & 3;

    float cacc[4][4][4];
#pragma unroll
    for (int i = 0; i < 4; i++)
#pragma unroll
        for (int j = 0; j < 4; j++)
#pragma unroll
            for (int r = 0; r < 4; r++) cacc[i][j][r] = 0.f;

    int ca0 = tid * 2, ca1 = tid * 2 + 1;

    auto issue = [&](int buf, int k0) {
#pragma unroll
        for (int i = 0; i < 2; i++) {
            int c = (i == 0) ? ca0 : ca1;
            int row = c >> 2, ko = (c & 3) * 4;
            int grow = m0 + row;
            int kstart = k0 + ko;
            int bytes = 0;
            const float* src = A;
            if (grow < M && kstart < K) {
                bytes = (K - kstart) * 4;
                if (bytes > 16) bytes = 16;
                src = A + (size_t)grow * lda + kstart;
            }
            unsigned sa = (unsigned)__cvta_generic_to_shared(&Asm[buf][row * A_ST + ko]);
            cp_async16(sa, src, bytes);
        }
#pragma unroll
        for (int i = 0; i < 2; i++) {
            int c = (i == 0) ? ca0 : ca1;
            int kr = c >> 5, no = (c & 31) * 4;
            int kg = k0 + kr, gn = n0 + no;
            int bytes = 0;
            const float* src = B;
            if (kg < K && gn < N) {
                bytes = (N - gn) * 4;
                if (bytes > 16) bytes = 16;
                src = B + (size_t)kg * N + gn;
            }
            unsigned sa = (unsigned)__cvta_generic_to_shared(&Bsm[buf][kr * B_ST + no]);
            cp_async16(sa, src, bytes);
        }
        cp_commit();
    };

    int ntile = (K + 15) >> 4;
    issue(0, 0);
    if (ntile > 1) issue(1, 16);

    int p = 0;
    for (int t = 0; t < ntile; t++) {
        if (t + 1 < ntile) cp_wait<1>(); else cp_wait<0>();
        __syncthreads();
#pragma unroll
        for (int ks = 0; ks < 2; ks++) {
            unsigned af[4][4], bf[4][2];
#pragma unroll
            for (int mt = 0; mt < 4; mt++) {
                int mb = warpM * 64 + mt * 16;
                int r0 = (mb + gid) * A_ST + ks * 8 + tig;
                int r1 = (mb + gid + 8) * A_ST + ks * 8 + tig;
                af[mt][0] = __float_as_uint(Asm[p][r0]);
                af[mt][1] = __float_as_uint(Asm[p][r1]);
                af[mt][2] = __float_as_uint(Asm[p][r0 + 4]);
                af[mt][3] = __float_as_uint(Asm[p][r1 + 4]);
            }
#pragma unroll
            for (int nt = 0; nt < 4; nt++) {
                int nb = warpN * 32 + nt * 8;
                int base = (ks * 8 + tig) * B_ST + nb + gid;
                bf[nt][0] = __float_as_uint(Bsm[p][base]);
                bf[nt][1] = __float_as_uint(Bsm[p][base + 4 * B_ST]);
            }
#pragma unroll
            for (int mt = 0; mt < 4; mt++)
#pragma unroll
                for (int nt = 0; nt < 4; nt++) {
                    asm volatile(
                        "mma.sync.aligned.m16n8k8.row.col.f32.tf32.tf32.f32 "
                        "{%0,%1,%2,%3}, {%4,%5,%6,%7}, {%8,%9}, {%0,%1,%2,%3};"
                        : "+f"(cacc[mt][nt][0]), "+f"(cacc[mt][nt][1]),
                          "+f"(cacc[mt][nt][2]), "+f"(cacc[mt][nt][3])
                        : "r"(af[mt][0]), "r"(af[mt][1]), "r"(af[mt][2]), "r"(af[mt][3]),
                          "r"(bf[nt][0]), "r"(bf[nt][1]));
                }
        }
        __syncthreads();
        if (t + 2 < ntile) issue(p, (t + 2) * 16);
        p ^= 1;
    }

#pragma unroll
    for (int mt = 0; mt < 4; mt++) {
#pragma unroll
        for (int nt = 0; nt < 4; nt++) {
            int row0 = m0 + warpM * 64 + mt * 16 + gid;
            int col  = n0 + warpN * 32 + nt * 8 + 2 * tig;
            if (col + 1 < N) {
                if (row0 < M)
                    *(float2*)&C[(size_t)row0 * N + col] =
                        make_float2(cacc[mt][nt][0], cacc[mt][nt][1]);
                if (row0 + 8 < M)
                    *(float2*)&C[(size_t)(row0 + 8) * N + col] =
                        make_float2(cacc[mt][nt][2], cacc[mt][nt][3]);
            }
        }
    }
}

// ---------------- fused gathers: packed-metadata CSR, warp per dst -------------------
__device__ __forceinline__ void fwd_edge_meta(int p0, int idx, int cnt, int b, float pc,
                                              int &s, float &ev) {
    s = 0; ev = 0.f;
    if (idx < cnt) {
        int4 m = g_edat_e2h[p0 + idx];
        s = m.x + b * ERA;
        float pe = __int_as_float(m.y) * g_wred[OFF_WEA_F]
                 + __int_as_float(m.z) * g_wred[OFF_WEA_F+1]
                 + __int_as_float(m.w) * g_wred[OFF_WEA_F+2];
        float l = g_psrc_f[s] + pc + pe;
        l = l > 0.f ? l : 0.2f * l;
        ev = expf(l);
    }
}

// warp per dst; both column halves accumulated (alpha is head-independent here)
__global__ void k_fwd_gather() {
    int d = (blockIdx.x * blockDim.x + threadIdx.x) >> 5;
    int lane = threadIdx.x & 31;
    if (d >= NDST_F) return;
    int node = d % HMESH, b = d / HMESH;
    int p0 = g_ptr_e2h[node];
    int cnt = g_ptr_e2h[node + 1] - p0;
    float pc = g_pctx_f[d];

    int s0; float e0;
    fwd_edge_meta(p0, lane, cnt, b, pc, s0, e0);
    float ssum = e0;
    for (int base = 32; base < cnt; base += 32) {
        int st; float et;
        fwd_edge_meta(p0, base + lane, cnt, b, pc, st, et);
        ssum += et;
    }
#pragma unroll
    for (int o = 16; o > 0; o >>= 1) ssum += __shfl_xor_sync(0xffffffffu, ssum, o);
    float inv = 1.f / (ssum + 1e-9f);

    float4 acc0 = make_float4(0.f, 0.f, 0.f, 0.f);
    float4 acc1 = make_float4(0.f, 0.f, 0.f, 0.f);
    int c0 = lane * 4, c1 = 128 + lane * 4;
    int n1 = cnt < 32 ? cnt : 32;
    for (int j = 0; j < n1; j++) {
        int s = __shfl_sync(0xffffffffu, s0, j);
        float alpha = __shfl_sync(0xffffffffu, e0, j) * inv;
        float4 v0 = *(const float4*)&g_Vf[s * HID + c0];
        float4 v1 = *(const float4*)&g_Vf[s * HID + c1];
        acc0.x += alpha * v0.x; acc0.y += alpha * v0.y;
        acc0.z += alpha * v0.z; acc0.w += alpha * v0.w;
        acc1.x += alpha * v1.x; acc1.y += alpha * v1.y;
        acc1.z += alpha * v1.z; acc1.w += alpha * v1.w;
    }
    for (int base = 32; base < cnt; base += 32) {
        int st; float et;
        fwd_edge_meta(p0, base + lane, cnt, b, pc, st, et);
        int nn = (cnt - base) < 32 ? (cnt - base) : 32;
        for (int j = 0; j < nn; j++) {
            int s = __shfl_sync(0xffffffffu, st, j);
            float alpha = __shfl_sync(0xffffffffu, et, j) * inv;
            float4 v0 = *(const float4*)&g_Vf[s * HID + c0];
            float4 v1 = *(const float4*)&g_Vf[s * HID + c1];
            acc0.x += alpha * v0.x; acc0.y += alpha * v0.y;
            acc0.z += alpha * v0.z; acc0.w += alpha * v0.w;
            acc1.x += alpha * v1.x; acc1.y += alpha * v1.y;
            acc1.z += alpha * v1.z; acc1.w += alpha * v1.w;
        }
    }
    *(float4*)&g_xlat[d * HID + c0] = acc0;
    *(float4*)&g_xlat[d * HID + c1] = acc1;
}

__device__ __forceinline__ void gat_edge_meta2(int p0, int idx, int cnt, int b,
                                               float pqd0, float pqd1, int l,
                                               int &s, float &ev0, float &ev1) {
    s = 0; ev0 = 0.f; ev1 = 0.f;
    if (idx < cnt) {
        int4 m = g_edat_h2h[p0 + idx];
        s = m.x + b * HMESH;
        float a0 = __int_as_float(m.y), a1 = __int_as_float(m.z), a2 = __int_as_float(m.w);
        const float* w0 = &g_wred[OFF_WER + (l*2)*4];
        const float* w1 = &g_wred[OFF_WER + (l*2 + 1)*4];
        float lg0 = g_pqs[s*2]     + pqd0 + a0*w0[0] + a1*w0[1] + a2*w0[2];
        float lg1 = g_pqs[s*2 + 1] + pqd1 + a0*w1[0] + a1*w1[1] + a2*w1[2];
        lg0 = lg0 > 0.f ? lg0 : 0.2f * lg0;
        lg1 = lg1 > 0.f ? lg1 : 0.2f * lg1;
        ev0 = expf(lg0);
        ev1 = expf(lg1);
    }
}

// warp per dst; both heads accumulated in one pass.
// mode 0 (layer 0): gelu + store to g_h.
// mode 1 (layer 1): add xlat residual, store into g_xpc (stride 260) + h_ll cols,
//                   and compute psrc_b[d] in-register (decoder prep fully fused).
__global__ void k_gat_gather(const float* __restrict__ h_ll, int l, int mode) {
    int d = (blockIdx.x * blockDim.x + threadIdx.x) >> 5;
    int lane = threadIdx.x & 31;
    if (d >= NDST_F) return;
    int node = d % HMESH, b = d / HMESH;
    int p0 = g_ptr_h2h[node];
    int cnt = g_ptr_h2h[node + 1] - p0;
    float pqd0 = g_pqd[d*2], pqd1 = g_pqd[d*2 + 1];

    int s0; float e00, e01;
    gat_edge_meta2(p0, lane, cnt, b, pqd0, pqd1, l, s0, e00, e01);
    float ssum0 = e00, ssum1 = e01;
    for (int base = 32; base < cnt; base += 32) {
        int st; float et0, et1;
        gat_edge_meta2(p0, base + lane, cnt, b, pqd0, pqd1, l, st, et0, et1);
        ssum0 += et0; ssum1 += et1;
    }
#pragma unroll
    for (int o = 16; o > 0; o >>= 1) {
        ssum0 += __shfl_xor_sync(0xffffffffu, ssum0, o);
        ssum1 += __shfl_xor_sync(0xffffffffu, ssum1, o);
    }
    float inv0 = 1.f / (ssum0 + 1e-9f);
    float inv1 = 1.f / (ssum1 + 1e-9f);

    float4 acc0 = make_float4(0.f, 0.f, 0.f, 0.f);
    float4 acc1 = make_float4(0.f, 0.f, 0.f, 0.f);
    int c0 = lane * 4, c1 = 128 + lane * 4;
    int n1 = cnt < 32 ? cnt : 32;
    for (int j = 0; j < n1; j++) {
        int s = __shfl_sync(0xffffffffu, s0, j);
        float al0 = __shfl_sync(0xffffffffu, e00, j) * inv0;
        float al1 = __shfl_sync(0xffffffffu, e01, j) * inv1;
        float4 v0 = *(const float4*)&g_q[s * HID + c0];
        float4 v1 = *(const float4*)&g_q[s * HID + c1];
        acc0.x += al0 * v0.x; acc0.y += al0 * v0.y;
        acc0.z += al0 * v0.z; acc0.w += al0 * v0.w;
        acc1.x += al1 * v1.x; acc1.y += al1 * v1.y;
        acc1.z += al1 * v1.z; acc1.w += al1 * v1.w;
    }
    for (int base = 32; base < cnt; base += 32) {
        int st; float et0, et1;
        gat_edge_meta2(p0, base + lane, cnt, b, pqd0, pqd1, l, st, et0, et1);
        int nn = (cnt - base) < 32 ? (cnt - base) : 32;
        for (int j = 0; j < nn; j++) {
            int s = __shfl_sync(0xffffffffu, st, j);
            float al0 = __shfl_sync(0xffffffffu, et0, j) * inv0;
            float al1 = __shfl_sync(0xffffffffu, et1, j) * inv1;
            float4 v0 = *(const float4*)&g_q[s * HID + c0];
            float4 v1 = *(const float4*)&g_q[s * HID + c1];
            acc0.x += al0 * v0.x; acc0.y += al0 * v0.y;
            acc0.z += al0 * v0.z; acc0.w += al0 * v0.w;
            acc1.x += al1 * v1.x; acc1.y += al1 * v1.y;
            acc1.z += al1 * v1.z; acc1.w += al1 * v1.w;
        }
    }

    if (mode == 0) {
        float* a0 = &acc0.x; float* a1 = &acc1.x;
#pragma unroll
        for (int i = 0; i < 4; i++) {
            float xx = a0[i];
            float t = tanhf(0.7978845608f * (xx + 0.044715f * xx * xx * xx));
            a0[i] = 0.5f * xx * (1.f + t);
            xx = a1[i];
            t = tanhf(0.7978845608f * (xx + 0.044715f * xx * xx * xx));
            a1[i] = 0.5f * xx * (1.f + t);
        }
        *(float4*)&g_h[d * HID + c0] = acc0;
        *(float4*)&g_h[d * HID + c1] = acc1;
        return;
    }

    // mode 1: fused decoder prep
    float4 r0 = *(const float4*)&g_xlat[d * HID + c0];
    float4 r1 = *(const float4*)&g_xlat[d * HID + c1];
    acc0.x += r0.x; acc0.y += r0.y; acc0.z += r0.z; acc0.w += r0.w;
    acc1.x += r1.x; acc1.y += r1.y; acc1.z += r1.z; acc1.w += r1.w;
    *(float4*)&g_xpc[d * K_B + c0] = acc0;
    *(float4*)&g_xpc[d * K_B + c1] = acc1;

    // psrc_b partial: dot this lane's 8 values with wsa_b
    const float* wsa = &g_wred[OFF_WSA_B];
    float ps = acc0.x * wsa[c0] + acc0.y * wsa[c0+1] + acc0.z * wsa[c0+2] + acc0.w * wsa[c0+3]
             + acc1.x * wsa[c1] + acc1.y * wsa[c1+1] + acc1.z * wsa[c1+2] + acc1.w * wsa[c1+3];
    if (lane == 0) {
#pragma unroll
        for (int k = 0; k < 4; k++) {
            float hv = h_ll[node * 4 + k];
            g_xpc[d * K_B + 256 + k] = hv;
            ps += hv * wsa[256 + k];
        }
    }
#pragma unroll
    for (int o = 16; o > 0; o >>= 1) ps += __shfl_xor_sync(0xffffffffu, ps, o);
    if (lane == 0) g_psrc_b[d] = ps;
}

__device__ __forceinline__ void bwd_edge_meta(int p0, int idx, int cnt, int b, float pc,
                                              int &s, float &ev) {
    s = 0; ev = 0.f;
    if (idx < cnt) {
        int4 m = g_edat_h2e[p0 + idx];
        s = m.x + b * HMESH;
        float pe = __int_as_float(m.y) * g_wred[OFF_WEA_B]
                 + __int_as_float(m.z) * g_wred[OFF_WEA_B+1]
                 + __int_as_float(m.w) * g_wred[OFF_WEA_B+2];
        float l = g_psrc_b[s] + pc + pe;
        l = l > 0.f ? l : 0.2f * l;
        ev = expf(l);
    }
}

__global__ void k_bwd_gather(const float* __restrict__ x, float* __restrict__ out) {
    int w = (blockIdx.x * blockDim.x + threadIdx.x) >> 5;
    int lane = threadIdx.x & 31;
    if (w >= NSRC_F) return;
    int node = w % ERA, b = w / ERA;
    int p0 = g_ptr_h2e[node];
    int cnt = g_ptr_h2e[node + 1] - p0;
    float pc = g_pctx_b[w];

    int s0; float e0;
    bwd_edge_meta(p0, lane, cnt, b, pc, s0, e0);
    float ssum = e0;
    for (int base = 32; base < cnt; base += 32) {
        int st; float et;
        bwd_edge_meta(p0, base + lane, cnt, b, pc, st, et);
        ssum += et;
    }
#pragma unroll
    for (int o = 16; o > 0; o >>= 1) ssum += __shfl_xor_sync(0xffffffffu, ssum, o);
    float inv = 1.f / (ssum + 1e-9f);

    int c = lane * 4;
    float4 acc = make_float4(0.f, 0.f, 0.f, 0.f);
    int n1 = cnt < 32 ? cnt : 32;
    for (int j = 0; j < n1; j++) {
        int s = __shfl_sync(0xffffffffu, s0, j);
        float alpha = __shfl_sync(0xffffffffu, e0, j) * inv;
        if (lane < 24) {
            float4 v = *(const float4*)&g_Vb[s * OUTC + c];
            acc.x += alpha * v.x; acc.y += alpha * v.y;
            acc.z += alpha * v.z; acc.w += alpha * v.w;
        }
    }
    for (int base = 32; base < cnt; base += 32) {
        int st; float et;
        bwd_edge_meta(p0, base + lane, cnt, b, pc, st, et);
        int nn = (cnt - base) < 32 ? (cnt - base) : 32;
        for (int j = 0; j < nn; j++) {
            int s = __shfl_sync(0xffffffffu, st, j);
            float alpha = __shfl_sync(0xffffffffu, et, j) * inv;
            if (lane < 24) {
                float4 v = *(const float4*)&g_Vb[s * OUTC + c];
                acc.x += alpha * v.x; acc.y += alpha * v.y;
                acc.z += alpha * v.z; acc.w += alpha * v.w;
            }
        }
    }
    if (lane < 24) {
        const float* xr = &x[(size_t)w * 98 + c];
        acc.x += xr[0]; acc.y += xr[1]; acc.z += xr[2]; acc.w += xr[3];
        *(float4*)&out[w * OUTC + c] = acc;
    }
}

// ---------------- GAT per-node scalars ----------------
__global__ void k_gat_pq(const float* __restrict__ asrc, const float* __restrict__ adst) {
    int w = (blockIdx.x * blockDim.x + threadIdx.x) >> 5;
    int lane = threadIdx.x & 31;
    if (w >= NDST_F * 2) return;
    int n = w >> 1, h = w & 1;
    const float* qrow = &g_q[n * HID + h * 128];
    float as_ = 0.f, ad_ = 0.f;
#pragma unroll
    for (int it = 0; it < 4; it++) {
        int dd = lane + it * 32;
        float qv = qrow[dd];
        as_ += qv * asrc[h * 128 + dd];
        ad_ += qv * adst[h * 128 + dd];
    }
    for (int o = 16; o > 0; o >>= 1) {
        as_ += __shfl_down_sync(0xffffffff, as_, o);
        ad_ += __shfl_down_sync(0xffffffff, ad_, o);
    }
    if (lane == 0) { g_pqs[w] = as_; g_pqd[w] = ad_; }
}

// ---------------- host ----------------
static float* sym(const void* s) { void* p = nullptr; cudaGetSymbolAddress(&p, s); return (float*)p; }

extern "C" void kernel_launch(void* const* d_in, const int* in_sizes, int n_in,
                              void* d_out, int out_size) {
    const float* x        = (const float*)d_in[0];
    const int*   e2h      = (const int*)  d_in[1];
    const int*   h2h      = (const int*)  d_in[2];
    const int*   h2e      = (const int*)  d_in[3];
    const float* e2h_attr = (const float*)d_in[4];
    const float* h2h_attr = (const float*)d_in[5];
    const float* h2e_attr = (const float*)d_in[6];
    const float* era_ll   = (const float*)d_in[7];
    const float* h_ll     = (const float*)d_in[8];
    const float* fm_ctx   = (const float*)d_in[9];
    const float* fm_Wsrc  = (const float*)d_in[10];
    const float* fm_Wctx  = (const float*)d_in[11];
    const float* fm_Wedge = (const float*)d_in[12];
    const float* fm_att   = (const float*)d_in[13];
    const float* fm_Wval  = (const float*)d_in[14];
    const float* bm_ctx   = (const float*)d_in[15];
    const float* bm_Wsrc  = (const float*)d_in[16];
    const float* bm_Wctx  = (const float*)d_in[17];
    const float* bm_Wedge = (const float*)d_in[18];
    const float* bm_att   = (const float*)d_in[19];
    const float* bm_Wval  = (const float*)d_in[20];
    const float* gat_W    = (const float*)d_in[21];
    const float* gat_We   = (const float*)d_in[22];
    const float* gat_asrc = (const float*)d_in[23];
    const float* gat_adst = (const float*)d_in[24];
    const float* gat_ae   = (const float*)d_in[25];
    float* out = (float*)d_out;

    float* p_xin  = sym(g_xin);
    float* p_Vf   = sym(g_Vf);
    float* p_xlat = sym(g_xlat);
    float* p_q    = sym(g_q);
    float* p_h    = sym(g_h);
    float* p_xpc  = sym(g_xpc);
    float* p_Vb   = sym(g_Vb);

    const int T = 256;
    auto cdiv = [](int a, int b) { return (a + b - 1) / b; };

    // init (csr_zero + weight precompute) then CSR build (packed src+attr metadata)
    k_init<<<ZBLK + 2, T>>>(fm_Wsrc, fm_Wctx, fm_Wedge, fm_att,
                            bm_Wsrc, bm_Wctx, bm_Wedge, bm_att, gat_We, gat_ae);
    k_csr_count<<<cdiv(E_CSR_ALL, T), T>>>(e2h, h2h, h2e);
    k_csr_scan<<<3, 1024>>>();
    k_csr_fill<<<cdiv(E_CSR_ALL, T), T>>>(e2h, h2h, h2e, e2h_attr, h2h_attr, h2e_attr);

    // xin+psrc_f, pctx_f, pctx_b (all depend only on inputs + wred)
    k_prep_f<<<XIN_BLK + PCF_BLK + cdiv(NSRC_F, T), T>>>(x, era_ll, fm_ctx, h_ll, bm_ctx);

    // Vf = x_in @ fm_Wval   (tf32 tensor cores, cp.async staging)
    k_gemm<<<dim3(cdiv(NSRC_F, 128), 2), 256>>>(p_xin, LDA_F, fm_Wval, p_Vf, NSRC_F, HID, K_F);

    // fused logits+softmax+gather (warp per dst, both halves, packed metadata)
    k_fwd_gather<<<cdiv(NDST_F * 32, T), T>>>();

    // GAT layers; layer-1 gather fuses the decoder prep (xpc + psrc_b)
    for (int l = 0; l < 2; l++) {
        const float* hin = (l == 0) ? p_xlat : p_h;
        k_gemm<<<dim3(cdiv(NDST_F, 128), 2), 256>>>(hin, HID, gat_W + l * HID * HID, p_q,
                                                    NDST_F, HID, HID);
        k_gat_pq<<<cdiv(NDST_F * 2 * 32, T), T>>>(gat_asrc + l * 256, gat_adst + l * 256);
        k_gat_gather<<<cdiv(NDST_F * 32, T), T>>>(h_ll, l, (l == 0) ? 0 : 1);
    }

    // decoder: Vb = x_proc @ bm_Wval (xpc already built by the layer-1 gather)
    k_gemm<<<dim3(cdiv(NDST_F, 128), 1), 256>>>(p_xpc, K_B, bm_Wval, p_Vb, NDST_F, OUTC, K_B);

    k_bwd_gather<<<cdiv(NSRC_F * 32, T), T>>>(x, out);
}